// round 4
// baseline (speedup 1.0000x reference)
#include <cuda_runtime.h>
#include <math.h>
#include <stdint.h>

#define Tn 1024
#define Bn 8
#define Dn 512
#define Hn 8
#define DHn 64
#define NPAIR 64           // Hn*Bn
#define ROWS (Bn*Tn)       // 8192

// ---------------- scratch (device globals: allocation-free) ----------------
__device__ float g_xb[Bn*Tn*Dn];
__device__ float g_Q [Bn*Tn*Dn];
__device__ float g_K [Bn*Tn*Dn];
__device__ float g_V [Bn*Tn*Dn];
__device__ float g_tmp[Bn*Tn*Dn];
__device__ float g_invnorm[Bn*Dn];
__device__ float g_adj[Tn];

__device__ __forceinline__ float powtf(float v){
    return sqrtf(fmaxf(v,0.f)) - sqrtf(fmaxf(-v,0.f));
}

__device__ __forceinline__ uint32_t f2tf(float f){
    uint32_t u; asm("cvt.rna.tf32.f32 %0, %1;" : "=r"(u) : "f"(f)); return u;
}

// mma.sync m16n8k8 tf32, fp32 accum, row.col
__device__ __forceinline__ void mma8(float* c, const uint32_t* a, const uint32_t* b){
    asm volatile(
        "mma.sync.aligned.m16n8k8.row.col.f32.tf32.tf32.f32 "
        "{%0,%1,%2,%3},{%4,%5,%6,%7},{%8,%9},{%0,%1,%2,%3};"
        : "+f"(c[0]),"+f"(c[1]),"+f"(c[2]),"+f"(c[3])
        : "r"(a[0]),"r"(a[1]),"r"(a[2]),"r"(a[3]),"r"(b[0]),"r"(b[1]));
}

// ---------------- transposes ----------------
__global__ void k_transpose_in(const float* __restrict__ x){
    int idx = blockIdx.x*256 + threadIdx.x;          // [B,T,D] linear
    int d = idx & (Dn-1);
    int t = (idx >> 9) & (Tn-1);
    int b = idx >> 19;
    g_xb[idx] = x[(t*Bn + b)*Dn + d];
}

__global__ void k_transpose_out(float* __restrict__ out){
    int idx = blockIdx.x*256 + threadIdx.x;          // [T,B,D] linear
    int d = idx & (Dn-1);
    int b = (idx >> 9) & (Bn-1);
    int t = idx >> 12;
    out[idx] = g_xb[((b<<10) + t)*Dn + d];
}

// ---------------- adj table ----------------
__global__ void k_adj(const float* __restrict__ aw, const float* __restrict__ ab){
    int i = threadIdx.x;
    float dist = (float)i;
    g_adj[i] = expf(-fabsf(aw[0]*dist*dist - ab[0]));
}

// ================= tf32 projection GEMM: C = A @ W + b =================
__global__ __launch_bounds__(256) void k_proj_qkv(
    const float* __restrict__ Wq, const float* __restrict__ Wk, const float* __restrict__ Wv,
    const float* __restrict__ bq, const float* __restrict__ bk, const float* __restrict__ bv,
    int layer)
{
    __shared__ uint32_t As[128][36];
    __shared__ uint32_t Bs[32][72];
    int tid = threadIdx.x;
    int z = blockIdx.z;
    const float* W    = (z==0 ? Wq : (z==1 ? Wk : Wv)) + (size_t)layer*Dn*Dn;
    const float* bias = (z==0 ? bq : (z==1 ? bk : bv)) + layer*Dn;
    float* C          = (z==0 ? g_Q : (z==1 ? g_K : g_V));
    int m0 = blockIdx.y*128, n0 = blockIdx.x*64;
    int wid = tid>>5, lane = tid&31, g = lane>>2, t = lane&3;
    int m_off = (wid>>1)*32, n_off = (wid&1)*32;

    float c[2][4][4] = {};
    int arow = tid>>3, acol = (tid&7)*4;
    int brow = tid>>4, bcol = (tid&15)*4;

    for (int k0=0; k0<Dn; k0+=32){
#pragma unroll
        for (int i=0;i<4;i++){
            float4 v = *(const float4*)&g_xb[(size_t)(m0+arow+i*32)*Dn + k0 + acol];
            As[arow+i*32][acol+0]=f2tf(v.x); As[arow+i*32][acol+1]=f2tf(v.y);
            As[arow+i*32][acol+2]=f2tf(v.z); As[arow+i*32][acol+3]=f2tf(v.w);
        }
#pragma unroll
        for (int i=0;i<2;i++){
            float4 v = *(const float4*)&W[(size_t)(k0+brow+i*16)*Dn + n0 + bcol];
            Bs[brow+i*16][bcol+0]=f2tf(v.x); Bs[brow+i*16][bcol+1]=f2tf(v.y);
            Bs[brow+i*16][bcol+2]=f2tf(v.z); Bs[brow+i*16][bcol+3]=f2tf(v.w);
        }
        __syncthreads();
#pragma unroll
        for (int ks=0; ks<4; ks++){
            uint32_t a[2][4], b[4][2];
#pragma unroll
            for (int mi=0;mi<2;mi++){
                int r = m_off+mi*16;
                a[mi][0]=As[r+g  ][ks*8+t];   a[mi][1]=As[r+g+8][ks*8+t];
                a[mi][2]=As[r+g  ][ks*8+t+4]; a[mi][3]=As[r+g+8][ks*8+t+4];
            }
#pragma unroll
            for (int ni=0;ni<4;ni++){
                b[ni][0]=Bs[ks*8+t  ][n_off+ni*8+g];
                b[ni][1]=Bs[ks*8+t+4][n_off+ni*8+g];
            }
#pragma unroll
            for (int mi=0;mi<2;mi++)
#pragma unroll
                for (int ni=0;ni<4;ni++) mma8(c[mi][ni], a[mi], b[ni]);
        }
        __syncthreads();
    }
#pragma unroll
    for (int mi=0;mi<2;mi++){
#pragma unroll
        for (int ni=0;ni<4;ni++){
            int row = m0 + m_off + mi*16 + g;
            int col = n0 + n_off + ni*8 + 2*t;
            float b0 = bias[col], b1 = bias[col+1];
            float2 v0 = {c[mi][ni][0]+b0, c[mi][ni][1]+b1};
            float2 v1 = {c[mi][ni][2]+b0, c[mi][ni][3]+b1};
            *(float2*)&C[(size_t)row*Dn + col]     = v0;
            *(float2*)&C[(size_t)(row+8)*Dn + col] = v1;
        }
    }
}

// ---- out proj: g_xb = g_xb + (g_tmp * invnorm) @ Wo + bo ----
__global__ __launch_bounds__(256) void k_proj_out(
    const float* __restrict__ Wo, const float* __restrict__ bo, int layer)
{
    __shared__ uint32_t As[128][36];
    __shared__ uint32_t Bs[32][72];
    int tid = threadIdx.x;
    const float* W    = Wo + (size_t)layer*Dn*Dn;
    const float* bias = bo + layer*Dn;
    int m0 = blockIdx.y*128, n0 = blockIdx.x*64;
    int wid = tid>>5, lane = tid&31, g = lane>>2, t = lane&3;
    int m_off = (wid>>1)*32, n_off = (wid&1)*32;

    float c[2][4][4] = {};
    int arow = tid>>3, acol = (tid&7)*4;
    int brow = tid>>4, bcol = (tid&15)*4;

    for (int k0=0; k0<Dn; k0+=32){
#pragma unroll
        for (int i=0;i<4;i++){
            int m = m0+arow+i*32;
            float4 v = *(const float4*)&g_tmp[(size_t)m*Dn + k0 + acol];
            float4 s = *(const float4*)&g_invnorm[(m>>10)*Dn + k0 + acol];
            As[arow+i*32][acol+0]=f2tf(v.x*s.x); As[arow+i*32][acol+1]=f2tf(v.y*s.y);
            As[arow+i*32][acol+2]=f2tf(v.z*s.z); As[arow+i*32][acol+3]=f2tf(v.w*s.w);
        }
#pragma unroll
        for (int i=0;i<2;i++){
            float4 v = *(const float4*)&W[(size_t)(k0+brow+i*16)*Dn + n0 + bcol];
            Bs[brow+i*16][bcol+0]=f2tf(v.x); Bs[brow+i*16][bcol+1]=f2tf(v.y);
            Bs[brow+i*16][bcol+2]=f2tf(v.z); Bs[brow+i*16][bcol+3]=f2tf(v.w);
        }
        __syncthreads();
#pragma unroll
        for (int ks=0; ks<4; ks++){
            uint32_t a[2][4], b[4][2];
#pragma unroll
            for (int mi=0;mi<2;mi++){
                int r = m_off+mi*16;
                a[mi][0]=As[r+g  ][ks*8+t];   a[mi][1]=As[r+g+8][ks*8+t];
                a[mi][2]=As[r+g  ][ks*8+t+4]; a[mi][3]=As[r+g+8][ks*8+t+4];
            }
#pragma unroll
            for (int ni=0;ni<4;ni++){
                b[ni][0]=Bs[ks*8+t  ][n_off+ni*8+g];
                b[ni][1]=Bs[ks*8+t+4][n_off+ni*8+g];
            }
#pragma unroll
            for (int mi=0;mi<2;mi++)
#pragma unroll
                for (int ni=0;ni<4;ni++) mma8(c[mi][ni], a[mi], b[ni]);
        }
        __syncthreads();
    }
#pragma unroll
    for (int mi=0;mi<2;mi++){
#pragma unroll
        for (int ni=0;ni<4;ni++){
            int row = m0 + m_off + mi*16 + g;
            int col = n0 + n_off + ni*8 + 2*t;
            float b0 = bias[col], b1 = bias[col+1];
            float2 r0 = *(float2*)&g_xb[(size_t)row*Dn + col];
            float2 r1 = *(float2*)&g_xb[(size_t)(row+8)*Dn + col];
            float2 v0 = {c[mi][ni][0]+b0+r0.x, c[mi][ni][1]+b1+r0.y};
            float2 v1 = {c[mi][ni][2]+b0+r1.x, c[mi][ni][3]+b1+r1.y};
            *(float2*)&g_xb[(size_t)row*Dn + col]     = v0;
            *(float2*)&g_xb[(size_t)(row+8)*Dn + col] = v1;
        }
    }
}

// ================= fused flash attention =================
// grid (8 q-tiles, 64 pairs), 256 threads = 8 warps; warp w owns rows w*16..w*16+15.
// Online global softmax + exact local-window softmax epilogue; writes powtf(out) to g_tmp.
#define Q_STRIDE 68
#define V_STRIDE 72
#define SH_QS 0
#define SH_KS (128*Q_STRIDE)
#define SH_VS (2*128*Q_STRIDE)
#define SH_ADJ (2*128*Q_STRIDE + 128*V_STRIDE)
#define FLASH_SMEM ((2*128*Q_STRIDE + 128*V_STRIDE + Tn)*4)

__global__ __launch_bounds__(256,1) void k_flash(const float* __restrict__ alpha, int layer){
    extern __shared__ uint32_t sh[];
    uint32_t (*Qs)[Q_STRIDE] = (uint32_t(*)[Q_STRIDE])(sh + SH_QS);
    uint32_t (*Ks)[Q_STRIDE] = (uint32_t(*)[Q_STRIDE])(sh + SH_KS);
    uint32_t (*Vs)[V_STRIDE] = (uint32_t(*)[V_STRIDE])(sh + SH_VS);
    float* adj_s = (float*)(sh + SH_ADJ);
    float (*Og)[V_STRIDE] = (float(*)[V_STRIDE])(sh + SH_VS);   // overlay after mainloop

    const int tid = threadIdx.x;
    const int p  = blockIdx.y;
    const int q0 = blockIdx.x*128;
    const float* Qp = g_Q + (size_t)p*Tn*DHn;
    const float* Kp = g_K + (size_t)p*Tn*DHn;
    const float* Vp = g_V + (size_t)p*Tn*DHn;

    for (int i=tid;i<Tn;i+=256) adj_s[i] = g_adj[i];
    int lrow = tid>>4, lcol = (tid&15)*4;
#pragma unroll
    for (int i=0;i<8;i++){
        int r = lrow + i*16;
        float4 q4 = *(const float4*)&Qp[(size_t)(q0+r)*DHn + lcol];
        Qs[r][lcol+0]=f2tf(q4.x); Qs[r][lcol+1]=f2tf(q4.y);
        Qs[r][lcol+2]=f2tf(q4.z); Qs[r][lcol+3]=f2tf(q4.w);
    }
    __syncthreads();

    const int wid = tid>>5, lane = tid&31, g = lane>>2, t = lane&3;
    const int r0 = wid*16;
    const int qlo = q0 + r0 + g;
    const float scale = 0.04419417382415922f;   // 1/sqrt(512)

    float m_lo=-1e30f, m_hi=-1e30f, l_lo=0.f, l_hi=0.f;
    float o[8][4] = {};

    for (int kb=0; kb<Tn; kb+=128){
#pragma unroll
        for (int i=0;i<8;i++){
            int r = lrow + i*16;
            float4 k4 = *(const float4*)&Kp[(size_t)(kb+r)*DHn + lcol];
            Ks[r][lcol+0]=f2tf(k4.x); Ks[r][lcol+1]=f2tf(k4.y);
            Ks[r][lcol+2]=f2tf(k4.z); Ks[r][lcol+3]=f2tf(k4.w);
            float4 v4 = *(const float4*)&Vp[(size_t)(kb+r)*DHn + lcol];
            Vs[r][lcol+0]=f2tf(v4.x); Vs[r][lcol+1]=f2tf(v4.y);
            Vs[r][lcol+2]=f2tf(v4.z); Vs[r][lcol+3]=f2tf(v4.w);
        }
        __syncthreads();

        // S = Q K^T for this warp's 16 rows x 128 cols
        float c[16][4] = {};
#pragma unroll
        for (int ks=0; ks<8; ks++){
            uint32_t a[4];
            a[0]=Qs[r0+g  ][ks*8+t];   a[1]=Qs[r0+g+8][ks*8+t];
            a[2]=Qs[r0+g  ][ks*8+t+4]; a[3]=Qs[r0+g+8][ks*8+t+4];
#pragma unroll
            for (int ni=0;ni<16;ni++){
                uint32_t b[2];
                b[0]=Ks[ni*8+g][ks*8+t];
                b[1]=Ks[ni*8+g][ks*8+t+4];
                mma8(c[ni], a, b);
            }
        }
        // scale + adj
#pragma unroll
        for (int ni=0;ni<16;ni++){
            int kk = kb + ni*8 + 2*t;
            c[ni][0] = fmaf(c[ni][0], scale, adj_s[abs(qlo   - kk    )]);
            c[ni][1] = fmaf(c[ni][1], scale, adj_s[abs(qlo   - kk - 1)]);
            c[ni][2] = fmaf(c[ni][2], scale, adj_s[abs(qlo+8 - kk    )]);
            c[ni][3] = fmaf(c[ni][3], scale, adj_s[abs(qlo+8 - kk - 1)]);
        }
        // row max (quad-local rows)
        float rmx_lo=-1e30f, rmx_hi=-1e30f;
#pragma unroll
        for (int ni=0;ni<16;ni++){
            rmx_lo = fmaxf(rmx_lo, fmaxf(c[ni][0], c[ni][1]));
            rmx_hi = fmaxf(rmx_hi, fmaxf(c[ni][2], c[ni][3]));
        }
        rmx_lo = fmaxf(rmx_lo, __shfl_xor_sync(0xffffffffu, rmx_lo, 1));
        rmx_lo = fmaxf(rmx_lo, __shfl_xor_sync(0xffffffffu, rmx_lo, 2));
        rmx_hi = fmaxf(rmx_hi, __shfl_xor_sync(0xffffffffu, rmx_hi, 1));
        rmx_hi = fmaxf(rmx_hi, __shfl_xor_sync(0xffffffffu, rmx_hi, 2));
        float mn_lo = fmaxf(m_lo, rmx_lo), mn_hi = fmaxf(m_hi, rmx_hi);
        float f_lo = __expf(m_lo - mn_lo),  f_hi = __expf(m_hi - mn_hi);
        m_lo = mn_lo; m_hi = mn_hi;
        // exp + rowsum
        float rs_lo=0.f, rs_hi=0.f;
#pragma unroll
        for (int ni=0;ni<16;ni++){
            c[ni][0]=__expf(c[ni][0]-mn_lo); c[ni][1]=__expf(c[ni][1]-mn_lo);
            c[ni][2]=__expf(c[ni][2]-mn_hi); c[ni][3]=__expf(c[ni][3]-mn_hi);
            rs_lo += c[ni][0]+c[ni][1];
            rs_hi += c[ni][2]+c[ni][3];
        }
        rs_lo += __shfl_xor_sync(0xffffffffu, rs_lo, 1);
        rs_lo += __shfl_xor_sync(0xffffffffu, rs_lo, 2);
        rs_hi += __shfl_xor_sync(0xffffffffu, rs_hi, 1);
        rs_hi += __shfl_xor_sync(0xffffffffu, rs_hi, 2);
        l_lo = l_lo*f_lo + rs_lo;
        l_hi = l_hi*f_hi + rs_hi;
#pragma unroll
        for (int ni=0;ni<8;ni++){
            o[ni][0]*=f_lo; o[ni][1]*=f_lo; o[ni][2]*=f_hi; o[ni][3]*=f_hi;
        }
        // P @ V : convert C-layout P regs to A-frags via quad shuffles
        const int qb = lane & ~3;
        const int srcA = qb + (t>>1), srcB = srcA + 2;
        const bool odd = (t&1);
#pragma unroll
        for (int kp=0; kp<16; kp++){
            float v0 = __shfl_sync(0xffffffffu, c[kp][0], srcA);
            float v1 = __shfl_sync(0xffffffffu, c[kp][1], srcA);
            float v2 = __shfl_sync(0xffffffffu, c[kp][2], srcA);
            float v3 = __shfl_sync(0xffffffffu, c[kp][3], srcA);
            float w0 = __shfl_sync(0xffffffffu, c[kp][0], srcB);
            float w1 = __shfl_sync(0xffffffffu, c[kp][1], srcB);
            float w2 = __shfl_sync(0xffffffffu, c[kp][2], srcB);
            float w3 = __shfl_sync(0xffffffffu, c[kp][3], srcB);
            uint32_t a[4];
            a[0] = f2tf(odd ? v1 : v0);
            a[1] = f2tf(odd ? v3 : v2);
            a[2] = f2tf(odd ? w1 : w0);
            a[3] = f2tf(odd ? w3 : w2);
#pragma unroll
            for (int ni=0;ni<8;ni++){
                uint32_t b[2];
                b[0]=Vs[kp*8+t  ][ni*8+g];
                b[1]=Vs[kp*8+t+4][ni*8+g];
                mma8(o[ni], a, b);
            }
        }
        __syncthreads();
    }

    // stash global-softmax output (already normalized) into smem (overlay on Vs)
    float rcp_lo = 1.f/l_lo, rcp_hi = 1.f/l_hi;
#pragma unroll
    for (int ni=0;ni<8;ni++){
        Og[r0+g  ][ni*8+2*t  ] = o[ni][0]*rcp_lo;
        Og[r0+g  ][ni*8+2*t+1] = o[ni][1]*rcp_lo;
        Og[r0+g+8][ni*8+2*t  ] = o[ni][2]*rcp_hi;
        Og[r0+g+8][ni*8+2*t+1] = o[ni][3]*rcp_hi;
    }
    __syncwarp();

    // ---- local-window epilogue: 2 lanes per row, each handles 32 dims ----
    const float aa = 1.f/(1.f+__expf(-alpha[layer]));
    const int rowl = r0 + (lane>>1);
    const int q = q0 + rowl;
    const int d0 = (lane&1)*32;
    const int lo = (q-4>0)? q-4 : 0;
    const int hi = (q+4<Tn-1)? q+4 : Tn-1;
    const int nw = hi-lo+1;

    float s[9];
    for (int j=0;j<nw;j++){
        const float* krow = &Kp[(size_t)(lo+j)*DHn + d0];
        float dot = 0.f;
#pragma unroll
        for (int i=0;i<32;i++)
            dot = fmaf(__uint_as_float(Qs[rowl][d0+i]), __uint_as_float(f2tf(krow[i])), dot);
        dot += __shfl_xor_sync(0xffffffffu, dot, 1);
        s[j] = fmaf(dot, scale, adj_s[abs(q-(lo+j))]);
    }
    float lm = -1e30f;
    for (int j=0;j<nw;j++) lm = fmaxf(lm, s[j]);
    float ls = 0.f;
    for (int j=0;j<nw;j++){ s[j] = __expf(s[j]-lm); ls += s[j]; }
    float linv = (1.f-aa)/ls;

    float acc[32];
#pragma unroll
    for (int i=0;i<32;i++) acc[i] = aa*Og[rowl][d0+i];
    for (int j=0;j<nw;j++){
        float w = s[j]*linv;
        const float* vrow = &Vp[(size_t)(lo+j)*DHn + d0];
#pragma unroll
        for (int i=0;i<32;i++) acc[i] = fmaf(w, vrow[i], acc[i]);
    }
    float* outp = &g_tmp[(size_t)p*Tn*DHn + (size_t)q*DHn + d0];
#pragma unroll
    for (int i=0;i<32;i+=4){
        float4 v;
        v.x=powtf(acc[i]); v.y=powtf(acc[i+1]); v.z=powtf(acc[i+2]); v.w=powtf(acc[i+3]);
        *(float4*)&outp[i] = v;
    }
}

// ---------------- column L2 norms over seq axis (per b,d) ----------------
__global__ void k_colnorm(){
    int tid = threadIdx.x;
    int col = blockIdx.x*8 + (tid>>5);   // 0..4095
    int lane = tid&31;
    int b = col >> 9, d = col & (Dn-1);
    const float* base = g_tmp + (size_t)b*Tn*Dn + d;
    float sum = 0.f;
    for (int t=lane; t<Tn; t+=32){ float v = base[(size_t)t*Dn]; sum = fmaf(v,v,sum); }
#pragma unroll
    for (int o=16;o;o>>=1) sum += __shfl_xor_sync(0xffffffffu,sum,o);
    if (lane==0) g_invnorm[col] = 1.f/fmaxf(sqrtf(sum), 1e-12f);
}

// ---------------- LayerNorm over D, in place on g_xb ----------------
__global__ __launch_bounds__(128) void k_ln(
    const float* __restrict__ lng, const float* __restrict__ lnb, int layer)
{
    __shared__ float shm[10];
    int r = blockIdx.x;
    int tid = threadIdx.x, lane = tid&31, wid = tid>>5;
    float v[4];
    float sum=0.f, sq=0.f;
#pragma unroll
    for (int j=0;j<4;j++){
        v[j] = g_xb[(size_t)r*Dn + tid + j*128];
        sum += v[j]; sq = fmaf(v[j],v[j],sq);
    }
#pragma unroll
    for (int o=16;o;o>>=1){ sum += __shfl_xor_sync(0xffffffffu,sum,o); sq += __shfl_xor_sync(0xffffffffu,sq,o); }
    if (lane==0){ shm[wid]=sum; shm[4+wid]=sq; }
    __syncthreads();
    if (tid==0){ shm[8]=shm[0]+shm[1]+shm[2]+shm[3]; shm[9]=shm[4]+shm[5]+shm[6]+shm[7]; }
    __syncthreads();
    float mu  = shm[8]*(1.f/Dn);
    float var = shm[9]*(1.f/Dn) - mu*mu;
    float rstd = rsqrtf(fmaxf(var,0.f) + 1e-5f);
    const float* gg = lng + layer*Dn;
    const float* bb = lnb + layer*Dn;
#pragma unroll
    for (int j=0;j<4;j++){
        int d = tid + j*128;
        g_xb[(size_t)r*Dn + d] = (v[j]-mu)*rstd*gg[d] + bb[d];
    }
}

// ---------------- launch ----------------
extern "C" void kernel_launch(void* const* d_in, const int* in_sizes, int n_in,
                              void* d_out, int out_size)
{
    const float* x     = (const float*)d_in[0];
    const float* Wq    = (const float*)d_in[1];
    const float* bq    = (const float*)d_in[2];
    const float* Wk    = (const float*)d_in[3];
    const float* bk    = (const float*)d_in[4];
    const float* Wv    = (const float*)d_in[5];
    const float* bv    = (const float*)d_in[6];
    const float* Wo    = (const float*)d_in[7];
    const float* bo    = (const float*)d_in[8];
    const float* alpha = (const float*)d_in[9];
    const float* ln_g  = (const float*)d_in[10];
    const float* ln_b  = (const float*)d_in[11];
    const float* adj_w = (const float*)d_in[12];
    const float* adj_b = (const float*)d_in[13];
    float* out = (float*)d_out;

    cudaFuncSetAttribute(k_flash, cudaFuncAttributeMaxDynamicSharedMemorySize, FLASH_SMEM);

    k_transpose_in<<<(ROWS*Dn)/256, 256>>>(x);
    k_adj<<<1, Tn>>>(adj_w, adj_b);
    for (int l=0; l<2; l++){
        k_proj_qkv<<<dim3(8,64,3), 256>>>(Wq,Wk,Wv,bq,bk,bv,l);
        k_flash<<<dim3(8,64), 256, FLASH_SMEM>>>(alpha, l);
        k_colnorm<<<512, 256>>>();
        k_proj_out<<<dim3(8,64), 256>>>(Wo, bo, l);
        k_ln<<<ROWS, 128>>>(ln_g, ln_b, l);
    }
    k_transpose_out<<<(ROWS*Dn)/256, 256>>>(out);
}

// round 6
// speedup vs baseline: 1.1486x; 1.1486x over previous
#include <cuda_runtime.h>
#include <cuda_fp16.h>
#include <math.h>
#include <stdint.h>

#define Tn 1024
#define Bn 8
#define Dn 512
#define Hn 8
#define DHn 64
#define NPAIR 64           // Hn*Bn
#define ROWS (Bn*Tn)       // 8192

// ---------------- scratch (device globals: allocation-free) ----------------
__device__ float g_xb[Bn*Tn*Dn];
__device__ float g_Q [Bn*Tn*Dn];
__device__ float g_K [Bn*Tn*Dn];
__device__ float g_V [Bn*Tn*Dn];
__device__ float g_tmp[Bn*Tn*Dn];
__device__ float g_invnorm[Bn*Dn];
__device__ float g_adj[Tn];

__device__ __forceinline__ float powtf(float v){
    return sqrtf(fmaxf(v,0.f)) - sqrtf(fmaxf(-v,0.f));
}

__device__ __forceinline__ uint32_t packh2(float a, float b){
    __half2 h = __floats2half2_rn(a, b);   // .x (low) = a
    return *(uint32_t*)&h;
}

// mma.sync m16n8k16 fp16 in, fp32 accum, row.col
__device__ __forceinline__ void mma16(float* c, const uint32_t* a, const uint32_t* b){
    asm volatile(
        "mma.sync.aligned.m16n8k16.row.col.f32.f16.f16.f32 "
        "{%0,%1,%2,%3},{%4,%5,%6,%7},{%8,%9},{%0,%1,%2,%3};"
        : "+f"(c[0]),"+f"(c[1]),"+f"(c[2]),"+f"(c[3])
        : "r"(a[0]),"r"(a[1]),"r"(a[2]),"r"(a[3]),"r"(b[0]),"r"(b[1]));
}

// ---------------- transposes ----------------
__global__ void k_transpose_in(const float* __restrict__ x){
    int idx = blockIdx.x*256 + threadIdx.x;          // [B,T,D] linear
    int d = idx & (Dn-1);
    int t = (idx >> 9) & (Tn-1);
    int b = idx >> 19;
    g_xb[idx] = x[(t*Bn + b)*Dn + d];
}

__global__ void k_transpose_out(float* __restrict__ out){
    int idx = blockIdx.x*256 + threadIdx.x;          // [T,B,D] linear
    int d = idx & (Dn-1);
    int b = (idx >> 9) & (Bn-1);
    int t = idx >> 12;
    out[idx] = g_xb[((b<<10) + t)*Dn + d];
}

// ---------------- adj table ----------------
__global__ void k_adj(const float* __restrict__ aw, const float* __restrict__ ab){
    int i = threadIdx.x;
    float dist = (float)i;
    g_adj[i] = expf(-fabsf(aw[0]*dist*dist - ab[0]));
}

// ================= fp16 projection GEMM: C = A @ W + b =================
// M=8192, N=512, K=512. Block 128x64, BK=32. 8 warps 4(m)x2(n), warp 32x32.
// Ah2: [m][k/2] half2 payload; Bh2: [k/2][n] half2 (pairs over k).
__global__ __launch_bounds__(256) void k_proj_qkv(
    const float* __restrict__ Wq, const float* __restrict__ Wk, const float* __restrict__ Wv,
    const float* __restrict__ bq, const float* __restrict__ bk, const float* __restrict__ bv,
    int layer)
{
    __shared__ uint32_t Ah2[128][20];   // stride%32==4-class -> a-frag conflict free
    __shared__ uint32_t Bh2[16][72];    // stride%32==8 -> b-frag conflict free
    int tid = threadIdx.x;
    int z = blockIdx.z;
    const float* W    = (z==0 ? Wq : (z==1 ? Wk : Wv)) + (size_t)layer*Dn*Dn;
    const float* bias = (z==0 ? bq : (z==1 ? bk : bv)) + layer*Dn;
    float* C          = (z==0 ? g_Q : (z==1 ? g_K : g_V));
    int m0 = blockIdx.y*128, n0 = blockIdx.x*64;
    int wid = tid>>5, lane = tid&31, g = lane>>2, t = lane&3;
    int m_off = (wid>>1)*32, n_off = (wid&1)*32;

    float c[2][4][4] = {};
    int arow = tid>>3, acol = (tid&7)*4;     // A: 32 rows x 8 col-groups
    int pr   = tid>>4, pc   = (tid&15)*4;    // B: 16 pair-rows x 16 col-groups

    for (int k0=0; k0<Dn; k0+=32){
#pragma unroll
        for (int i=0;i<4;i++){
            float4 v = *(const float4*)&g_xb[(size_t)(m0+arow+i*32)*Dn + k0 + acol];
            Ah2[arow+i*32][(acol>>1)  ] = packh2(v.x, v.y);
            Ah2[arow+i*32][(acol>>1)+1] = packh2(v.z, v.w);
        }
        {
            float4 va = *(const float4*)&W[(size_t)(k0+2*pr  )*Dn + n0 + pc];
            float4 vb = *(const float4*)&W[(size_t)(k0+2*pr+1)*Dn + n0 + pc];
            Bh2[pr][pc+0] = packh2(va.x, vb.x);
            Bh2[pr][pc+1] = packh2(va.y, vb.y);
            Bh2[pr][pc+2] = packh2(va.z, vb.z);
            Bh2[pr][pc+3] = packh2(va.w, vb.w);
        }
        __syncthreads();
#pragma unroll
        for (int j=0; j<2; j++){
            uint32_t a[2][4], b[4][2];
#pragma unroll
            for (int mi=0;mi<2;mi++){
                int r = m_off+mi*16;
                a[mi][0]=Ah2[r+g  ][j*8+t];   a[mi][1]=Ah2[r+g+8][j*8+t];
                a[mi][2]=Ah2[r+g  ][j*8+t+4]; a[mi][3]=Ah2[r+g+8][j*8+t+4];
            }
#pragma unroll
            for (int ni=0;ni<4;ni++){
                b[ni][0]=Bh2[j*8+t  ][n_off+ni*8+g];
                b[ni][1]=Bh2[j*8+t+4][n_off+ni*8+g];
            }
#pragma unroll
            for (int mi=0;mi<2;mi++)
#pragma unroll
                for (int ni=0;ni<4;ni++) mma16(c[mi][ni], a[mi], b[ni]);
        }
        __syncthreads();
    }
#pragma unroll
    for (int mi=0;mi<2;mi++){
#pragma unroll
        for (int ni=0;ni<4;ni++){
            int row = m0 + m_off + mi*16 + g;
            int col = n0 + n_off + ni*8 + 2*t;
            float b0 = bias[col], b1 = bias[col+1];
            float2 v0 = {c[mi][ni][0]+b0, c[mi][ni][1]+b1};
            float2 v1 = {c[mi][ni][2]+b0, c[mi][ni][3]+b1};
            *(float2*)&C[(size_t)row*Dn + col]     = v0;
            *(float2*)&C[(size_t)(row+8)*Dn + col] = v1;
        }
    }
}

// ---- out proj: g_xb = g_xb + (g_tmp * invnorm) @ Wo + bo ----
__global__ __launch_bounds__(256) void k_proj_out(
    const float* __restrict__ Wo, const float* __restrict__ bo, int layer)
{
    __shared__ uint32_t Ah2[128][20];
    __shared__ uint32_t Bh2[16][72];
    int tid = threadIdx.x;
    const float* W    = Wo + (size_t)layer*Dn*Dn;
    const float* bias = bo + layer*Dn;
    int m0 = blockIdx.y*128, n0 = blockIdx.x*64;
    int wid = tid>>5, lane = tid&31, g = lane>>2, t = lane&3;
    int m_off = (wid>>1)*32, n_off = (wid&1)*32;

    float c[2][4][4] = {};
    int arow = tid>>3, acol = (tid&7)*4;
    int pr   = tid>>4, pc   = (tid&15)*4;

    for (int k0=0; k0<Dn; k0+=32){
#pragma unroll
        for (int i=0;i<4;i++){
            int m = m0+arow+i*32;
            float4 v = *(const float4*)&g_tmp[(size_t)m*Dn + k0 + acol];
            float4 s = *(const float4*)&g_invnorm[(m>>10)*Dn + k0 + acol];
            Ah2[arow+i*32][(acol>>1)  ] = packh2(v.x*s.x, v.y*s.y);
            Ah2[arow+i*32][(acol>>1)+1] = packh2(v.z*s.z, v.w*s.w);
        }
        {
            float4 va = *(const float4*)&W[(size_t)(k0+2*pr  )*Dn + n0 + pc];
            float4 vb = *(const float4*)&W[(size_t)(k0+2*pr+1)*Dn + n0 + pc];
            Bh2[pr][pc+0] = packh2(va.x, vb.x);
            Bh2[pr][pc+1] = packh2(va.y, vb.y);
            Bh2[pr][pc+2] = packh2(va.z, vb.z);
            Bh2[pr][pc+3] = packh2(va.w, vb.w);
        }
        __syncthreads();
#pragma unroll
        for (int j=0; j<2; j++){
            uint32_t a[2][4], b[4][2];
#pragma unroll
            for (int mi=0;mi<2;mi++){
                int r = m_off+mi*16;
                a[mi][0]=Ah2[r+g  ][j*8+t];   a[mi][1]=Ah2[r+g+8][j*8+t];
                a[mi][2]=Ah2[r+g  ][j*8+t+4]; a[mi][3]=Ah2[r+g+8][j*8+t+4];
            }
#pragma unroll
            for (int ni=0;ni<4;ni++){
                b[ni][0]=Bh2[j*8+t  ][n_off+ni*8+g];
                b[ni][1]=Bh2[j*8+t+4][n_off+ni*8+g];
            }
#pragma unroll
            for (int mi=0;mi<2;mi++)
#pragma unroll
                for (int ni=0;ni<4;ni++) mma16(c[mi][ni], a[mi], b[ni]);
        }
        __syncthreads();
    }
#pragma unroll
    for (int mi=0;mi<2;mi++){
#pragma unroll
        for (int ni=0;ni<4;ni++){
            int row = m0 + m_off + mi*16 + g;
            int col = n0 + n_off + ni*8 + 2*t;
            float b0 = bias[col], b1 = bias[col+1];
            float2 r0 = *(float2*)&g_xb[(size_t)row*Dn + col];
            float2 r1 = *(float2*)&g_xb[(size_t)(row+8)*Dn + col];
            float2 v0 = {c[mi][ni][0]+b0+r0.x, c[mi][ni][1]+b1+r0.y};
            float2 v1 = {c[mi][ni][2]+b0+r1.x, c[mi][ni][3]+b1+r1.y};
            *(float2*)&g_xb[(size_t)row*Dn + col]     = v0;
            *(float2*)&g_xb[(size_t)(row+8)*Dn + col] = v1;
        }
    }
}

// ================= fused flash attention (fp16 mma, no shuffles) =================
// grid (8 q-tiles, 64 pairs), 256 threads = 8 warps; warp w owns rows w*16..w*16+15.
// Qh2/Kh2: [row][dh/2] half2; Vh2: [k/2][n] half2 (pairs over k).
#define QK_STRIDE 36
#define V_STRIDE2 72
#define SH_Q 0
#define SH_K (128*QK_STRIDE)
#define SH_V (2*128*QK_STRIDE)
#define SH_ADJ (2*128*QK_STRIDE + 64*V_STRIDE2)
#define FLASH_SMEM ((2*128*QK_STRIDE + 64*V_STRIDE2 + Tn)*4)
#define OG_STRIDE 68

__global__ __launch_bounds__(256,1) void k_flash(const float* __restrict__ alpha, int layer){
    extern __shared__ uint32_t sh[];
    uint32_t (*Qh2)[QK_STRIDE] = (uint32_t(*)[QK_STRIDE])(sh + SH_Q);
    uint32_t (*Kh2)[QK_STRIDE] = (uint32_t(*)[QK_STRIDE])(sh + SH_K);
    uint32_t (*Vh2)[V_STRIDE2] = (uint32_t(*)[V_STRIDE2])(sh + SH_V);
    float* adj_s = (float*)(sh + SH_ADJ);
    float (*Og)[OG_STRIDE] = (float(*)[OG_STRIDE])(sh + SH_K);  // overlay K+V after mainloop

    const int tid = threadIdx.x;
    const int p  = blockIdx.y;
    const int q0 = blockIdx.x*128;
    const float* Qp = g_Q + (size_t)p*Tn*DHn;
    const float* Kp = g_K + (size_t)p*Tn*DHn;
    const float* Vp = g_V + (size_t)p*Tn*DHn;

    for (int i=tid;i<Tn;i+=256) adj_s[i] = g_adj[i];
    const int lrow = tid>>4, lcol = (tid&15)*4;
#pragma unroll
    for (int i=0;i<8;i++){
        int r = lrow + i*16;
        float4 q4 = *(const float4*)&Qp[(size_t)(q0+r)*DHn + lcol];
        Qh2[r][(lcol>>1)  ] = packh2(q4.x, q4.y);
        Qh2[r][(lcol>>1)+1] = packh2(q4.z, q4.w);
    }
    __syncthreads();

    const int wid = tid>>5, lane = tid&31, g = lane>>2, t = lane&3;
    const int r0 = wid*16;
    const int qlo = q0 + r0 + g;
    const float scale = 0.04419417382415922f;   // 1/sqrt(512)

    float m_lo=-1e30f, m_hi=-1e30f, l_lo=0.f, l_hi=0.f;
    float o[8][4] = {};

    for (int kb=0; kb<Tn; kb+=128){
#pragma unroll
        for (int i=0;i<8;i++){
            int r = lrow + i*16;
            float4 k4 = *(const float4*)&Kp[(size_t)(kb+r)*DHn + lcol];
            Kh2[r][(lcol>>1)  ] = packh2(k4.x, k4.y);
            Kh2[r][(lcol>>1)+1] = packh2(k4.z, k4.w);
        }
#pragma unroll
        for (int i=0;i<4;i++){
            int prr = lrow + i*16;   // pair-row 0..63
            float4 va = *(const float4*)&Vp[(size_t)(kb+2*prr  )*DHn + lcol];
            float4 vb = *(const float4*)&Vp[(size_t)(kb+2*prr+1)*DHn + lcol];
            Vh2[prr][lcol+0] = packh2(va.x, vb.x);
            Vh2[prr][lcol+1] = packh2(va.y, vb.y);
            Vh2[prr][lcol+2] = packh2(va.z, vb.z);
            Vh2[prr][lcol+3] = packh2(va.w, vb.w);
        }
        __syncthreads();

        // S = Q K^T: warp's 16 rows x 128 cols, 4 k-steps of 16
        float c[16][4] = {};
#pragma unroll
        for (int ks=0; ks<4; ks++){
            uint32_t a[4];
            a[0]=Qh2[r0+g  ][ks*8+t];   a[1]=Qh2[r0+g+8][ks*8+t];
            a[2]=Qh2[r0+g  ][ks*8+t+4]; a[3]=Qh2[r0+g+8][ks*8+t+4];
#pragma unroll
            for (int ni=0;ni<16;ni++){
                uint32_t b[2];
                b[0]=Kh2[ni*8+g][ks*8+t];
                b[1]=Kh2[ni*8+g][ks*8+t+4];
                mma16(c[ni], a, b);
            }
        }
        // scale + adj
#pragma unroll
        for (int ni=0;ni<16;ni++){
            int kk = kb + ni*8 + 2*t;
            c[ni][0] = fmaf(c[ni][0], scale, adj_s[abs(qlo   - kk    )]);
            c[ni][1] = fmaf(c[ni][1], scale, adj_s[abs(qlo   - kk - 1)]);
            c[ni][2] = fmaf(c[ni][2], scale, adj_s[abs(qlo+8 - kk    )]);
            c[ni][3] = fmaf(c[ni][3], scale, adj_s[abs(qlo+8 - kk - 1)]);
        }
        // online softmax stats (rows live inside one quad)
        float rmx_lo=-1e30f, rmx_hi=-1e30f;
#pragma unroll
        for (int ni=0;ni<16;ni++){
            rmx_lo = fmaxf(rmx_lo, fmaxf(c[ni][0], c[ni][1]));
            rmx_hi = fmaxf(rmx_hi, fmaxf(c[ni][2], c[ni][3]));
        }
        rmx_lo = fmaxf(rmx_lo, __shfl_xor_sync(0xffffffffu, rmx_lo, 1));
        rmx_lo = fmaxf(rmx_lo, __shfl_xor_sync(0xffffffffu, rmx_lo, 2));
        rmx_hi = fmaxf(rmx_hi, __shfl_xor_sync(0xffffffffu, rmx_hi, 1));
        rmx_hi = fmaxf(rmx_hi, __shfl_xor_sync(0xffffffffu, rmx_hi, 2));
        float mn_lo = fmaxf(m_lo, rmx_lo), mn_hi = fmaxf(m_hi, rmx_hi);
        float f_lo = __expf(m_lo - mn_lo),  f_hi = __expf(m_hi - mn_hi);
        m_lo = mn_lo; m_hi = mn_hi;
        float rs_lo=0.f, rs_hi=0.f;
#pragma unroll
        for (int ni=0;ni<16;ni++){
            c[ni][0]=__expf(c[ni][0]-mn_lo); c[ni][1]=__expf(c[ni][1]-mn_lo);
            c[ni][2]=__expf(c[ni][2]-mn_hi); c[ni][3]=__expf(c[ni][3]-mn_hi);
            rs_lo += c[ni][0]+c[ni][1];
            rs_hi += c[ni][2]+c[ni][3];
        }
        rs_lo += __shfl_xor_sync(0xffffffffu, rs_lo, 1);
        rs_lo += __shfl_xor_sync(0xffffffffu, rs_lo, 2);
        rs_hi += __shfl_xor_sync(0xffffffffu, rs_hi, 1);
        rs_hi += __shfl_xor_sync(0xffffffffu, rs_hi, 2);
        l_lo = l_lo*f_lo + rs_lo;
        l_hi = l_hi*f_hi + rs_hi;
#pragma unroll
        for (int ni=0;ni<8;ni++){
            o[ni][0]*=f_lo; o[ni][1]*=f_lo; o[ni][2]*=f_hi; o[ni][3]*=f_hi;
        }
        // P @ V : C-layout regs pack DIRECTLY into fp16 k16 A-frags (no shuffles)
#pragma unroll
        for (int j=0; j<8; j++){
            uint32_t a[4];
            a[0] = packh2(c[2*j  ][0], c[2*j  ][1]);
            a[1] = packh2(c[2*j  ][2], c[2*j  ][3]);
            a[2] = packh2(c[2*j+1][0], c[2*j+1][1]);
            a[3] = packh2(c[2*j+1][2], c[2*j+1][3]);
#pragma unroll
            for (int ni=0;ni<8;ni++){
                uint32_t b[2];
                b[0]=Vh2[j*8+t  ][ni*8+g];
                b[1]=Vh2[j*8+t+4][ni*8+g];
                mma16(o[ni], a, b);
            }
        }
        __syncthreads();
    }

    // stash normalized global-softmax output into smem overlay
    float rcp_lo = 1.f/l_lo, rcp_hi = 1.f/l_hi;
#pragma unroll
    for (int ni=0;ni<8;ni++){
        Og[r0+g  ][ni*8+2*t  ] = o[ni][0]*rcp_lo;
        Og[r0+g  ][ni*8+2*t+1] = o[ni][1]*rcp_lo;
        Og[r0+g+8][ni*8+2*t  ] = o[ni][2]*rcp_hi;
        Og[r0+g+8][ni*8+2*t+1] = o[ni][3]*rcp_hi;
    }
    __syncwarp();

    // ---- local-window epilogue: 2 lanes per row, each handles 32 dims ----
    const float aa = 1.f/(1.f+__expf(-alpha[layer]));
    const int rowl = r0 + (lane>>1);
    const int q = q0 + rowl;
    const int d0 = (lane&1)*32;
    const int lo = (q-4>0)? q-4 : 0;
    const int hi = (q+4<Tn-1)? q+4 : Tn-1;
    const int nw = hi-lo+1;

    float s[9];
    for (int j=0;j<nw;j++){
        const float* krow = &Kp[(size_t)(lo+j)*DHn + d0];
        float dot = 0.f;
#pragma unroll
        for (int i=0;i<16;i++){
            __half2 q2 = *(__half2*)&Qh2[rowl][(d0>>1)+i];
            dot = fmaf(__half2float(q2.x), krow[2*i  ], dot);
            dot = fmaf(__half2float(q2.y), krow[2*i+1], dot);
        }
        dot += __shfl_xor_sync(0xffffffffu, dot, 1);
        s[j] = fmaf(dot, scale, adj_s[abs(q-(lo+j))]);
    }
    float lm = -1e30f;
    for (int j=0;j<nw;j++) lm = fmaxf(lm, s[j]);
    float ls = 0.f;
    for (int j=0;j<nw;j++){ s[j] = __expf(s[j]-lm); ls += s[j]; }
    float linv = (1.f-aa)/ls;

    float acc[32];
#pragma unroll
    for (int i=0;i<32;i++) acc[i] = aa*Og[rowl][d0+i];
    for (int j=0;j<nw;j++){
        float w = s[j]*linv;
        const float* vrow = &Vp[(size_t)(lo+j)*DHn + d0];
#pragma unroll
        for (int i=0;i<32;i++) acc[i] = fmaf(w, vrow[i], acc[i]);
    }
    float* outp = &g_tmp[(size_t)p*Tn*DHn + (size_t)q*DHn + d0];
#pragma unroll
    for (int i=0;i<32;i+=4){
        float4 v;
        v.x=powtf(acc[i]); v.y=powtf(acc[i+1]); v.z=powtf(acc[i+2]); v.w=powtf(acc[i+3]);
        *(float4*)&outp[i] = v;
    }
}

// ---------------- column L2 norms over seq axis (per b,d) ----------------
__global__ void k_colnorm(){
    int tid = threadIdx.x;
    int col = blockIdx.x*8 + (tid>>5);   // 0..4095
    int lane = tid&31;
    int b = col >> 9, d = col & (Dn-1);
    const float* base = g_tmp + (size_t)b*Tn*Dn + d;
    float sum = 0.f;
    for (int t=lane; t<Tn; t+=32){ float v = base[(size_t)t*Dn]; sum = fmaf(v,v,sum); }
#pragma unroll
    for (int o=16;o;o>>=1) sum += __shfl_xor_sync(0xffffffffu,sum,o);
    if (lane==0) g_invnorm[col] = 1.f/fmaxf(sqrtf(sum), 1e-12f);
}

// ---------------- LayerNorm over D, in place on g_xb ----------------
__global__ __launch_bounds__(128) void k_ln(
    const float* __restrict__ lng, const float* __restrict__ lnb, int layer)
{
    __shared__ float shm[10];
    int r = blockIdx.x;
    int tid = threadIdx.x, lane = tid&31, wid = tid>>5;
    float v[4];
    float sum=0.f, sq=0.f;
#pragma unroll
    for (int j=0;j<4;j++){
        v[j] = g_xb[(size_t)r*Dn + tid + j*128];
        sum += v[j]; sq = fmaf(v[j],v[j],sq);
    }
#pragma unroll
    for (int o=16;o;o>>=1){ sum += __shfl_xor_sync(0xffffffffu,sum,o); sq += __shfl_xor_sync(0xffffffffu,sq,o); }
    if (lane==0){ shm[wid]=sum; shm[4+wid]=sq; }
    __syncthreads();
    if (tid==0){ shm[8]=shm[0]+shm[1]+shm[2]+shm[3]; shm[9]=shm[4]+shm[5]+shm[6]+shm[7]; }
    __syncthreads();
    float mu  = shm[8]*(1.f/Dn);
    float var = shm[9]*(1.f/Dn) - mu*mu;
    float rstd = rsqrtf(fmaxf(var,0.f) + 1e-5f);
    const float* gg = lng + layer*Dn;
    const float* bb = lnb + layer*Dn;
#pragma unroll
    for (int j=0;j<4;j++){
        int d = tid + j*128;
        g_xb[(size_t)r*Dn + d] = (v[j]-mu)*rstd*gg[d] + bb[d];
    }
}

// ---------------- launch ----------------
extern "C" void kernel_launch(void* const* d_in, const int* in_sizes, int n_in,
                              void* d_out, int out_size)
{
    const float* x     = (const float*)d_in[0];
    const float* Wq    = (const float*)d_in[1];
    const float* bq    = (const float*)d_in[2];
    const float* Wk    = (const float*)d_in[3];
    const float* bk    = (const float*)d_in[4];
    const float* Wv    = (const float*)d_in[5];
    const float* bv    = (const float*)d_in[6];
    const float* Wo    = (const float*)d_in[7];
    const float* bo    = (const float*)d_in[8];
    const float* alpha = (const float*)d_in[9];
    const float* ln_g  = (const float*)d_in[10];
    const float* ln_b  = (const float*)d_in[11];
    const float* adj_w = (const float*)d_in[12];
    const float* adj_b = (const float*)d_in[13];
    float* out = (float*)d_out;

    cudaFuncSetAttribute(k_flash, cudaFuncAttributeMaxDynamicSharedMemorySize, FLASH_SMEM);

    k_transpose_in<<<(ROWS*Dn)/256, 256>>>(x);
    k_adj<<<1, Tn>>>(adj_w, adj_b);
    for (int l=0; l<2; l++){
        k_proj_qkv<<<dim3(8,64,3), 256>>>(Wq,Wk,Wv,bq,bk,bv,l);
        k_flash<<<dim3(8,64), 256, FLASH_SMEM>>>(alpha, l);
        k_colnorm<<<512, 256>>>();
        k_proj_out<<<dim3(8,64), 256>>>(Wo, bo, l);
        k_ln<<<ROWS, 128>>>(ln_g, ln_b, l);
    }
    k_transpose_out<<<(ROWS*Dn)/256, 256>>>(out);
}

// round 7
// speedup vs baseline: 2.1914x; 1.9079x over previous
#include <cuda_runtime.h>
#include <cuda_fp16.h>
#include <math.h>
#include <stdint.h>

#define Tn 1024
#define Bn 8
#define Dn 512
#define Hn 8
#define DHn 64
#define NPAIR 64           // Hn*Bn
#define ROWS (Bn*Tn)       // 8192

// ---------------- scratch (device globals: allocation-free) ----------------
__device__ float    g_xb [Bn*Tn*Dn];
__device__ uint32_t g_Qh [Bn*Tn*Dn/2];   // half2 pairs over d
__device__ uint32_t g_Kh [Bn*Tn*Dn/2];
__device__ uint32_t g_Vh [Bn*Tn*Dn/2];
__device__ float    g_tmp[Bn*Tn*Dn];
__device__ float    g_invnorm[Bn*Dn];
__device__ float    g_adj[Tn];

__device__ __forceinline__ float powtf(float v){
    return sqrtf(fmaxf(v,0.f)) - sqrtf(fmaxf(-v,0.f));
}

__device__ __forceinline__ uint32_t packh2(float a, float b){
    __half2 h = __floats2half2_rn(a, b);   // .x (low) = a
    return *(uint32_t*)&h;
}

// mma.sync m16n8k16 fp16 in, fp32 accum, row.col
__device__ __forceinline__ void mma16(float* c, const uint32_t* a, const uint32_t* b){
    asm volatile(
        "mma.sync.aligned.m16n8k16.row.col.f32.f16.f16.f32 "
        "{%0,%1,%2,%3},{%4,%5,%6,%7},{%8,%9},{%0,%1,%2,%3};"
        : "+f"(c[0]),"+f"(c[1]),"+f"(c[2]),"+f"(c[3])
        : "r"(a[0]),"r"(a[1]),"r"(a[2]),"r"(a[3]),"r"(b[0]),"r"(b[1]));
}

// ---------------- transposes ----------------
__global__ void k_transpose_in(const float* __restrict__ x){
    int idx = blockIdx.x*256 + threadIdx.x;          // [B,T,D] linear
    int d = idx & (Dn-1);
    int t = (idx >> 9) & (Tn-1);
    int b = idx >> 19;
    g_xb[idx] = x[(t*Bn + b)*Dn + d];
}

__global__ void k_transpose_out(float* __restrict__ out){
    int idx = blockIdx.x*256 + threadIdx.x;          // [T,B,D] linear
    int d = idx & (Dn-1);
    int b = (idx >> 9) & (Bn-1);
    int t = idx >> 12;
    out[idx] = g_xb[((b<<10) + t)*Dn + d];
}

// ---------------- adj table ----------------
__global__ void k_adj(const float* __restrict__ aw, const float* __restrict__ ab){
    int i = threadIdx.x;
    float dist = (float)i;
    g_adj[i] = expf(-fabsf(aw[0]*dist*dist - ab[0]));
}

// ================= fp16 QKV projection: C(half2) = xb @ W + b =================
__global__ __launch_bounds__(256) void k_proj_qkv(
    const float* __restrict__ Wq, const float* __restrict__ Wk, const float* __restrict__ Wv,
    const float* __restrict__ bq, const float* __restrict__ bk, const float* __restrict__ bv,
    int layer)
{
    __shared__ uint32_t Ah2[128][20];
    __shared__ uint32_t Bh2[16][72];
    int tid = threadIdx.x;
    int z = blockIdx.z;
    const float* W    = (z==0 ? Wq : (z==1 ? Wk : Wv)) + (size_t)layer*Dn*Dn;
    const float* bias = (z==0 ? bq : (z==1 ? bk : bv)) + layer*Dn;
    uint32_t* C       = (z==0 ? g_Qh : (z==1 ? g_Kh : g_Vh));
    int m0 = blockIdx.y*128, n0 = blockIdx.x*64;
    int wid = tid>>5, lane = tid&31, g = lane>>2, t = lane&3;
    int m_off = (wid>>1)*32, n_off = (wid&1)*32;

    float c[2][4][4] = {};
    int arow = tid>>3, acol = (tid&7)*4;
    int pr   = tid>>4, pc   = (tid&15)*4;

    for (int k0=0; k0<Dn; k0+=32){
#pragma unroll
        for (int i=0;i<4;i++){
            float4 v = *(const float4*)&g_xb[(size_t)(m0+arow+i*32)*Dn + k0 + acol];
            Ah2[arow+i*32][(acol>>1)  ] = packh2(v.x, v.y);
            Ah2[arow+i*32][(acol>>1)+1] = packh2(v.z, v.w);
        }
        {
            float4 va = *(const float4*)&W[(size_t)(k0+2*pr  )*Dn + n0 + pc];
            float4 vb = *(const float4*)&W[(size_t)(k0+2*pr+1)*Dn + n0 + pc];
            Bh2[pr][pc+0] = packh2(va.x, vb.x);
            Bh2[pr][pc+1] = packh2(va.y, vb.y);
            Bh2[pr][pc+2] = packh2(va.z, vb.z);
            Bh2[pr][pc+3] = packh2(va.w, vb.w);
        }
        __syncthreads();
#pragma unroll
        for (int j=0; j<2; j++){
            uint32_t a[2][4], b[4][2];
#pragma unroll
            for (int mi=0;mi<2;mi++){
                int r = m_off+mi*16;
                a[mi][0]=Ah2[r+g  ][j*8+t];   a[mi][1]=Ah2[r+g+8][j*8+t];
                a[mi][2]=Ah2[r+g  ][j*8+t+4]; a[mi][3]=Ah2[r+g+8][j*8+t+4];
            }
#pragma unroll
            for (int ni=0;ni<4;ni++){
                b[ni][0]=Bh2[j*8+t  ][n_off+ni*8+g];
                b[ni][1]=Bh2[j*8+t+4][n_off+ni*8+g];
            }
#pragma unroll
            for (int mi=0;mi<2;mi++)
#pragma unroll
                for (int ni=0;ni<4;ni++) mma16(c[mi][ni], a[mi], b[ni]);
        }
        __syncthreads();
    }
#pragma unroll
    for (int mi=0;mi<2;mi++){
#pragma unroll
        for (int ni=0;ni<4;ni++){
            int row = m0 + m_off + mi*16 + g;
            int col = n0 + n_off + ni*8 + 2*t;
            float b0 = bias[col], b1 = bias[col+1];
            int w = col>>1;
            C[(size_t)row*(Dn/2) + w]     = packh2(c[mi][ni][0]+b0, c[mi][ni][1]+b1);
            C[(size_t)(row+8)*(Dn/2) + w] = packh2(c[mi][ni][2]+b0, c[mi][ni][3]+b1);
        }
    }
}

// ---- out proj: g_xb = g_xb + (g_tmp * invnorm) @ Wo + bo ----
__global__ __launch_bounds__(256) void k_proj_out(
    const float* __restrict__ Wo, const float* __restrict__ bo, int layer)
{
    __shared__ uint32_t Ah2[128][20];
    __shared__ uint32_t Bh2[16][72];
    int tid = threadIdx.x;
    const float* W    = Wo + (size_t)layer*Dn*Dn;
    const float* bias = bo + layer*Dn;
    int m0 = blockIdx.y*128, n0 = blockIdx.x*64;
    int wid = tid>>5, lane = tid&31, g = lane>>2, t = lane&3;
    int m_off = (wid>>1)*32, n_off = (wid&1)*32;

    float c[2][4][4] = {};
    int arow = tid>>3, acol = (tid&7)*4;
    int pr   = tid>>4, pc   = (tid&15)*4;

    for (int k0=0; k0<Dn; k0+=32){
#pragma unroll
        for (int i=0;i<4;i++){
            int m = m0+arow+i*32;
            float4 v = *(const float4*)&g_tmp[(size_t)m*Dn + k0 + acol];
            float4 s = *(const float4*)&g_invnorm[(m>>10)*Dn + k0 + acol];
            Ah2[arow+i*32][(acol>>1)  ] = packh2(v.x*s.x, v.y*s.y);
            Ah2[arow+i*32][(acol>>1)+1] = packh2(v.z*s.z, v.w*s.w);
        }
        {
            float4 va = *(const float4*)&W[(size_t)(k0+2*pr  )*Dn + n0 + pc];
            float4 vb = *(const float4*)&W[(size_t)(k0+2*pr+1)*Dn + n0 + pc];
            Bh2[pr][pc+0] = packh2(va.x, vb.x);
            Bh2[pr][pc+1] = packh2(va.y, vb.y);
            Bh2[pr][pc+2] = packh2(va.z, vb.z);
            Bh2[pr][pc+3] = packh2(va.w, vb.w);
        }
        __syncthreads();
#pragma unroll
        for (int j=0; j<2; j++){
            uint32_t a[2][4], b[4][2];
#pragma unroll
            for (int mi=0;mi<2;mi++){
                int r = m_off+mi*16;
                a[mi][0]=Ah2[r+g  ][j*8+t];   a[mi][1]=Ah2[r+g+8][j*8+t];
                a[mi][2]=Ah2[r+g  ][j*8+t+4]; a[mi][3]=Ah2[r+g+8][j*8+t+4];
            }
#pragma unroll
            for (int ni=0;ni<4;ni++){
                b[ni][0]=Bh2[j*8+t  ][n_off+ni*8+g];
                b[ni][1]=Bh2[j*8+t+4][n_off+ni*8+g];
            }
#pragma unroll
            for (int mi=0;mi<2;mi++)
#pragma unroll
                for (int ni=0;ni<4;ni++) mma16(c[mi][ni], a[mi], b[ni]);
        }
        __syncthreads();
    }
#pragma unroll
    for (int mi=0;mi<2;mi++){
#pragma unroll
        for (int ni=0;ni<4;ni++){
            int row = m0 + m_off + mi*16 + g;
            int col = n0 + n_off + ni*8 + 2*t;
            float b0 = bias[col], b1 = bias[col+1];
            float2 r0 = *(float2*)&g_xb[(size_t)row*Dn + col];
            float2 r1 = *(float2*)&g_xb[(size_t)(row+8)*Dn + col];
            float2 v0 = {c[mi][ni][0]+b0+r0.x, c[mi][ni][1]+b1+r0.y};
            float2 v1 = {c[mi][ni][2]+b0+r1.x, c[mi][ni][3]+b1+r1.y};
            *(float2*)&g_xb[(size_t)row*Dn + col]     = v0;
            *(float2*)&g_xb[(size_t)(row+8)*Dn + col] = v1;
        }
    }
}

// ================= fused flash attention: warp-pair key-split =================
// grid (16 q-tiles of 64 rows, 64 pairs), 256 thr = 8 warps = 4 row-groups x 2 key-halves.
// 2 CTAs/SM (regs capped 128, smem 50KB). Pair stats via named barriers.
#define QK_STRIDE 36
#define V_STRIDE2 72
#define SH_Q   0
#define SH_K   (64*QK_STRIDE)                    // 2304
#define SH_V   (SH_K + 128*QK_STRIDE)            // 6912
#define SH_ADJ (SH_V + 64*V_STRIDE2)             // 11520
#define SH_SB  (SH_ADJ + Tn)                     // 12544
#define FLASH_SMEM ((SH_SB + 256)*4)             // 51200 B
#define OG_STRIDE 68

__global__ __launch_bounds__(256,2) void k_flash(const float* __restrict__ alpha, int layer){
    extern __shared__ uint32_t sh[];
    uint32_t (*Qh2)[QK_STRIDE] = (uint32_t(*)[QK_STRIDE])(sh + SH_Q);
    uint32_t (*Kh2)[QK_STRIDE] = (uint32_t(*)[QK_STRIDE])(sh + SH_K);
    uint32_t (*Vh2)[V_STRIDE2] = (uint32_t(*)[V_STRIDE2])(sh + SH_V);
    float* adj_s = (float*)(sh + SH_ADJ);
    float* sb    = (float*)(sh + SH_SB);
    float (*Og)[OG_STRIDE] = (float(*)[OG_STRIDE])(sh + SH_K);  // overlay K+V post-mainloop

    const int tid = threadIdx.x;
    const int p  = blockIdx.y;
    const int q0 = blockIdx.x*64;
    const uint4* Qp4 = (const uint4*)(g_Qh + (size_t)p*Tn*(DHn/2));
    const uint4* Kp4 = (const uint4*)(g_Kh + (size_t)p*Tn*(DHn/2));
    const uint4* Vp4 = (const uint4*)(g_Vh + (size_t)p*Tn*(DHn/2));
    const uint32_t* Kpw = g_Kh + (size_t)p*Tn*(DHn/2);
    const uint32_t* Vpw = g_Vh + (size_t)p*Tn*(DHn/2);

    for (int i=tid;i<Tn;i+=256) adj_s[i] = g_adj[i];
    // Q fill: 64 rows x 8 uint4
#pragma unroll
    for (int i=0;i<2;i++){
        int c = tid + i*256;
        *(uint4*)&Qh2[c>>3][(c&7)<<2] = Qp4[(size_t)(q0 + (c>>3))*8 + (c&7)];
    }
    __syncthreads();

    const int wid = tid>>5, lane = tid&31, g = lane>>2, t = lane&3;
    const int rg = wid>>1, h = wid&1;
    const int r0 = rg*16;
    const int qlo = q0 + r0 + g;
    const int sidx = ((rg*2+h)*8 + g)*2;
    const int pidx = ((rg*2+(h^1))*8 + g)*2;
    const float scale = 0.04419417382415922f;   // 1/sqrt(512)

    float m_lo=-1e30f, m_hi=-1e30f, l_lo=0.f, l_hi=0.f;
    float o[8][4] = {};

    const int vpr = tid>>2, vs2 = (tid&3)*2;

    for (int kb=0; kb<Tn; kb+=128){
        // K fill: 128 rows x 8 uint4
#pragma unroll
        for (int i=0;i<4;i++){
            int c = tid + i*256;
            *(uint4*)&Kh2[c>>3][(c&7)<<2] = Kp4[(size_t)(kb + (c>>3))*8 + (c&7)];
        }
        // V fill: interleave key pairs via PRMT
#pragma unroll
        for (int ss=0; ss<2; ss++){
            int seg = vs2+ss;
            uint4 va = Vp4[(size_t)(kb+2*vpr  )*8 + seg];
            uint4 vb = Vp4[(size_t)(kb+2*vpr+1)*8 + seg];
            uint32_t* dst = &Vh2[vpr][seg*8];
            dst[0]=__byte_perm(va.x,vb.x,0x5410); dst[1]=__byte_perm(va.x,vb.x,0x7632);
            dst[2]=__byte_perm(va.y,vb.y,0x5410); dst[3]=__byte_perm(va.y,vb.y,0x7632);
            dst[4]=__byte_perm(va.z,vb.z,0x5410); dst[5]=__byte_perm(va.z,vb.z,0x7632);
            dst[6]=__byte_perm(va.w,vb.w,0x5410); dst[7]=__byte_perm(va.w,vb.w,0x7632);
        }
        __syncthreads();

        // S = Q K^T: 16 rows x 64 keys (this warp's half)
        float c[8][4] = {};
#pragma unroll
        for (int ks=0; ks<4; ks++){
            uint32_t a[4];
            a[0]=Qh2[r0+g  ][ks*8+t];   a[1]=Qh2[r0+g+8][ks*8+t];
            a[2]=Qh2[r0+g  ][ks*8+t+4]; a[3]=Qh2[r0+g+8][ks*8+t+4];
#pragma unroll
            for (int ni=0;ni<8;ni++){
                uint32_t b[2];
                b[0]=Kh2[h*64+ni*8+g][ks*8+t];
                b[1]=Kh2[h*64+ni*8+g][ks*8+t+4];
                mma16(c[ni], a, b);
            }
        }
        // scale + adj
#pragma unroll
        for (int ni=0;ni<8;ni++){
            int kk = kb + h*64 + ni*8 + 2*t;
            c[ni][0] = fmaf(c[ni][0], scale, adj_s[abs(qlo   - kk    )]);
            c[ni][1] = fmaf(c[ni][1], scale, adj_s[abs(qlo   - kk - 1)]);
            c[ni][2] = fmaf(c[ni][2], scale, adj_s[abs(qlo+8 - kk    )]);
            c[ni][3] = fmaf(c[ni][3], scale, adj_s[abs(qlo+8 - kk - 1)]);
        }
        // intra-quad row max
        float rmx_lo=-1e30f, rmx_hi=-1e30f;
#pragma unroll
        for (int ni=0;ni<8;ni++){
            rmx_lo = fmaxf(rmx_lo, fmaxf(c[ni][0], c[ni][1]));
            rmx_hi = fmaxf(rmx_hi, fmaxf(c[ni][2], c[ni][3]));
        }
        rmx_lo = fmaxf(rmx_lo, __shfl_xor_sync(0xffffffffu, rmx_lo, 1));
        rmx_lo = fmaxf(rmx_lo, __shfl_xor_sync(0xffffffffu, rmx_lo, 2));
        rmx_hi = fmaxf(rmx_hi, __shfl_xor_sync(0xffffffffu, rmx_hi, 1));
        rmx_hi = fmaxf(rmx_hi, __shfl_xor_sync(0xffffffffu, rmx_hi, 2));
        // exchange max with partner warp
        if ((lane&3)==0){ sb[sidx]=rmx_lo; sb[sidx+1]=rmx_hi; }
        asm volatile("bar.sync %0, 64;" :: "r"(rg+1) : "memory");
        float mn_lo = fmaxf(fmaxf(m_lo, rmx_lo), sb[pidx]);
        float mn_hi = fmaxf(fmaxf(m_hi, rmx_hi), sb[pidx+1]);
        float f_lo = __expf(m_lo - mn_lo),  f_hi = __expf(m_hi - mn_hi);
        m_lo = mn_lo; m_hi = mn_hi;
        // exp + partial rowsum
        float rs_lo=0.f, rs_hi=0.f;
#pragma unroll
        for (int ni=0;ni<8;ni++){
            c[ni][0]=__expf(c[ni][0]-mn_lo); c[ni][1]=__expf(c[ni][1]-mn_lo);
            c[ni][2]=__expf(c[ni][2]-mn_hi); c[ni][3]=__expf(c[ni][3]-mn_hi);
            rs_lo += c[ni][0]+c[ni][1];
            rs_hi += c[ni][2]+c[ni][3];
        }
        rs_lo += __shfl_xor_sync(0xffffffffu, rs_lo, 1);
        rs_lo += __shfl_xor_sync(0xffffffffu, rs_lo, 2);
        rs_hi += __shfl_xor_sync(0xffffffffu, rs_hi, 1);
        rs_hi += __shfl_xor_sync(0xffffffffu, rs_hi, 2);
        if ((lane&3)==0){ sb[128+sidx]=rs_lo; sb[128+sidx+1]=rs_hi; }
        asm volatile("bar.sync %0, 64;" :: "r"(rg+1) : "memory");
        l_lo = l_lo*f_lo + rs_lo + sb[128+pidx];
        l_hi = l_hi*f_hi + rs_hi + sb[128+pidx+1];
#pragma unroll
        for (int ni=0;ni<8;ni++){
            o[ni][0]*=f_lo; o[ni][1]*=f_lo; o[ni][2]*=f_hi; o[ni][3]*=f_hi;
        }
        // P @ V over this warp's 64 keys (4 k16 steps); C regs pack directly to A-frags
#pragma unroll
        for (int j=0; j<4; j++){
            uint32_t a[4];
            a[0] = packh2(c[2*j  ][0], c[2*j  ][1]);
            a[1] = packh2(c[2*j  ][2], c[2*j  ][3]);
            a[2] = packh2(c[2*j+1][0], c[2*j+1][1]);
            a[3] = packh2(c[2*j+1][2], c[2*j+1][3]);
#pragma unroll
            for (int ni=0;ni<8;ni++){
                uint32_t b[2];
                b[0]=Vh2[h*32+j*8+t  ][ni*8+g];
                b[1]=Vh2[h*32+j*8+t+4][ni*8+g];
                mma16(o[ni], a, b);
            }
        }
        __syncthreads();
    }

    // merge partner halves: h==0 writes normalized, h==1 adds
    float rcp_lo = 1.f/l_lo, rcp_hi = 1.f/l_hi;
    if (h==0){
#pragma unroll
        for (int ni=0;ni<8;ni++){
            Og[r0+g  ][ni*8+2*t  ] = o[ni][0]*rcp_lo;
            Og[r0+g  ][ni*8+2*t+1] = o[ni][1]*rcp_lo;
            Og[r0+g+8][ni*8+2*t  ] = o[ni][2]*rcp_hi;
            Og[r0+g+8][ni*8+2*t+1] = o[ni][3]*rcp_hi;
        }
    }
    __syncthreads();
    if (h==1){
#pragma unroll
        for (int ni=0;ni<8;ni++){
            Og[r0+g  ][ni*8+2*t  ] += o[ni][0]*rcp_lo;
            Og[r0+g  ][ni*8+2*t+1] += o[ni][1]*rcp_lo;
            Og[r0+g+8][ni*8+2*t  ] += o[ni][2]*rcp_hi;
            Og[r0+g+8][ni*8+2*t+1] += o[ni][3]*rcp_hi;
        }
    }
    __syncthreads();

    // ---- local-window epilogue: 4 lanes per row, 16 dims each ----
    const float aa = 1.f/(1.f+__expf(-alpha[layer]));
    const int rowl = wid*8 + (lane>>2);
    const int q = q0 + rowl;
    const int d0 = (lane&3)*16;
    const int lo = (q-4>0)? q-4 : 0;
    const int hi = (q+4<Tn-1)? q+4 : Tn-1;
    const int nw = hi-lo+1;

    float s[9];
    for (int j=0;j<nw;j++){
        float dot = 0.f;
#pragma unroll
        for (int i=0;i<8;i++){
            __half2 q2 = *(__half2*)&Qh2[rowl][(d0>>1)+i];
            __half2 k2 = *(__half2*)&Kpw[(size_t)(lo+j)*(DHn/2) + (d0>>1)+i];
            dot = fmaf(__half2float(q2.x), __half2float(k2.x), dot);
            dot = fmaf(__half2float(q2.y), __half2float(k2.y), dot);
        }
        dot += __shfl_xor_sync(0xffffffffu, dot, 1);
        dot += __shfl_xor_sync(0xffffffffu, dot, 2);
        s[j] = fmaf(dot, scale, adj_s[abs(q-(lo+j))]);
    }
    float lm = -1e30f;
    for (int j=0;j<nw;j++) lm = fmaxf(lm, s[j]);
    float ls = 0.f;
    for (int j=0;j<nw;j++){ s[j] = __expf(s[j]-lm); ls += s[j]; }
    float linv = (1.f-aa)/ls;

    float acc[16];
#pragma unroll
    for (int i=0;i<16;i++) acc[i] = aa*Og[rowl][d0+i];
    for (int j=0;j<nw;j++){
        float w = s[j]*linv;
#pragma unroll
        for (int i=0;i<8;i++){
            __half2 v2 = *(__half2*)&Vpw[(size_t)(lo+j)*(DHn/2) + (d0>>1)+i];
            acc[2*i  ] = fmaf(w, __half2float(v2.x), acc[2*i  ]);
            acc[2*i+1] = fmaf(w, __half2float(v2.y), acc[2*i+1]);
        }
    }
    float* outp = &g_tmp[(size_t)p*Tn*DHn + (size_t)q*DHn + d0];
#pragma unroll
    for (int i=0;i<16;i+=4){
        float4 v;
        v.x=powtf(acc[i]); v.y=powtf(acc[i+1]); v.z=powtf(acc[i+2]); v.w=powtf(acc[i+3]);
        *(float4*)&outp[i] = v;
    }
}

// ---------------- column L2 norms over seq axis (per b,d) ----------------
__global__ void k_colnorm(){
    int tid = threadIdx.x;
    int col = blockIdx.x*8 + (tid>>5);   // 0..4095
    int lane = tid&31;
    int b = col >> 9, d = col & (Dn-1);
    const float* base = g_tmp + (size_t)b*Tn*Dn + d;
    float sum = 0.f;
    for (int t=lane; t<Tn; t+=32){ float v = base[(size_t)t*Dn]; sum = fmaf(v,v,sum); }
#pragma unroll
    for (int o=16;o;o>>=1) sum += __shfl_xor_sync(0xffffffffu,sum,o);
    if (lane==0) g_invnorm[col] = 1.f/fmaxf(sqrtf(sum), 1e-12f);
}

// ---------------- LayerNorm over D, in place on g_xb ----------------
__global__ __launch_bounds__(128) void k_ln(
    const float* __restrict__ lng, const float* __restrict__ lnb, int layer)
{
    __shared__ float shm[10];
    int r = blockIdx.x;
    int tid = threadIdx.x, lane = tid&31, wid = tid>>5;
    float v[4];
    float sum=0.f, sq=0.f;
#pragma unroll
    for (int j=0;j<4;j++){
        v[j] = g_xb[(size_t)r*Dn + tid + j*128];
        sum += v[j]; sq = fmaf(v[j],v[j],sq);
    }
#pragma unroll
    for (int o=16;o;o>>=1){ sum += __shfl_xor_sync(0xffffffffu,sum,o); sq += __shfl_xor_sync(0xffffffffu,sq,o); }
    if (lane==0){ shm[wid]=sum; shm[4+wid]=sq; }
    __syncthreads();
    if (tid==0){ shm[8]=shm[0]+shm[1]+shm[2]+shm[3]; shm[9]=shm[4]+shm[5]+shm[6]+shm[7]; }
    __syncthreads();
    float mu  = shm[8]*(1.f/Dn);
    float var = shm[9]*(1.f/Dn) - mu*mu;
    float rstd = rsqrtf(fmaxf(var,0.f) + 1e-5f);
    const float* gg = lng + layer*Dn;
    const float* bb = lnb + layer*Dn;
#pragma unroll
    for (int j=0;j<4;j++){
        int d = tid + j*128;
        g_xb[(size_t)r*Dn + d] = (v[j]-mu)*rstd*gg[d] + bb[d];
    }
}

// ---------------- launch ----------------
extern "C" void kernel_launch(void* const* d_in, const int* in_sizes, int n_in,
                              void* d_out, int out_size)
{
    const float* x     = (const float*)d_in[0];
    const float* Wq    = (const float*)d_in[1];
    const float* bq    = (const float*)d_in[2];
    const float* Wk    = (const float*)d_in[3];
    const float* bk    = (const float*)d_in[4];
    const float* Wv    = (const float*)d_in[5];
    const float* bv    = (const float*)d_in[6];
    const float* Wo    = (const float*)d_in[7];
    const float* bo    = (const float*)d_in[8];
    const float* alpha = (const float*)d_in[9];
    const float* ln_g  = (const float*)d_in[10];
    const float* ln_b  = (const float*)d_in[11];
    const float* adj_w = (const float*)d_in[12];
    const float* adj_b = (const float*)d_in[13];
    float* out = (float*)d_out;

    cudaFuncSetAttribute(k_flash, cudaFuncAttributeMaxDynamicSharedMemorySize, FLASH_SMEM);

    k_transpose_in<<<(ROWS*Dn)/256, 256>>>(x);
    k_adj<<<1, Tn>>>(adj_w, adj_b);
    for (int l=0; l<2; l++){
        k_proj_qkv<<<dim3(8,64,3), 256>>>(Wq,Wk,Wv,bq,bk,bv,l);
        k_flash<<<dim3(16,64), 256, FLASH_SMEM>>>(alpha, l);
        k_colnorm<<<512, 256>>>();
        k_proj_out<<<dim3(8,64), 256>>>(Wo, bo, l);
        k_ln<<<ROWS, 128>>>(ln_g, ln_b, l);
    }
    k_transpose_out<<<(ROWS*Dn)/256, 256>>>(out);
}

// round 8
// speedup vs baseline: 2.4205x; 1.1045x over previous
#include <cuda_runtime.h>
#include <cuda_fp16.h>
#include <math.h>
#include <stdint.h>

#define Tn 1024
#define Bn 8
#define Dn 512
#define Hn 8
#define DHn 64
#define NPAIR 64           // Hn*Bn
#define ROWS (Bn*Tn)       // 8192

// ---------------- scratch (device globals: allocation-free) ----------------
__device__ float    g_xb [Bn*Tn*Dn];
__device__ uint32_t g_xbh[Bn*Tn*Dn/2];   // xb fp16 shadow, half2 pairs over d
__device__ uint32_t g_Qh [Bn*Tn*Dn/2];
__device__ uint32_t g_Kh [Bn*Tn*Dn/2];
__device__ uint32_t g_Vh [Bn*Tn*Dn/2];
__device__ float    g_tmp[Bn*Tn*Dn];
__device__ uint32_t g_tmph[Bn*Tn*Dn/2];  // (tmp*invnorm) fp16, pairs over d
__device__ uint32_t g_Wh [8*256*512];    // [layer*4+z][k/2][n] half2 pairs over k
__device__ float    g_invnorm[Bn*Dn];
__device__ float    g_adj[Tn];

__device__ __forceinline__ float powtf(float v){
    return sqrtf(fmaxf(v,0.f)) - sqrtf(fmaxf(-v,0.f));
}

__device__ __forceinline__ uint32_t packh2(float a, float b){
    __half2 h = __floats2half2_rn(a, b);   // .x (low) = a
    return *(uint32_t*)&h;
}

// mma.sync m16n8k16 fp16 in, fp32 accum, row.col
__device__ __forceinline__ void mma16(float* c, const uint32_t* a, const uint32_t* b){
    asm volatile(
        "mma.sync.aligned.m16n8k16.row.col.f32.f16.f16.f32 "
        "{%0,%1,%2,%3},{%4,%5,%6,%7},{%8,%9},{%0,%1,%2,%3};"
        : "+f"(c[0]),"+f"(c[1]),"+f"(c[2]),"+f"(c[3])
        : "r"(a[0]),"r"(a[1]),"r"(a[2]),"r"(a[3]),"r"(b[0]),"r"(b[1]));
}

__device__ __forceinline__ void cpa16(uint32_t dst, const void* src){
    asm volatile("cp.async.cg.shared.global [%0], [%1], 16;" :: "r"(dst), "l"(src));
}

// ---------------- weight prep: fp32 -> fp16 k-paired, once ----------------
__global__ void k_prep_w(const float* __restrict__ Wq, const float* __restrict__ Wk,
                         const float* __restrict__ Wv, const float* __restrict__ Wo){
    int idx = blockIdx.x*256 + threadIdx.x;       // < 8*131072
    int m8  = idx >> 17;
    int rem = idx & 131071;
    int kp  = rem >> 9;
    int n   = rem & 511;
    int l = m8 >> 2, z = m8 & 3;
    const float* W = (z==0?Wq:(z==1?Wk:(z==2?Wv:Wo))) + (size_t)l*Dn*Dn;
    g_Wh[idx] = packh2(W[(size_t)(2*kp)*Dn + n], W[(size_t)(2*kp+1)*Dn + n]);
}

// ---------------- transpose in: x[T,B,D] -> g_xb[B,T,D] + fp16 shadow ----------------
__global__ void k_transpose_in(const float* __restrict__ x){
    int i = blockIdx.x*256 + threadIdx.x;         // word idx < ROWS*256
    int d0 = (i & 255)*2;
    int row = i >> 8;
    int b = row >> 10, t = row & 1023;
    const float* src = &x[(size_t)(t*Bn + b)*Dn + d0];
    float v0 = src[0], v1 = src[1];
    float2* dst = (float2*)&g_xb[(size_t)row*Dn + d0];
    *dst = make_float2(v0, v1);
    g_xbh[i] = packh2(v0, v1);
}

__global__ void k_transpose_out(float* __restrict__ out){
    int idx = blockIdx.x*256 + threadIdx.x;          // [T,B,D] linear
    int d = idx & (Dn-1);
    int b = (idx >> 9) & (Bn-1);
    int t = idx >> 12;
    out[idx] = g_xb[((b<<10) + t)*Dn + d];
}

// ---------------- adj table ----------------
__global__ void k_adj(const float* __restrict__ aw, const float* __restrict__ ab){
    int i = threadIdx.x;
    float dist = (float)i;
    g_adj[i] = expf(-fabsf(aw[0]*dist*dist - ab[0]));
}

// ================= unified cp.async double-buffered fp16 GEMM =================
// mode 0: C = xbh @ W[z] + b[z] -> g_{Q,K,V}h (fp16), grid z = 3
// mode 1: g_xb += tmph @ Wo + bo (fp32 residual), grid z = 1
// M=8192, N=512, K=512; block 128x64, BK=64, 2-stage cp.async pipeline.
#define PA_ST 4608                 // words per A stage: 128*36
#define PB_ST 2304                 // words per B stage: 32*72
#define PROJ_SMEM ((2*PA_ST + 2*PB_ST)*4)   // 55296 B

__global__ __launch_bounds__(256,2) void k_proj(
    const float* __restrict__ bq, const float* __restrict__ bk,
    const float* __restrict__ bv, const float* __restrict__ bo,
    int mode, int layer)
{
    extern __shared__ uint32_t shp[];
    const int tid = threadIdx.x;
    const int z   = (mode==0) ? blockIdx.z : 3;
    const uint32_t* Bsrc = g_Wh + (size_t)(layer*4 + z)*131072;
    const uint32_t* Asrc = (mode==0) ? g_xbh : g_tmph;
    const float* bias = ((mode==0) ? (z==0?bq:(z==1?bk:bv)) : bo) + layer*Dn;
    uint32_t* Ch = (z==0? g_Qh : (z==1? g_Kh : g_Vh));

    const int m0 = blockIdx.y*128, n0 = blockIdx.x*64;
    const int wid = tid>>5, lane = tid&31, g = lane>>2, t = lane&3;
    const int m_off = (wid>>1)*32, n_off = (wid&1)*32;
    const uint32_t sbase = (uint32_t)__cvta_generic_to_shared(shp);

    float c[2][4][4] = {};

    // cp.async issue for k-tile kt into buffer buf
    auto issue = [&](int kt, int buf){
        const uint32_t* Ag = Asrc + (size_t)m0*256 + kt*32;
#pragma unroll
        for (int i2=0;i2<4;i2++){
            int cc = tid + i2*256;
            int r = cc>>3, ch = cc&7;
            cpa16(sbase + (buf*PA_ST + r*36 + ch*4)*4, Ag + (size_t)r*256 + ch*4);
        }
        const uint32_t* Bg = Bsrc + (size_t)(kt*32)*512 + n0;
#pragma unroll
        for (int i2=0;i2<2;i2++){
            int cc = tid + i2*256;
            int kr = cc>>4, ch = cc&15;
            cpa16(sbase + (2*PA_ST + buf*PB_ST + kr*72 + ch*4)*4, Bg + (size_t)kr*512 + ch*4);
        }
        asm volatile("cp.async.commit_group;");
    };

    issue(0, 0);
    for (int kt=0; kt<8; kt++){
        if (kt < 7) issue(kt+1, (kt+1)&1);
        if (kt < 7) asm volatile("cp.async.wait_group 1;");
        else        asm volatile("cp.async.wait_group 0;");
        __syncthreads();
        uint32_t (*Ah2)[36] = (uint32_t(*)[36])(shp + (kt&1)*PA_ST);
        uint32_t (*Bh2)[72] = (uint32_t(*)[72])(shp + 2*PA_ST + (kt&1)*PB_ST);
#pragma unroll
        for (int j=0; j<4; j++){
            uint32_t a[2][4], b[4][2];
#pragma unroll
            for (int mi=0;mi<2;mi++){
                int r = m_off+mi*16;
                a[mi][0]=Ah2[r+g  ][j*8+t];   a[mi][1]=Ah2[r+g+8][j*8+t];
                a[mi][2]=Ah2[r+g  ][j*8+t+4]; a[mi][3]=Ah2[r+g+8][j*8+t+4];
            }
#pragma unroll
            for (int ni=0;ni<4;ni++){
                b[ni][0]=Bh2[j*8+t  ][n_off+ni*8+g];
                b[ni][1]=Bh2[j*8+t+4][n_off+ni*8+g];
            }
#pragma unroll
            for (int mi=0;mi<2;mi++)
#pragma unroll
                for (int ni=0;ni<4;ni++) mma16(c[mi][ni], a[mi], b[ni]);
        }
        __syncthreads();
    }

#pragma unroll
    for (int mi=0;mi<2;mi++){
#pragma unroll
        for (int ni=0;ni<4;ni++){
            int row = m0 + m_off + mi*16 + g;
            int col = n0 + n_off + ni*8 + 2*t;
            float b0 = bias[col], b1 = bias[col+1];
            if (mode==0){
                int w = col>>1;
                Ch[(size_t)row*256 + w]     = packh2(c[mi][ni][0]+b0, c[mi][ni][1]+b1);
                Ch[(size_t)(row+8)*256 + w] = packh2(c[mi][ni][2]+b0, c[mi][ni][3]+b1);
            } else {
                float2 r0 = *(float2*)&g_xb[(size_t)row*Dn + col];
                float2 r1 = *(float2*)&g_xb[(size_t)(row+8)*Dn + col];
                float2 v0 = {c[mi][ni][0]+b0+r0.x, c[mi][ni][1]+b1+r0.y};
                float2 v1 = {c[mi][ni][2]+b0+r1.x, c[mi][ni][3]+b1+r1.y};
                *(float2*)&g_xb[(size_t)row*Dn + col]     = v0;
                *(float2*)&g_xb[(size_t)(row+8)*Dn + col] = v1;
            }
        }
    }
}

// ================= fused flash attention: warp-pair key-split (round-7, unchanged) =================
#define QK_STRIDE 36
#define V_STRIDE2 72
#define SH_Q   0
#define SH_K   (64*QK_STRIDE)
#define SH_V   (SH_K + 128*QK_STRIDE)
#define SH_ADJ (SH_V + 64*V_STRIDE2)
#define SH_SB  (SH_ADJ + Tn)
#define FLASH_SMEM ((SH_SB + 256)*4)
#define OG_STRIDE 68

__global__ __launch_bounds__(256,2) void k_flash(const float* __restrict__ alpha, int layer){
    extern __shared__ uint32_t sh[];
    uint32_t (*Qh2)[QK_STRIDE] = (uint32_t(*)[QK_STRIDE])(sh + SH_Q);
    uint32_t (*Kh2)[QK_STRIDE] = (uint32_t(*)[QK_STRIDE])(sh + SH_K);
    uint32_t (*Vh2)[V_STRIDE2] = (uint32_t(*)[V_STRIDE2])(sh + SH_V);
    float* adj_s = (float*)(sh + SH_ADJ);
    float* sb    = (float*)(sh + SH_SB);
    float (*Og)[OG_STRIDE] = (float(*)[OG_STRIDE])(sh + SH_K);

    const int tid = threadIdx.x;
    const int p  = blockIdx.y;
    const int q0 = blockIdx.x*64;
    const uint4* Qp4 = (const uint4*)(g_Qh + (size_t)p*Tn*(DHn/2));
    const uint4* Kp4 = (const uint4*)(g_Kh + (size_t)p*Tn*(DHn/2));
    const uint4* Vp4 = (const uint4*)(g_Vh + (size_t)p*Tn*(DHn/2));
    const uint32_t* Kpw = g_Kh + (size_t)p*Tn*(DHn/2);
    const uint32_t* Vpw = g_Vh + (size_t)p*Tn*(DHn/2);

    for (int i=tid;i<Tn;i+=256) adj_s[i] = g_adj[i];
#pragma unroll
    for (int i=0;i<2;i++){
        int c = tid + i*256;
        *(uint4*)&Qh2[c>>3][(c&7)<<2] = Qp4[(size_t)(q0 + (c>>3))*8 + (c&7)];
    }
    __syncthreads();

    const int wid = tid>>5, lane = tid&31, g = lane>>2, t = lane&3;
    const int rg = wid>>1, h = wid&1;
    const int r0 = rg*16;
    const int qlo = q0 + r0 + g;
    const int sidx = ((rg*2+h)*8 + g)*2;
    const int pidx = ((rg*2+(h^1))*8 + g)*2;
    const float scale = 0.04419417382415922f;

    float m_lo=-1e30f, m_hi=-1e30f, l_lo=0.f, l_hi=0.f;
    float o[8][4] = {};

    const int vpr = tid>>2, vs2 = (tid&3)*2;

    for (int kb=0; kb<Tn; kb+=128){
#pragma unroll
        for (int i=0;i<4;i++){
            int c = tid + i*256;
            *(uint4*)&Kh2[c>>3][(c&7)<<2] = Kp4[(size_t)(kb + (c>>3))*8 + (c&7)];
        }
#pragma unroll
        for (int ss=0; ss<2; ss++){
            int seg = vs2+ss;
            uint4 va = Vp4[(size_t)(kb+2*vpr  )*8 + seg];
            uint4 vb = Vp4[(size_t)(kb+2*vpr+1)*8 + seg];
            uint32_t* dst = &Vh2[vpr][seg*8];
            dst[0]=__byte_perm(va.x,vb.x,0x5410); dst[1]=__byte_perm(va.x,vb.x,0x7632);
            dst[2]=__byte_perm(va.y,vb.y,0x5410); dst[3]=__byte_perm(va.y,vb.y,0x7632);
            dst[4]=__byte_perm(va.z,vb.z,0x5410); dst[5]=__byte_perm(va.z,vb.z,0x7632);
            dst[6]=__byte_perm(va.w,vb.w,0x5410); dst[7]=__byte_perm(va.w,vb.w,0x7632);
        }
        __syncthreads();

        float c[8][4] = {};
#pragma unroll
        for (int ks=0; ks<4; ks++){
            uint32_t a[4];
            a[0]=Qh2[r0+g  ][ks*8+t];   a[1]=Qh2[r0+g+8][ks*8+t];
            a[2]=Qh2[r0+g  ][ks*8+t+4]; a[3]=Qh2[r0+g+8][ks*8+t+4];
#pragma unroll
            for (int ni=0;ni<8;ni++){
                uint32_t b[2];
                b[0]=Kh2[h*64+ni*8+g][ks*8+t];
                b[1]=Kh2[h*64+ni*8+g][ks*8+t+4];
                mma16(c[ni], a, b);
            }
        }
#pragma unroll
        for (int ni=0;ni<8;ni++){
            int kk = kb + h*64 + ni*8 + 2*t;
            c[ni][0] = fmaf(c[ni][0], scale, adj_s[abs(qlo   - kk    )]);
            c[ni][1] = fmaf(c[ni][1], scale, adj_s[abs(qlo   - kk - 1)]);
            c[ni][2] = fmaf(c[ni][2], scale, adj_s[abs(qlo+8 - kk    )]);
            c[ni][3] = fmaf(c[ni][3], scale, adj_s[abs(qlo+8 - kk - 1)]);
        }
        float rmx_lo=-1e30f, rmx_hi=-1e30f;
#pragma unroll
        for (int ni=0;ni<8;ni++){
            rmx_lo = fmaxf(rmx_lo, fmaxf(c[ni][0], c[ni][1]));
            rmx_hi = fmaxf(rmx_hi, fmaxf(c[ni][2], c[ni][3]));
        }
        rmx_lo = fmaxf(rmx_lo, __shfl_xor_sync(0xffffffffu, rmx_lo, 1));
        rmx_lo = fmaxf(rmx_lo, __shfl_xor_sync(0xffffffffu, rmx_lo, 2));
        rmx_hi = fmaxf(rmx_hi, __shfl_xor_sync(0xffffffffu, rmx_hi, 1));
        rmx_hi = fmaxf(rmx_hi, __shfl_xor_sync(0xffffffffu, rmx_hi, 2));
        if ((lane&3)==0){ sb[sidx]=rmx_lo; sb[sidx+1]=rmx_hi; }
        asm volatile("bar.sync %0, 64;" :: "r"(rg+1) : "memory");
        float mn_lo = fmaxf(fmaxf(m_lo, rmx_lo), sb[pidx]);
        float mn_hi = fmaxf(fmaxf(m_hi, rmx_hi), sb[pidx+1]);
        float f_lo = __expf(m_lo - mn_lo),  f_hi = __expf(m_hi - mn_hi);
        m_lo = mn_lo; m_hi = mn_hi;
        float rs_lo=0.f, rs_hi=0.f;
#pragma unroll
        for (int ni=0;ni<8;ni++){
            c[ni][0]=__expf(c[ni][0]-mn_lo); c[ni][1]=__expf(c[ni][1]-mn_lo);
            c[ni][2]=__expf(c[ni][2]-mn_hi); c[ni][3]=__expf(c[ni][3]-mn_hi);
            rs_lo += c[ni][0]+c[ni][1];
            rs_hi += c[ni][2]+c[ni][3];
        }
        rs_lo += __shfl_xor_sync(0xffffffffu, rs_lo, 1);
        rs_lo += __shfl_xor_sync(0xffffffffu, rs_lo, 2);
        rs_hi += __shfl_xor_sync(0xffffffffu, rs_hi, 1);
        rs_hi += __shfl_xor_sync(0xffffffffu, rs_hi, 2);
        if ((lane&3)==0){ sb[128+sidx]=rs_lo; sb[128+sidx+1]=rs_hi; }
        asm volatile("bar.sync %0, 64;" :: "r"(rg+1) : "memory");
        l_lo = l_lo*f_lo + rs_lo + sb[128+pidx];
        l_hi = l_hi*f_hi + rs_hi + sb[128+pidx+1];
#pragma unroll
        for (int ni=0;ni<8;ni++){
            o[ni][0]*=f_lo; o[ni][1]*=f_lo; o[ni][2]*=f_hi; o[ni][3]*=f_hi;
        }
#pragma unroll
        for (int j=0; j<4; j++){
            uint32_t a[4];
            a[0] = packh2(c[2*j  ][0], c[2*j  ][1]);
            a[1] = packh2(c[2*j  ][2], c[2*j  ][3]);
            a[2] = packh2(c[2*j+1][0], c[2*j+1][1]);
            a[3] = packh2(c[2*j+1][2], c[2*j+1][3]);
#pragma unroll
            for (int ni=0;ni<8;ni++){
                uint32_t b[2];
                b[0]=Vh2[h*32+j*8+t  ][ni*8+g];
                b[1]=Vh2[h*32+j*8+t+4][ni*8+g];
                mma16(o[ni], a, b);
            }
        }
        __syncthreads();
    }

    float rcp_lo = 1.f/l_lo, rcp_hi = 1.f/l_hi;
    if (h==0){
#pragma unroll
        for (int ni=0;ni<8;ni++){
            Og[r0+g  ][ni*8+2*t  ] = o[ni][0]*rcp_lo;
            Og[r0+g  ][ni*8+2*t+1] = o[ni][1]*rcp_lo;
            Og[r0+g+8][ni*8+2*t  ] = o[ni][2]*rcp_hi;
            Og[r0+g+8][ni*8+2*t+1] = o[ni][3]*rcp_hi;
        }
    }
    __syncthreads();
    if (h==1){
#pragma unroll
        for (int ni=0;ni<8;ni++){
            Og[r0+g  ][ni*8+2*t  ] += o[ni][0]*rcp_lo;
            Og[r0+g  ][ni*8+2*t+1] += o[ni][1]*rcp_lo;
            Og[r0+g+8][ni*8+2*t  ] += o[ni][2]*rcp_hi;
            Og[r0+g+8][ni*8+2*t+1] += o[ni][3]*rcp_hi;
        }
    }
    __syncthreads();

    const float aa = 1.f/(1.f+__expf(-alpha[layer]));
    const int rowl = wid*8 + (lane>>2);
    const int q = q0 + rowl;
    const int d0 = (lane&3)*16;
    const int lo = (q-4>0)? q-4 : 0;
    const int hi = (q+4<Tn-1)? q+4 : Tn-1;
    const int nw = hi-lo+1;

    float s[9];
    for (int j=0;j<nw;j++){
        float dot = 0.f;
#pragma unroll
        for (int i=0;i<8;i++){
            __half2 q2 = *(__half2*)&Qh2[rowl][(d0>>1)+i];
            __half2 k2 = *(__half2*)&Kpw[(size_t)(lo+j)*(DHn/2) + (d0>>1)+i];
            dot = fmaf(__half2float(q2.x), __half2float(k2.x), dot);
            dot = fmaf(__half2float(q2.y), __half2float(k2.y), dot);
        }
        dot += __shfl_xor_sync(0xffffffffu, dot, 1);
        dot += __shfl_xor_sync(0xffffffffu, dot, 2);
        s[j] = fmaf(dot, scale, adj_s[abs(q-(lo+j))]);
    }
    float lm = -1e30f;
    for (int j=0;j<nw;j++) lm = fmaxf(lm, s[j]);
    float ls = 0.f;
    for (int j=0;j<nw;j++){ s[j] = __expf(s[j]-lm); ls += s[j]; }
    float linv = (1.f-aa)/ls;

    float acc[16];
#pragma unroll
    for (int i=0;i<16;i++) acc[i] = aa*Og[rowl][d0+i];
    for (int j=0;j<nw;j++){
        float w = s[j]*linv;
#pragma unroll
        for (int i=0;i<8;i++){
            __half2 v2 = *(__half2*)&Vpw[(size_t)(lo+j)*(DHn/2) + (d0>>1)+i];
            acc[2*i  ] = fmaf(w, __half2float(v2.x), acc[2*i  ]);
            acc[2*i+1] = fmaf(w, __half2float(v2.y), acc[2*i+1]);
        }
    }
    float* outp = &g_tmp[(size_t)p*Tn*DHn + (size_t)q*DHn + d0];
#pragma unroll
    for (int i=0;i<16;i+=4){
        float4 v;
        v.x=powtf(acc[i]); v.y=powtf(acc[i+1]); v.z=powtf(acc[i+2]); v.w=powtf(acc[i+3]);
        *(float4*)&outp[i] = v;
    }
}

// ---------------- column L2 norms over seq axis (per b,d) ----------------
__global__ void k_colnorm(){
    int tid = threadIdx.x;
    int col = blockIdx.x*8 + (tid>>5);   // 0..4095
    int lane = tid&31;
    int b = col >> 9, d = col & (Dn-1);
    const float* base = g_tmp + (size_t)b*Tn*Dn + d;
    float sum = 0.f;
    for (int t=lane; t<Tn; t+=32){ float v = base[(size_t)t*Dn]; sum = fmaf(v,v,sum); }
#pragma unroll
    for (int o=16;o;o>>=1) sum += __shfl_xor_sync(0xffffffffu,sum,o);
    if (lane==0) g_invnorm[col] = 1.f/fmaxf(sqrtf(sum), 1e-12f);
}

// ---------------- scale tmp by invnorm -> fp16 ----------------
__global__ void k_scale_tmp(){
    int i = blockIdx.x*256 + threadIdx.x;   // word idx < ROWS*256
    int d0 = (i & 255)*2;
    int row = i >> 8;
    float2 v = *(float2*)&g_tmp[(size_t)row*Dn + d0];
    const float* inv = &g_invnorm[(row>>10)*Dn + d0];
    g_tmph[i] = packh2(v.x*inv[0], v.y*inv[1]);
}

// ---------------- LayerNorm over D, writes fp32 + fp16 shadow ----------------
__global__ __launch_bounds__(128) void k_ln(
    const float* __restrict__ lng, const float* __restrict__ lnb, int layer)
{
    __shared__ float shm[10];
    int r = blockIdx.x;
    int tid = threadIdx.x, lane = tid&31, wid = tid>>5;
    int d0 = tid*4;
    float4 v = *(const float4*)&g_xb[(size_t)r*Dn + d0];
    float sum = v.x+v.y+v.z+v.w;
    float sq  = v.x*v.x+v.y*v.y+v.z*v.z+v.w*v.w;
#pragma unroll
    for (int o=16;o;o>>=1){ sum += __shfl_xor_sync(0xffffffffu,sum,o); sq += __shfl_xor_sync(0xffffffffu,sq,o); }
    if (lane==0){ shm[wid]=sum; shm[4+wid]=sq; }
    __syncthreads();
    if (tid==0){ shm[8]=shm[0]+shm[1]+shm[2]+shm[3]; shm[9]=shm[4]+shm[5]+shm[6]+shm[7]; }
    __syncthreads();
    float mu  = shm[8]*(1.f/Dn);
    float var = shm[9]*(1.f/Dn) - mu*mu;
    float rstd = rsqrtf(fmaxf(var,0.f) + 1e-5f);
    float4 gg = *(const float4*)&lng[layer*Dn + d0];
    float4 bb = *(const float4*)&lnb[layer*Dn + d0];
    float y0 = (v.x-mu)*rstd*gg.x + bb.x;
    float y1 = (v.y-mu)*rstd*gg.y + bb.y;
    float y2 = (v.z-mu)*rstd*gg.z + bb.z;
    float y3 = (v.w-mu)*rstd*gg.w + bb.w;
    *(float4*)&g_xb[(size_t)r*Dn + d0] = make_float4(y0,y1,y2,y3);
    g_xbh[(size_t)r*256 + tid*2    ] = packh2(y0,y1);
    g_xbh[(size_t)r*256 + tid*2 + 1] = packh2(y2,y3);
}

// ---------------- launch ----------------
extern "C" void kernel_launch(void* const* d_in, const int* in_sizes, int n_in,
                              void* d_out, int out_size)
{
    const float* x     = (const float*)d_in[0];
    const float* Wq    = (const float*)d_in[1];
    const float* bq    = (const float*)d_in[2];
    const float* Wk    = (const float*)d_in[3];
    const float* bk    = (const float*)d_in[4];
    const float* Wv    = (const float*)d_in[5];
    const float* bv    = (const float*)d_in[6];
    const float* Wo    = (const float*)d_in[7];
    const float* bo    = (const float*)d_in[8];
    const float* alpha = (const float*)d_in[9];
    const float* ln_g  = (const float*)d_in[10];
    const float* ln_b  = (const float*)d_in[11];
    const float* adj_w = (const float*)d_in[12];
    const float* adj_b = (const float*)d_in[13];
    float* out = (float*)d_out;

    cudaFuncSetAttribute(k_flash, cudaFuncAttributeMaxDynamicSharedMemorySize, FLASH_SMEM);
    cudaFuncSetAttribute(k_proj,  cudaFuncAttributeMaxDynamicSharedMemorySize, PROJ_SMEM);

    k_prep_w<<<4096, 256>>>(Wq, Wk, Wv, Wo);
    k_transpose_in<<<ROWS, 256>>>(x);
    k_adj<<<1, Tn>>>(adj_w, adj_b);
    for (int l=0; l<2; l++){
        k_proj<<<dim3(8,64,3), 256, PROJ_SMEM>>>(bq,bk,bv,bo, 0, l);
        k_flash<<<dim3(16,64), 256, FLASH_SMEM>>>(alpha, l);
        k_colnorm<<<512, 256>>>();
        k_scale_tmp<<<ROWS, 256>>>();
        k_proj<<<dim3(8,64,1), 256, PROJ_SMEM>>>(bq,bk,bv,bo, 1, l);
        k_ln<<<ROWS, 128>>>(ln_g, ln_b, l);
    }
    k_transpose_out<<<(ROWS*Dn)/256, 256>>>(out);
}

// round 9
// speedup vs baseline: 2.4685x; 1.0198x over previous
#include <cuda_runtime.h>
#include <cuda_fp16.h>
#include <math.h>
#include <stdint.h>

#define Tn 1024
#define Bn 8
#define Dn 512
#define Hn 8
#define DHn 64
#define NPAIR 64           // Hn*Bn
#define ROWS (Bn*Tn)       // 8192

// ---------------- scratch (device globals: allocation-free) ----------------
__device__ float    g_xb [Bn*Tn*Dn];
__device__ uint32_t g_xbh[Bn*Tn*Dn/2];   // xb fp16 shadow, half2 pairs over d
__device__ uint32_t g_Qh [Bn*Tn*Dn/2];
__device__ uint32_t g_Kh [Bn*Tn*Dn/2];
__device__ uint32_t g_Vh [Bn*Tn*Dn/2];
__device__ uint32_t g_Vi [Bn*Tn*Dn/2];   // V interleaved: [p][kp][n], word=(V[2kp,n],V[2kp+1,n])
__device__ float    g_tmp[Bn*Tn*Dn];
__device__ uint32_t g_tmph[Bn*Tn*Dn/2];  // (tmp*invnorm) fp16, pairs over d
__device__ uint32_t g_Wh [8*256*512];    // [layer*4+z][k/2][n] half2 pairs over k
__device__ float    g_invnorm[Bn*Dn];
__device__ float    g_adj[Tn];

__device__ __forceinline__ float powtf(float v){
    return sqrtf(fmaxf(v,0.f)) - sqrtf(fmaxf(-v,0.f));
}

__device__ __forceinline__ uint32_t packh2(float a, float b){
    __half2 h = __floats2half2_rn(a, b);   // .x (low) = a
    return *(uint32_t*)&h;
}

// mma.sync m16n8k16 fp16 in, fp32 accum, row.col
__device__ __forceinline__ void mma16(float* c, const uint32_t* a, const uint32_t* b){
    asm volatile(
        "mma.sync.aligned.m16n8k16.row.col.f32.f16.f16.f32 "
        "{%0,%1,%2,%3},{%4,%5,%6,%7},{%8,%9},{%0,%1,%2,%3};"
        : "+f"(c[0]),"+f"(c[1]),"+f"(c[2]),"+f"(c[3])
        : "r"(a[0]),"r"(a[1]),"r"(a[2]),"r"(a[3]),"r"(b[0]),"r"(b[1]));
}

__device__ __forceinline__ void cpa16(uint32_t dst, const void* src){
    asm volatile("cp.async.cg.shared.global [%0], [%1], 16;" :: "r"(dst), "l"(src));
}

// ---------------- weight prep: fp32 -> fp16 k-paired, once ----------------
__global__ void k_prep_w(const float* __restrict__ Wq, const float* __restrict__ Wk,
                         const float* __restrict__ Wv, const float* __restrict__ Wo){
    int idx = blockIdx.x*256 + threadIdx.x;       // < 8*131072
    int m8  = idx >> 17;
    int rem = idx & 131071;
    int kp  = rem >> 9;
    int n   = rem & 511;
    int l = m8 >> 2, z = m8 & 3;
    const float* W = (z==0?Wq:(z==1?Wk:(z==2?Wv:Wo))) + (size_t)l*Dn*Dn;
    g_Wh[idx] = packh2(W[(size_t)(2*kp)*Dn + n], W[(size_t)(2*kp+1)*Dn + n]);
}

// ---------------- V interleave: g_Vh -> g_Vi ----------------
__global__ void k_vint(){
    int i = blockIdx.x*256 + threadIdx.x;    // < NPAIR*512*32 = 1M; 2 words each
    int n2 = i & 31;
    int kp = (i >> 5) & 511;
    int p  = i >> 14;
    const uint32_t* src = g_Vh + ((size_t)p<<15) + kp*64;
    uint32_t w0 = src[n2], w1 = src[n2+32];
    uint32_t* dst = g_Vi + ((size_t)p<<15) + kp*64;
    dst[2*n2]   = __byte_perm(w0,w1,0x5410);
    dst[2*n2+1] = __byte_perm(w0,w1,0x7632);
}

// ---------------- transpose in: x[T,B,D] -> g_xb[B,T,D] + fp16 shadow ----------------
__global__ void k_transpose_in(const float* __restrict__ x){
    int i = blockIdx.x*256 + threadIdx.x;         // word idx < ROWS*256
    int d0 = (i & 255)*2;
    int row = i >> 8;
    int b = row >> 10, t = row & 1023;
    const float* src = &x[(size_t)(t*Bn + b)*Dn + d0];
    float v0 = src[0], v1 = src[1];
    float2* dst = (float2*)&g_xb[(size_t)row*Dn + d0];
    *dst = make_float2(v0, v1);
    g_xbh[i] = packh2(v0, v1);
}

__global__ void k_transpose_out(float* __restrict__ out){
    int idx = blockIdx.x*256 + threadIdx.x;          // [T,B,D] linear
    int d = idx & (Dn-1);
    int b = (idx >> 9) & (Bn-1);
    int t = idx >> 12;
    out[idx] = g_xb[((b<<10) + t)*Dn + d];
}

// ---------------- adj table ----------------
__global__ void k_adj(const float* __restrict__ aw, const float* __restrict__ ab){
    int i = threadIdx.x;
    float dist = (float)i;
    g_adj[i] = expf(-fabsf(aw[0]*dist*dist - ab[0]));
}

// ================= unified cp.async double-buffered fp16 GEMM (round-8, unchanged) =================
#define PA_ST 4608
#define PB_ST 2304
#define PROJ_SMEM ((2*PA_ST + 2*PB_ST)*4)

__global__ __launch_bounds__(256,2) void k_proj(
    const float* __restrict__ bq, const float* __restrict__ bk,
    const float* __restrict__ bv, const float* __restrict__ bo,
    int mode, int layer)
{
    extern __shared__ uint32_t shp[];
    const int tid = threadIdx.x;
    const int z   = (mode==0) ? blockIdx.z : 3;
    const uint32_t* Bsrc = g_Wh + (size_t)(layer*4 + z)*131072;
    const uint32_t* Asrc = (mode==0) ? g_xbh : g_tmph;
    const float* bias = ((mode==0) ? (z==0?bq:(z==1?bk:bv)) : bo) + layer*Dn;
    uint32_t* Ch = (z==0? g_Qh : (z==1? g_Kh : g_Vh));

    const int m0 = blockIdx.y*128, n0 = blockIdx.x*64;
    const int wid = tid>>5, lane = tid&31, g = lane>>2, t = lane&3;
    const int m_off = (wid>>1)*32, n_off = (wid&1)*32;
    const uint32_t sbase = (uint32_t)__cvta_generic_to_shared(shp);

    float c[2][4][4] = {};

    auto issue = [&](int kt, int buf){
        const uint32_t* Ag = Asrc + (size_t)m0*256 + kt*32;
#pragma unroll
        for (int i2=0;i2<4;i2++){
            int cc = tid + i2*256;
            int r = cc>>3, ch = cc&7;
            cpa16(sbase + (buf*PA_ST + r*36 + ch*4)*4, Ag + (size_t)r*256 + ch*4);
        }
        const uint32_t* Bg = Bsrc + (size_t)(kt*32)*512 + n0;
#pragma unroll
        for (int i2=0;i2<2;i2++){
            int cc = tid + i2*256;
            int kr = cc>>4, ch = cc&15;
            cpa16(sbase + (2*PA_ST + buf*PB_ST + kr*72 + ch*4)*4, Bg + (size_t)kr*512 + ch*4);
        }
        asm volatile("cp.async.commit_group;");
    };

    issue(0, 0);
    for (int kt=0; kt<8; kt++){
        if (kt < 7) issue(kt+1, (kt+1)&1);
        if (kt < 7) asm volatile("cp.async.wait_group 1;");
        else        asm volatile("cp.async.wait_group 0;");
        __syncthreads();
        uint32_t (*Ah2)[36] = (uint32_t(*)[36])(shp + (kt&1)*PA_ST);
        uint32_t (*Bh2)[72] = (uint32_t(*)[72])(shp + 2*PA_ST + (kt&1)*PB_ST);
#pragma unroll
        for (int j=0; j<4; j++){
            uint32_t a[2][4], b[4][2];
#pragma unroll
            for (int mi=0;mi<2;mi++){
                int r = m_off+mi*16;
                a[mi][0]=Ah2[r+g  ][j*8+t];   a[mi][1]=Ah2[r+g+8][j*8+t];
                a[mi][2]=Ah2[r+g  ][j*8+t+4]; a[mi][3]=Ah2[r+g+8][j*8+t+4];
            }
#pragma unroll
            for (int ni=0;ni<4;ni++){
                b[ni][0]=Bh2[j*8+t  ][n_off+ni*8+g];
                b[ni][1]=Bh2[j*8+t+4][n_off+ni*8+g];
            }
#pragma unroll
            for (int mi=0;mi<2;mi++)
#pragma unroll
                for (int ni=0;ni<4;ni++) mma16(c[mi][ni], a[mi], b[ni]);
        }
        __syncthreads();
    }

#pragma unroll
    for (int mi=0;mi<2;mi++){
#pragma unroll
        for (int ni=0;ni<4;ni++){
            int row = m0 + m_off + mi*16 + g;
            int col = n0 + n_off + ni*8 + 2*t;
            float b0 = bias[col], b1 = bias[col+1];
            if (mode==0){
                int w = col>>1;
                Ch[(size_t)row*256 + w]     = packh2(c[mi][ni][0]+b0, c[mi][ni][1]+b1);
                Ch[(size_t)(row+8)*256 + w] = packh2(c[mi][ni][2]+b0, c[mi][ni][3]+b1);
            } else {
                float2 r0 = *(float2*)&g_xb[(size_t)row*Dn + col];
                float2 r1 = *(float2*)&g_xb[(size_t)(row+8)*Dn + col];
                float2 v0 = {c[mi][ni][0]+b0+r0.x, c[mi][ni][1]+b1+r0.y};
                float2 v1 = {c[mi][ni][2]+b0+r1.x, c[mi][ni][3]+b1+r1.y};
                *(float2*)&g_xb[(size_t)row*Dn + col]     = v0;
                *(float2*)&g_xb[(size_t)(row+8)*Dn + col] = v1;
            }
        }
    }
}

// ================= flash attention: cp.async double-buffered K/V, hoisted Q frags =================
#define K_ST 4608                  // 128*36
#define V_ST 4608                  // 64*72
#define SH_Q   0                   // 64*36 = 2304
#define SH_K   2304
#define SH_V   (SH_K + 2*K_ST)     // 11520
#define SH_ADJ (SH_V + 2*V_ST)     // 20736
#define SH_SB  (SH_ADJ + Tn)       // 21760
#define FLASH_SMEM ((SH_SB + 256)*4)   // 88064 B
#define OG_STRIDE 68

__global__ __launch_bounds__(256,2) void k_flash(const float* __restrict__ alpha, int layer){
    extern __shared__ uint32_t sh[];
    uint32_t (*Qh2)[36] = (uint32_t(*)[36])(sh + SH_Q);
    float* adj_s = (float*)(sh + SH_ADJ);
    float* sb    = (float*)(sh + SH_SB);
    float (*Og)[OG_STRIDE] = (float(*)[OG_STRIDE])(sh + SH_K);  // overlay K stages post-mainloop

    const int tid = threadIdx.x;
    const int p  = blockIdx.y;
    const int q0 = blockIdx.x*64;
    const uint4* Qp4 = (const uint4*)(g_Qh + ((size_t)p<<15));
    const uint32_t* Kpw = g_Kh + ((size_t)p<<15);
    const uint32_t* Vint = g_Vi + ((size_t)p<<15);
    const uint32_t* Vpw = g_Vh + ((size_t)p<<15);
    const uint32_t sbase = (uint32_t)__cvta_generic_to_shared(sh);

    for (int i=tid;i<Tn;i+=256) adj_s[i] = g_adj[i];
#pragma unroll
    for (int i=0;i<2;i++){
        int c = tid + i*256;
        *(uint4*)&Qh2[c>>3][(c&7)<<2] = Qp4[(size_t)(q0 + (c>>3))*8 + (c&7)];
    }

    auto issue = [&](int kb, int buf){
#pragma unroll
        for (int i2=0;i2<4;i2++){
            int cc = tid + i2*256;             // 0..1023: K chunks
            int r = cc>>3, ch = cc&7;
            cpa16(sbase + (SH_K + buf*K_ST + r*36 + ch*4)*4, Kpw + (size_t)(kb+r)*32 + ch*4);
        }
#pragma unroll
        for (int i2=0;i2<4;i2++){
            int cc = tid + i2*256;             // 0..1023: V chunks
            int r = cc>>4, ch = cc&15;
            cpa16(sbase + (SH_V + buf*V_ST + r*72 + ch*4)*4, Vint + (size_t)((kb>>1)+r)*64 + ch*4);
        }
        asm volatile("cp.async.commit_group;");
    };

    issue(0, 0);
    __syncthreads();   // Q + adj ready

    const int wid = tid>>5, lane = tid&31, g = lane>>2, t = lane&3;
    const int rg = wid>>1, h = wid&1;
    const int r0 = rg*16;
    const int qlo = q0 + r0 + g;
    const int sidx4 = ((rg*2+h)*8 + g)*4;
    const int pidx4 = ((rg*2+(h^1))*8 + g)*4;
    const float scale = 0.04419417382415922f;

    // hoist Q fragments (invariant over k-blocks)
    uint32_t qa[4][4];
#pragma unroll
    for (int ks=0;ks<4;ks++){
        qa[ks][0]=Qh2[r0+g  ][ks*8+t];   qa[ks][1]=Qh2[r0+g+8][ks*8+t];
        qa[ks][2]=Qh2[r0+g  ][ks*8+t+4]; qa[ks][3]=Qh2[r0+g+8][ks*8+t+4];
    }

    float m_lo=-1e30f, m_hi=-1e30f, l_lo=0.f, l_hi=0.f;
    float o[8][4] = {};

    for (int kbi=0; kbi<8; kbi++){
        int kb = kbi*128;
        if (kbi < 7) issue(kb+128, (kbi+1)&1);
        if (kbi < 7) asm volatile("cp.async.wait_group 1;");
        else         asm volatile("cp.async.wait_group 0;");
        __syncthreads();
        uint32_t (*Kb)[36] = (uint32_t(*)[36])(sh + SH_K + (kbi&1)*K_ST);
        uint32_t (*Vb)[72] = (uint32_t(*)[72])(sh + SH_V + (kbi&1)*V_ST);

        // S = Q K^T: 16 rows x 64 keys (this warp's half)
        float c[8][4] = {};
#pragma unroll
        for (int ks=0; ks<4; ks++){
#pragma unroll
            for (int ni=0;ni<8;ni++){
                uint32_t b[2];
                b[0]=Kb[h*64+ni*8+g][ks*8+t];
                b[1]=Kb[h*64+ni*8+g][ks*8+t+4];
                mma16(c[ni], qa[ks], b);
            }
        }
#pragma unroll
        for (int ni=0;ni<8;ni++){
            int kk = kb + h*64 + ni*8 + 2*t;
            c[ni][0] = fmaf(c[ni][0], scale, adj_s[abs(qlo   - kk    )]);
            c[ni][1] = fmaf(c[ni][1], scale, adj_s[abs(qlo   - kk - 1)]);
            c[ni][2] = fmaf(c[ni][2], scale, adj_s[abs(qlo+8 - kk    )]);
            c[ni][3] = fmaf(c[ni][3], scale, adj_s[abs(qlo+8 - kk - 1)]);
        }
        // own-warp row max (rows live inside one quad)
        float rmx_lo=-1e30f, rmx_hi=-1e30f;
#pragma unroll
        for (int ni=0;ni<8;ni++){
            rmx_lo = fmaxf(rmx_lo, fmaxf(c[ni][0], c[ni][1]));
            rmx_hi = fmaxf(rmx_hi, fmaxf(c[ni][2], c[ni][3]));
        }
        rmx_lo = fmaxf(rmx_lo, __shfl_xor_sync(0xffffffffu, rmx_lo, 1));
        rmx_lo = fmaxf(rmx_lo, __shfl_xor_sync(0xffffffffu, rmx_lo, 2));
        rmx_hi = fmaxf(rmx_hi, __shfl_xor_sync(0xffffffffu, rmx_hi, 1));
        rmx_hi = fmaxf(rmx_hi, __shfl_xor_sync(0xffffffffu, rmx_hi, 2));
        // exp against own max + partial rowsum
        float rs_lo=0.f, rs_hi=0.f;
#pragma unroll
        for (int ni=0;ni<8;ni++){
            c[ni][0]=__expf(c[ni][0]-rmx_lo); c[ni][1]=__expf(c[ni][1]-rmx_lo);
            c[ni][2]=__expf(c[ni][2]-rmx_hi); c[ni][3]=__expf(c[ni][3]-rmx_hi);
            rs_lo += c[ni][0]+c[ni][1];
            rs_hi += c[ni][2]+c[ni][3];
        }
        rs_lo += __shfl_xor_sync(0xffffffffu, rs_lo, 1);
        rs_lo += __shfl_xor_sync(0xffffffffu, rs_lo, 2);
        rs_hi += __shfl_xor_sync(0xffffffffu, rs_hi, 1);
        rs_hi += __shfl_xor_sync(0xffffffffu, rs_hi, 2);
        // single exchange: (max_lo, max_hi, sum_lo, sum_hi)
        if ((lane&3)==0) *(float4*)&sb[sidx4] = make_float4(rmx_lo, rmx_hi, rs_lo, rs_hi);
        asm volatile("bar.sync %0, 64;" :: "r"(rg+1) : "memory");
        float4 pr = *(float4*)&sb[pidx4];
        float mn_lo = fmaxf(fmaxf(m_lo, rmx_lo), pr.x);
        float mn_hi = fmaxf(fmaxf(m_hi, rmx_hi), pr.y);
        float fold_lo = __expf(m_lo - mn_lo),   fold_hi = __expf(m_hi - mn_hi);
        float fown_lo = __expf(rmx_lo - mn_lo), fown_hi = __expf(rmx_hi - mn_hi);
        l_lo = l_lo*fold_lo + rs_lo*fown_lo + pr.z*__expf(pr.x - mn_lo);
        l_hi = l_hi*fold_hi + rs_hi*fown_hi + pr.w*__expf(pr.y - mn_hi);
        m_lo = mn_lo; m_hi = mn_hi;
#pragma unroll
        for (int ni=0;ni<8;ni++){
            o[ni][0]*=fold_lo; o[ni][1]*=fold_lo; o[ni][2]*=fold_hi; o[ni][3]*=fold_hi;
        }
        // P @ V with own->merged correction folded into the pack
#pragma unroll
        for (int j=0; j<4; j++){
            uint32_t a[4];
            a[0] = packh2(c[2*j  ][0]*fown_lo, c[2*j  ][1]*fown_lo);
            a[1] = packh2(c[2*j  ][2]*fown_hi, c[2*j  ][3]*fown_hi);
            a[2] = packh2(c[2*j+1][0]*fown_lo, c[2*j+1][1]*fown_lo);
            a[3] = packh2(c[2*j+1][2]*fown_hi, c[2*j+1][3]*fown_hi);
#pragma unroll
            for (int ni=0;ni<8;ni++){
                uint32_t b[2];
                b[0]=Vb[h*32+j*8+t  ][ni*8+g];
                b[1]=Vb[h*32+j*8+t+4][ni*8+g];
                mma16(o[ni], a, b);
            }
        }
        __syncthreads();
    }

    // merge partner halves: h==0 writes normalized, h==1 adds
    float rcp_lo = 1.f/l_lo, rcp_hi = 1.f/l_hi;
    if (h==0){
#pragma unroll
        for (int ni=0;ni<8;ni++){
            Og[r0+g  ][ni*8+2*t  ] = o[ni][0]*rcp_lo;
            Og[r0+g  ][ni*8+2*t+1] = o[ni][1]*rcp_lo;
            Og[r0+g+8][ni*8+2*t  ] = o[ni][2]*rcp_hi;
            Og[r0+g+8][ni*8+2*t+1] = o[ni][3]*rcp_hi;
        }
    }
    __syncthreads();
    if (h==1){
#pragma unroll
        for (int ni=0;ni<8;ni++){
            Og[r0+g  ][ni*8+2*t  ] += o[ni][0]*rcp_lo;
            Og[r0+g  ][ni*8+2*t+1] += o[ni][1]*rcp_lo;
            Og[r0+g+8][ni*8+2*t  ] += o[ni][2]*rcp_hi;
            Og[r0+g+8][ni*8+2*t+1] += o[ni][3]*rcp_hi;
        }
    }
    __syncthreads();

    // ---- local-window epilogue: 4 lanes per row, 16 dims each ----
    const float aa = 1.f/(1.f+__expf(-alpha[layer]));
    const int rowl = wid*8 + (lane>>2);
    const int q = q0 + rowl;
    const int d0 = (lane&3)*16;
    const int lo = (q-4>0)? q-4 : 0;
    const int hi = (q+4<Tn-1)? q+4 : Tn-1;
    const int nw = hi-lo+1;

    float s[9];
    for (int j=0;j<nw;j++){
        float dot = 0.f;
#pragma unroll
        for (int i=0;i<8;i++){
            __half2 q2 = *(__half2*)&Qh2[rowl][(d0>>1)+i];
            __half2 k2 = *(__half2*)&Kpw[(size_t)(lo+j)*(DHn/2) + (d0>>1)+i];
            dot = fmaf(__half2float(q2.x), __half2float(k2.x), dot);
            dot = fmaf(__half2float(q2.y), __half2float(k2.y), dot);
        }
        dot += __shfl_xor_sync(0xffffffffu, dot, 1);
        dot += __shfl_xor_sync(0xffffffffu, dot, 2);
        s[j] = fmaf(dot, scale, adj_s[abs(q-(lo+j))]);
    }
    float lm = -1e30f;
    for (int j=0;j<nw;j++) lm = fmaxf(lm, s[j]);
    float ls = 0.f;
    for (int j=0;j<nw;j++){ s[j] = __expf(s[j]-lm); ls += s[j]; }
    float linv = (1.f-aa)/ls;

    float acc[16];
#pragma unroll
    for (int i=0;i<16;i++) acc[i] = aa*Og[rowl][d0+i];
    for (int j=0;j<nw;j++){
        float w = s[j]*linv;
#pragma unroll
        for (int i=0;i<8;i++){
            __half2 v2 = *(__half2*)&Vpw[(size_t)(lo+j)*(DHn/2) + (d0>>1)+i];
            acc[2*i  ] = fmaf(w, __half2float(v2.x), acc[2*i  ]);
            acc[2*i+1] = fmaf(w, __half2float(v2.y), acc[2*i+1]);
        }
    }
    float* outp = &g_tmp[(size_t)p*Tn*DHn + (size_t)q*DHn + d0];
#pragma unroll
    for (int i=0;i<16;i+=4){
        float4 v;
        v.x=powtf(acc[i]); v.y=powtf(acc[i+1]); v.z=powtf(acc[i+2]); v.w=powtf(acc[i+3]);
        *(float4*)&outp[i] = v;
    }
}

// ---------------- column L2 norms over seq axis (per b,d) ----------------
__global__ void k_colnorm(){
    int tid = threadIdx.x;
    int col = blockIdx.x*8 + (tid>>5);   // 0..4095
    int lane = tid&31;
    int b = col >> 9, d = col & (Dn-1);
    const float* base = g_tmp + (size_t)b*Tn*Dn + d;
    float sum = 0.f;
    for (int t=lane; t<Tn; t+=32){ float v = base[(size_t)t*Dn]; sum = fmaf(v,v,sum); }
#pragma unroll
    for (int o=16;o;o>>=1) sum += __shfl_xor_sync(0xffffffffu,sum,o);
    if (lane==0) g_invnorm[col] = 1.f/fmaxf(sqrtf(sum), 1e-12f);
}

// ---------------- scale tmp by invnorm -> fp16 ----------------
__global__ void k_scale_tmp(){
    int i = blockIdx.x*256 + threadIdx.x;   // word idx < ROWS*256
    int d0 = (i & 255)*2;
    int row = i >> 8;
    float2 v = *(float2*)&g_tmp[(size_t)row*Dn + d0];
    const float* inv = &g_invnorm[(row>>10)*Dn + d0];
    g_tmph[i] = packh2(v.x*inv[0], v.y*inv[1]);
}

// ---------------- LayerNorm over D, writes fp32 + fp16 shadow ----------------
__global__ __launch_bounds__(128) void k_ln(
    const float* __restrict__ lng, const float* __restrict__ lnb, int layer)
{
    __shared__ float shm[10];
    int r = blockIdx.x;
    int tid = threadIdx.x, lane = tid&31, wid = tid>>5;
    int d0 = tid*4;
    float4 v = *(const float4*)&g_xb[(size_t)r*Dn + d0];
    float sum = v.x+v.y+v.z+v.w;
    float sq  = v.x*v.x+v.y*v.y+v.z*v.z+v.w*v.w;
#pragma unroll
    for (int o=16;o;o>>=1){ sum += __shfl_xor_sync(0xffffffffu,sum,o); sq += __shfl_xor_sync(0xffffffffu,sq,o); }
    if (lane==0){ shm[wid]=sum; shm[4+wid]=sq; }
    __syncthreads();
    if (tid==0){ shm[8]=shm[0]+shm[1]+shm[2]+shm[3]; shm[9]=shm[4]+shm[5]+shm[6]+shm[7]; }
    __syncthreads();
    float mu  = shm[8]*(1.f/Dn);
    float var = shm[9]*(1.f/Dn) - mu*mu;
    float rstd = rsqrtf(fmaxf(var,0.f) + 1e-5f);
    float4 gg = *(const float4*)&lng[layer*Dn + d0];
    float4 bb = *(const float4*)&lnb[layer*Dn + d0];
    float y0 = (v.x-mu)*rstd*gg.x + bb.x;
    float y1 = (v.y-mu)*rstd*gg.y + bb.y;
    float y2 = (v.z-mu)*rstd*gg.z + bb.z;
    float y3 = (v.w-mu)*rstd*gg.w + bb.w;
    *(float4*)&g_xb[(size_t)r*Dn + d0] = make_float4(y0,y1,y2,y3);
    g_xbh[(size_t)r*256 + tid*2    ] = packh2(y0,y1);
    g_xbh[(size_t)r*256 + tid*2 + 1] = packh2(y2,y3);
}

// ---------------- launch ----------------
extern "C" void kernel_launch(void* const* d_in, const int* in_sizes, int n_in,
                              void* d_out, int out_size)
{
    const float* x     = (const float*)d_in[0];
    const float* Wq    = (const float*)d_in[1];
    const float* bq    = (const float*)d_in[2];
    const float* Wk    = (const float*)d_in[3];
    const float* bk    = (const float*)d_in[4];
    const float* Wv    = (const float*)d_in[5];
    const float* bv    = (const float*)d_in[6];
    const float* Wo    = (const float*)d_in[7];
    const float* bo    = (const float*)d_in[8];
    const float* alpha = (const float*)d_in[9];
    const float* ln_g  = (const float*)d_in[10];
    const float* ln_b  = (const float*)d_in[11];
    const float* adj_w = (const float*)d_in[12];
    const float* adj_b = (const float*)d_in[13];
    float* out = (float*)d_out;

    cudaFuncSetAttribute(k_flash, cudaFuncAttributeMaxDynamicSharedMemorySize, FLASH_SMEM);
    cudaFuncSetAttribute(k_proj,  cudaFuncAttributeMaxDynamicSharedMemorySize, PROJ_SMEM);

    k_prep_w<<<4096, 256>>>(Wq, Wk, Wv, Wo);
    k_transpose_in<<<ROWS, 256>>>(x);
    k_adj<<<1, Tn>>>(adj_w, adj_b);
    for (int l=0; l<2; l++){
        k_proj<<<dim3(8,64,3), 256, PROJ_SMEM>>>(bq,bk,bv,bo, 0, l);
        k_vint<<<4096, 256>>>();
        k_flash<<<dim3(16,64), 256, FLASH_SMEM>>>(alpha, l);
        k_colnorm<<<512, 256>>>();
        k_scale_tmp<<<ROWS, 256>>>();
        k_proj<<<dim3(8,64,1), 256, PROJ_SMEM>>>(bq,bk,bv,bo, 1, l);
        k_ln<<<ROWS, 128>>>(ln_g, ln_b, l);
    }
    k_transpose_out<<<(ROWS*Dn)/256, 256>>>(out);
}

// round 10
// speedup vs baseline: 2.4950x; 1.0107x over previous
#include <cuda_runtime.h>
#include <cuda_fp16.h>
#include <math.h>
#include <stdint.h>

#define Tn 1024
#define Bn 8
#define Dn 512
#define Hn 8
#define DHn 64
#define NPAIR 64           // Hn*Bn
#define ROWS (Bn*Tn)       // 8192

// ---------------- scratch (device globals: allocation-free) ----------------
__device__ float    g_xb [Bn*Tn*Dn];
__device__ uint32_t g_xbh[Bn*Tn*Dn/2];   // xb fp16 shadow, half2 pairs over d
__device__ uint32_t g_Qh [Bn*Tn*Dn/2];
__device__ uint32_t g_Kh [Bn*Tn*Dn/2];
__device__ uint32_t g_Vh [Bn*Tn*Dn/2];
__device__ float    g_tmp[Bn*Tn*Dn];
__device__ uint32_t g_tmph[Bn*Tn*Dn/2];  // (tmp*invnorm) fp16, pairs over d
__device__ uint32_t g_Wh [8*256*512];    // [layer*4+z][k/2][n] half2 pairs over k
__device__ float    g_invnorm[Bn*Dn];
__device__ float    g_adj[Tn];

__device__ __forceinline__ float powtf(float v){
    return sqrtf(fmaxf(v,0.f)) - sqrtf(fmaxf(-v,0.f));
}

__device__ __forceinline__ uint32_t packh2(float a, float b){
    __half2 h = __floats2half2_rn(a, b);   // .x (low) = a
    return *(uint32_t*)&h;
}

// mma.sync m16n8k16 fp16 in, fp32 accum, row.col
__device__ __forceinline__ void mma16(float* c, const uint32_t* a, const uint32_t* b){
    asm volatile(
        "mma.sync.aligned.m16n8k16.row.col.f32.f16.f16.f32 "
        "{%0,%1,%2,%3},{%4,%5,%6,%7},{%8,%9},{%0,%1,%2,%3};"
        : "+f"(c[0]),"+f"(c[1]),"+f"(c[2]),"+f"(c[3])
        : "r"(a[0]),"r"(a[1]),"r"(a[2]),"r"(a[3]),"r"(b[0]),"r"(b[1]));
}

__device__ __forceinline__ void cpa16(uint32_t dst, const void* src){
    asm volatile("cp.async.cg.shared.global [%0], [%1], 16;" :: "r"(dst), "l"(src));
}

__device__ __forceinline__ void ldsm4(uint32_t& r0, uint32_t& r1, uint32_t& r2, uint32_t& r3, uint32_t addr){
    asm volatile("ldmatrix.sync.aligned.m8n8.x4.shared.b16 {%0,%1,%2,%3}, [%4];"
        : "=r"(r0),"=r"(r1),"=r"(r2),"=r"(r3) : "r"(addr));
}

__device__ __forceinline__ void ldsm4t(uint32_t& r0, uint32_t& r1, uint32_t& r2, uint32_t& r3, uint32_t addr){
    asm volatile("ldmatrix.sync.aligned.m8n8.x4.trans.shared.b16 {%0,%1,%2,%3}, [%4];"
        : "=r"(r0),"=r"(r1),"=r"(r2),"=r"(r3) : "r"(addr));
}

// ---------------- weight prep: fp32 -> fp16 k-paired, once ----------------
__global__ void k_prep_w(const float* __restrict__ Wq, const float* __restrict__ Wk,
                         const float* __restrict__ Wv, const float* __restrict__ Wo){
    int idx = blockIdx.x*256 + threadIdx.x;       // < 8*131072
    int m8  = idx >> 17;
    int rem = idx & 131071;
    int kp  = rem >> 9;
    int n   = rem & 511;
    int l = m8 >> 2, z = m8 & 3;
    const float* W = (z==0?Wq:(z==1?Wk:(z==2?Wv:Wo))) + (size_t)l*Dn*Dn;
    g_Wh[idx] = packh2(W[(size_t)(2*kp)*Dn + n], W[(size_t)(2*kp+1)*Dn + n]);
}

// ---------------- transpose in: x[T,B,D] -> g_xb[B,T,D] + fp16 shadow ----------------
__global__ void k_transpose_in(const float* __restrict__ x){
    int i = blockIdx.x*256 + threadIdx.x;         // word idx < ROWS*256
    int d0 = (i & 255)*2;
    int row = i >> 8;
    int b = row >> 10, t = row & 1023;
    const float* src = &x[(size_t)(t*Bn + b)*Dn + d0];
    float v0 = src[0], v1 = src[1];
    float2* dst = (float2*)&g_xb[(size_t)row*Dn + d0];
    *dst = make_float2(v0, v1);
    g_xbh[i] = packh2(v0, v1);
}

__global__ void k_transpose_out(float* __restrict__ out){
    int idx = blockIdx.x*256 + threadIdx.x;          // [T,B,D] linear
    int d = idx & (Dn-1);
    int b = (idx >> 9) & (Bn-1);
    int t = idx >> 12;
    out[idx] = g_xb[((b<<10) + t)*Dn + d];
}

// ---------------- adj table ----------------
__global__ void k_adj(const float* __restrict__ aw, const float* __restrict__ ab){
    int i = threadIdx.x;
    float dist = (float)i;
    g_adj[i] = expf(-fabsf(aw[0]*dist*dist - ab[0]));
}

// ================= unified cp.async double-buffered fp16 GEMM (round-8, unchanged) =================
#define PA_ST 4608
#define PB_ST 2304
#define PROJ_SMEM ((2*PA_ST + 2*PB_ST)*4)

__global__ __launch_bounds__(256,2) void k_proj(
    const float* __restrict__ bq, const float* __restrict__ bk,
    const float* __restrict__ bv, const float* __restrict__ bo,
    int mode, int layer)
{
    extern __shared__ uint32_t shp[];
    const int tid = threadIdx.x;
    const int z   = (mode==0) ? blockIdx.z : 3;
    const uint32_t* Bsrc = g_Wh + (size_t)(layer*4 + z)*131072;
    const uint32_t* Asrc = (mode==0) ? g_xbh : g_tmph;
    const float* bias = ((mode==0) ? (z==0?bq:(z==1?bk:bv)) : bo) + layer*Dn;
    uint32_t* Ch = (z==0? g_Qh : (z==1? g_Kh : g_Vh));

    const int m0 = blockIdx.y*128, n0 = blockIdx.x*64;
    const int wid = tid>>5, lane = tid&31, g = lane>>2, t = lane&3;
    const int m_off = (wid>>1)*32, n_off = (wid&1)*32;
    const uint32_t sbase = (uint32_t)__cvta_generic_to_shared(shp);

    float c[2][4][4] = {};

    auto issue = [&](int kt, int buf){
        const uint32_t* Ag = Asrc + (size_t)m0*256 + kt*32;
#pragma unroll
        for (int i2=0;i2<4;i2++){
            int cc = tid + i2*256;
            int r = cc>>3, ch = cc&7;
            cpa16(sbase + (buf*PA_ST + r*36 + ch*4)*4, Ag + (size_t)r*256 + ch*4);
        }
        const uint32_t* Bg = Bsrc + (size_t)(kt*32)*512 + n0;
#pragma unroll
        for (int i2=0;i2<2;i2++){
            int cc = tid + i2*256;
            int kr = cc>>4, ch = cc&15;
            cpa16(sbase + (2*PA_ST + buf*PB_ST + kr*72 + ch*4)*4, Bg + (size_t)kr*512 + ch*4);
        }
        asm volatile("cp.async.commit_group;");
    };

    issue(0, 0);
    for (int kt=0; kt<8; kt++){
        if (kt < 7) issue(kt+1, (kt+1)&1);
        if (kt < 7) asm volatile("cp.async.wait_group 1;");
        else        asm volatile("cp.async.wait_group 0;");
        __syncthreads();
        uint32_t (*Ah2)[36] = (uint32_t(*)[36])(shp + (kt&1)*PA_ST);
        uint32_t (*Bh2)[72] = (uint32_t(*)[72])(shp + 2*PA_ST + (kt&1)*PB_ST);
#pragma unroll
        for (int j=0; j<4; j++){
            uint32_t a[2][4], b[4][2];
#pragma unroll
            for (int mi=0;mi<2;mi++){
                int r = m_off+mi*16;
                a[mi][0]=Ah2[r+g  ][j*8+t];   a[mi][1]=Ah2[r+g+8][j*8+t];
                a[mi][2]=Ah2[r+g  ][j*8+t+4]; a[mi][3]=Ah2[r+g+8][j*8+t+4];
            }
#pragma unroll
            for (int ni=0;ni<4;ni++){
                b[ni][0]=Bh2[j*8+t  ][n_off+ni*8+g];
                b[ni][1]=Bh2[j*8+t+4][n_off+ni*8+g];
            }
#pragma unroll
            for (int mi=0;mi<2;mi++)
#pragma unroll
                for (int ni=0;ni<4;ni++) mma16(c[mi][ni], a[mi], b[ni]);
        }
        __syncthreads();
    }

#pragma unroll
    for (int mi=0;mi<2;mi++){
#pragma unroll
        for (int ni=0;ni<4;ni++){
            int row = m0 + m_off + mi*16 + g;
            int col = n0 + n_off + ni*8 + 2*t;
            float b0 = bias[col], b1 = bias[col+1];
            if (mode==0){
                int w = col>>1;
                Ch[(size_t)row*256 + w]     = packh2(c[mi][ni][0]+b0, c[mi][ni][1]+b1);
                Ch[(size_t)(row+8)*256 + w] = packh2(c[mi][ni][2]+b0, c[mi][ni][3]+b1);
            } else {
                float2 r0 = *(float2*)&g_xb[(size_t)row*Dn + col];
                float2 r1 = *(float2*)&g_xb[(size_t)(row+8)*Dn + col];
                float2 v0 = {c[mi][ni][0]+b0+r0.x, c[mi][ni][1]+b1+r0.y};
                float2 v1 = {c[mi][ni][2]+b0+r1.x, c[mi][ni][3]+b1+r1.y};
                *(float2*)&g_xb[(size_t)row*Dn + col]     = v0;
                *(float2*)&g_xb[(size_t)(row+8)*Dn + col] = v1;
            }
        }
    }
}

// ================= flash attention: ldmatrix B-frags, plain V layout =================
#define K_ST 4608                  // 128 rows * 36
#define V_ST 4608                  // 128 rows * 36 (plain [key][d-word], same as K)
#define SH_Q   0                   // 64*36 = 2304
#define SH_K   2304
#define SH_V   (SH_K + 2*K_ST)     // 11520
#define SH_ADJ (SH_V + 2*V_ST)     // 20736
#define SH_SB  (SH_ADJ + Tn)       // 21760
#define FLASH_SMEM ((SH_SB + 256)*4)   // 88064 B
#define OG_STRIDE 68

__global__ __launch_bounds__(256,2) void k_flash(const float* __restrict__ alpha, int layer){
    extern __shared__ uint32_t sh[];
    uint32_t (*Qh2)[36] = (uint32_t(*)[36])(sh + SH_Q);
    float* adj_s = (float*)(sh + SH_ADJ);
    float* sb    = (float*)(sh + SH_SB);
    float (*Og)[OG_STRIDE] = (float(*)[OG_STRIDE])(sh + SH_K);  // overlay K stages post-mainloop

    const int tid = threadIdx.x;
    const int p  = blockIdx.y;
    const int q0 = blockIdx.x*64;
    const uint4* Qp4 = (const uint4*)(g_Qh + ((size_t)p<<15));
    const uint32_t* Kpw = g_Kh + ((size_t)p<<15);
    const uint32_t* Vpw = g_Vh + ((size_t)p<<15);
    const uint32_t sbase = (uint32_t)__cvta_generic_to_shared(sh);

    for (int i=tid;i<Tn;i+=256) adj_s[i] = g_adj[i];
#pragma unroll
    for (int i=0;i<2;i++){
        int c = tid + i*256;
        *(uint4*)&Qh2[c>>3][(c&7)<<2] = Qp4[(size_t)(q0 + (c>>3))*8 + (c&7)];
    }

    auto issue = [&](int kb, int buf){
#pragma unroll
        for (int i2=0;i2<4;i2++){
            int cc = tid + i2*256;             // K: 128 rows x 8 chunks
            int r = cc>>3, ch = cc&7;
            cpa16(sbase + (SH_K + buf*K_ST + r*36 + ch*4)*4, Kpw + (size_t)(kb+r)*32 + ch*4);
        }
#pragma unroll
        for (int i2=0;i2<4;i2++){
            int cc = tid + i2*256;             // V: 128 rows x 8 chunks (plain layout)
            int r = cc>>3, ch = cc&7;
            cpa16(sbase + (SH_V + buf*V_ST + r*36 + ch*4)*4, Vpw + (size_t)(kb+r)*32 + ch*4);
        }
        asm volatile("cp.async.commit_group;");
    };

    issue(0, 0);
    __syncthreads();   // Q + adj ready

    const int wid = tid>>5, lane = tid&31, g = lane>>2, t = lane&3;
    const int rg = wid>>1, h = wid&1;
    const int r0 = rg*16;
    const int qlo = q0 + r0 + g;
    const int sidx4 = ((rg*2+h)*8 + g)*4;
    const int pidx4 = ((rg*2+(h^1))*8 + g)*4;
    const float scale = 0.04419417382415922f;

    // hoist Q fragments (invariant over k-blocks)
    uint32_t qa[4][4];
#pragma unroll
    for (int ks=0;ks<4;ks++){
        qa[ks][0]=Qh2[r0+g  ][ks*8+t];   qa[ks][1]=Qh2[r0+g+8][ks*8+t];
        qa[ks][2]=Qh2[r0+g  ][ks*8+t+4]; qa[ks][3]=Qh2[r0+g+8][ks*8+t+4];
    }

    // ldmatrix per-thread base offsets (words)
    const int rowin = lane&7;
    // K (normal): tiles (ni-part = lane>>4, d-half = (lane>>3)&1)
    const uint32_t k_off0 = (uint32_t)((h*64 + ((lane>>4)&1)*8 + rowin)*36 + ((lane>>3)&1)*4);
    // V (trans): tiles (row-half = (lane>>3)&1, ni-part = lane>>4)
    const uint32_t v_off0 = (uint32_t)((h*64 + ((lane>>3)&1)*8 + rowin)*36 + (lane>>4)*4);

    float m_lo=-1e30f, m_hi=-1e30f, l_lo=0.f, l_hi=0.f;
    float o[8][4] = {};

    for (int kbi=0; kbi<8; kbi++){
        int kb = kbi*128;
        if (kbi < 7) issue(kb+128, (kbi+1)&1);
        if (kbi < 7) asm volatile("cp.async.wait_group 1;");
        else         asm volatile("cp.async.wait_group 0;");
        __syncthreads();
        const uint32_t kstage = sbase + (SH_K + (kbi&1)*K_ST)*4;
        const uint32_t vstage = sbase + (SH_V + (kbi&1)*V_ST)*4;

        // S = Q K^T: 16 rows x 64 keys via ldmatrix b-frags
        float c[8][4] = {};
#pragma unroll
        for (int ks=0; ks<4; ks++){
#pragma unroll
            for (int m=0; m<4; m++){
                uint32_t b0,b1,b2,b3;
                ldsm4(b0,b1,b2,b3, kstage + (k_off0 + m*576 + ks*8)*4);
                uint32_t bb[2];
                bb[0]=b0; bb[1]=b1; mma16(c[2*m  ], qa[ks], bb);
                bb[0]=b2; bb[1]=b3; mma16(c[2*m+1], qa[ks], bb);
            }
        }
#pragma unroll
        for (int ni=0;ni<8;ni++){
            int kk = kb + h*64 + ni*8 + 2*t;
            c[ni][0] = fmaf(c[ni][0], scale, adj_s[abs(qlo   - kk    )]);
            c[ni][1] = fmaf(c[ni][1], scale, adj_s[abs(qlo   - kk - 1)]);
            c[ni][2] = fmaf(c[ni][2], scale, adj_s[abs(qlo+8 - kk    )]);
            c[ni][3] = fmaf(c[ni][3], scale, adj_s[abs(qlo+8 - kk - 1)]);
        }
        // own-warp row max (rows live inside one quad)
        float rmx_lo=-1e30f, rmx_hi=-1e30f;
#pragma unroll
        for (int ni=0;ni<8;ni++){
            rmx_lo = fmaxf(rmx_lo, fmaxf(c[ni][0], c[ni][1]));
            rmx_hi = fmaxf(rmx_hi, fmaxf(c[ni][2], c[ni][3]));
        }
        rmx_lo = fmaxf(rmx_lo, __shfl_xor_sync(0xffffffffu, rmx_lo, 1));
        rmx_lo = fmaxf(rmx_lo, __shfl_xor_sync(0xffffffffu, rmx_lo, 2));
        rmx_hi = fmaxf(rmx_hi, __shfl_xor_sync(0xffffffffu, rmx_hi, 1));
        rmx_hi = fmaxf(rmx_hi, __shfl_xor_sync(0xffffffffu, rmx_hi, 2));
        // exp against own max + partial rowsum
        float rs_lo=0.f, rs_hi=0.f;
#pragma unroll
        for (int ni=0;ni<8;ni++){
            c[ni][0]=__expf(c[ni][0]-rmx_lo); c[ni][1]=__expf(c[ni][1]-rmx_lo);
            c[ni][2]=__expf(c[ni][2]-rmx_hi); c[ni][3]=__expf(c[ni][3]-rmx_hi);
            rs_lo += c[ni][0]+c[ni][1];
            rs_hi += c[ni][2]+c[ni][3];
        }
        rs_lo += __shfl_xor_sync(0xffffffffu, rs_lo, 1);
        rs_lo += __shfl_xor_sync(0xffffffffu, rs_lo, 2);
        rs_hi += __shfl_xor_sync(0xffffffffu, rs_hi, 1);
        rs_hi += __shfl_xor_sync(0xffffffffu, rs_hi, 2);
        // single exchange: (max_lo, max_hi, sum_lo, sum_hi)
        if ((lane&3)==0) *(float4*)&sb[sidx4] = make_float4(rmx_lo, rmx_hi, rs_lo, rs_hi);
        asm volatile("bar.sync %0, 64;" :: "r"(rg+1) : "memory");
        float4 pr = *(float4*)&sb[pidx4];
        float mn_lo = fmaxf(fmaxf(m_lo, rmx_lo), pr.x);
        float mn_hi = fmaxf(fmaxf(m_hi, rmx_hi), pr.y);
        float fold_lo = __expf(m_lo - mn_lo),   fold_hi = __expf(m_hi - mn_hi);
        float fown_lo = __expf(rmx_lo - mn_lo), fown_hi = __expf(rmx_hi - mn_hi);
        l_lo = l_lo*fold_lo + rs_lo*fown_lo + pr.z*__expf(pr.x - mn_lo);
        l_hi = l_hi*fold_hi + rs_hi*fown_hi + pr.w*__expf(pr.y - mn_hi);
        m_lo = mn_lo; m_hi = mn_hi;
#pragma unroll
        for (int ni=0;ni<8;ni++){
            o[ni][0]*=fold_lo; o[ni][1]*=fold_lo; o[ni][2]*=fold_hi; o[ni][3]*=fold_hi;
        }
        // P @ V : ldmatrix.trans b-frags from plain V; own->merged correction in the pack
#pragma unroll
        for (int j=0; j<4; j++){
            uint32_t a[4];
            a[0] = packh2(c[2*j  ][0]*fown_lo, c[2*j  ][1]*fown_lo);
            a[1] = packh2(c[2*j  ][2]*fown_hi, c[2*j  ][3]*fown_hi);
            a[2] = packh2(c[2*j+1][0]*fown_lo, c[2*j+1][1]*fown_lo);
            a[3] = packh2(c[2*j+1][2]*fown_hi, c[2*j+1][3]*fown_hi);
#pragma unroll
            for (int m=0; m<4; m++){
                uint32_t b0,b1,b2,b3;
                ldsm4t(b0,b1,b2,b3, vstage + (v_off0 + j*576 + m*8)*4);
                uint32_t bb[2];
                bb[0]=b0; bb[1]=b1; mma16(o[2*m  ], a, bb);
                bb[0]=b2; bb[1]=b3; mma16(o[2*m+1], a, bb);
            }
        }
        __syncthreads();
    }

    // merge partner halves: h==0 writes normalized, h==1 adds
    float rcp_lo = 1.f/l_lo, rcp_hi = 1.f/l_hi;
    if (h==0){
#pragma unroll
        for (int ni=0;ni<8;ni++){
            Og[r0+g  ][ni*8+2*t  ] = o[ni][0]*rcp_lo;
            Og[r0+g  ][ni*8+2*t+1] = o[ni][1]*rcp_lo;
            Og[r0+g+8][ni*8+2*t  ] = o[ni][2]*rcp_hi;
            Og[r0+g+8][ni*8+2*t+1] = o[ni][3]*rcp_hi;
        }
    }
    __syncthreads();
    if (h==1){
#pragma unroll
        for (int ni=0;ni<8;ni++){
            Og[r0+g  ][ni*8+2*t  ] += o[ni][0]*rcp_lo;
            Og[r0+g  ][ni*8+2*t+1] += o[ni][1]*rcp_lo;
            Og[r0+g+8][ni*8+2*t  ] += o[ni][2]*rcp_hi;
            Og[r0+g+8][ni*8+2*t+1] += o[ni][3]*rcp_hi;
        }
    }
    __syncthreads();

    // ---- local-window epilogue: 4 lanes per row, 16 dims each ----
    const float aa = 1.f/(1.f+__expf(-alpha[layer]));
    const int rowl = wid*8 + (lane>>2);
    const int q = q0 + rowl;
    const int d0 = (lane&3)*16;
    const int lo = (q-4>0)? q-4 : 0;
    const int hi = (q+4<Tn-1)? q+4 : Tn-1;
    const int nw = hi-lo+1;

    float s[9];
    for (int j=0;j<nw;j++){
        float dot = 0.f;
#pragma unroll
        for (int i=0;i<8;i++){
            __half2 q2 = *(__half2*)&Qh2[rowl][(d0>>1)+i];
            __half2 k2 = *(__half2*)&Kpw[(size_t)(lo+j)*(DHn/2) + (d0>>1)+i];
            dot = fmaf(__half2float(q2.x), __half2float(k2.x), dot);
            dot = fmaf(__half2float(q2.y), __half2float(k2.y), dot);
        }
        dot += __shfl_xor_sync(0xffffffffu, dot, 1);
        dot += __shfl_xor_sync(0xffffffffu, dot, 2);
        s[j] = fmaf(dot, scale, adj_s[abs(q-(lo+j))]);
    }
    float lm = -1e30f;
    for (int j=0;j<nw;j++) lm = fmaxf(lm, s[j]);
    float ls = 0.f;
    for (int j=0;j<nw;j++){ s[j] = __expf(s[j]-lm); ls += s[j]; }
    float linv = (1.f-aa)/ls;

    float acc[16];
#pragma unroll
    for (int i=0;i<16;i++) acc[i] = aa*Og[rowl][d0+i];
    for (int j=0;j<nw;j++){
        float w = s[j]*linv;
#pragma unroll
        for (int i=0;i<8;i++){
            __half2 v2 = *(__half2*)&Vpw[(size_t)(lo+j)*(DHn/2) + (d0>>1)+i];
            acc[2*i  ] = fmaf(w, __half2float(v2.x), acc[2*i  ]);
            acc[2*i+1] = fmaf(w, __half2float(v2.y), acc[2*i+1]);
        }
    }
    float* outp = &g_tmp[(size_t)p*Tn*DHn + (size_t)q*DHn + d0];
#pragma unroll
    for (int i=0;i<16;i+=4){
        float4 v;
        v.x=powtf(acc[i]); v.y=powtf(acc[i+1]); v.z=powtf(acc[i+2]); v.w=powtf(acc[i+3]);
        *(float4*)&outp[i] = v;
    }
}

// ---------------- column L2 norms over seq axis (per b,d) ----------------
__global__ void k_colnorm(){
    int tid = threadIdx.x;
    int col = blockIdx.x*8 + (tid>>5);   // 0..4095
    int lane = tid&31;
    int b = col >> 9, d = col & (Dn-1);
    const float* base = g_tmp + (size_t)b*Tn*Dn + d;
    float sum = 0.f;
    for (int t=lane; t<Tn; t+=32){ float v = base[(size_t)t*Dn]; sum = fmaf(v,v,sum); }
#pragma unroll
    for (int o=16;o;o>>=1) sum += __shfl_xor_sync(0xffffffffu,sum,o);
    if (lane==0) g_invnorm[col] = 1.f/fmaxf(sqrtf(sum), 1e-12f);
}

// ---------------- scale tmp by invnorm -> fp16 ----------------
__global__ void k_scale_tmp(){
    int i = blockIdx.x*256 + threadIdx.x;   // word idx < ROWS*256
    int d0 = (i & 255)*2;
    int row = i >> 8;
    float2 v = *(float2*)&g_tmp[(size_t)row*Dn + d0];
    const float* inv = &g_invnorm[(row>>10)*Dn + d0];
    g_tmph[i] = packh2(v.x*inv[0], v.y*inv[1]);
}

// ---------------- LayerNorm over D, writes fp32 + fp16 shadow ----------------
__global__ __launch_bounds__(128) void k_ln(
    const float* __restrict__ lng, const float* __restrict__ lnb, int layer)
{
    __shared__ float shm[10];
    int r = blockIdx.x;
    int tid = threadIdx.x, lane = tid&31, wid = tid>>5;
    int d0 = tid*4;
    float4 v = *(const float4*)&g_xb[(size_t)r*Dn + d0];
    float sum = v.x+v.y+v.z+v.w;
    float sq  = v.x*v.x+v.y*v.y+v.z*v.z+v.w*v.w;
#pragma unroll
    for (int o=16;o;o>>=1){ sum += __shfl_xor_sync(0xffffffffu,sum,o); sq += __shfl_xor_sync(0xffffffffu,sq,o); }
    if (lane==0){ shm[wid]=sum; shm[4+wid]=sq; }
    __syncthreads();
    if (tid==0){ shm[8]=shm[0]+shm[1]+shm[2]+shm[3]; shm[9]=shm[4]+shm[5]+shm[6]+shm[7]; }
    __syncthreads();
    float mu  = shm[8]*(1.f/Dn);
    float var = shm[9]*(1.f/Dn) - mu*mu;
    float rstd = rsqrtf(fmaxf(var,0.f) + 1e-5f);
    float4 gg = *(const float4*)&lng[layer*Dn + d0];
    float4 bb = *(const float4*)&lnb[layer*Dn + d0];
    float y0 = (v.x-mu)*rstd*gg.x + bb.x;
    float y1 = (v.y-mu)*rstd*gg.y + bb.y;
    float y2 = (v.z-mu)*rstd*gg.z + bb.z;
    float y3 = (v.w-mu)*rstd*gg.w + bb.w;
    *(float4*)&g_xb[(size_t)r*Dn + d0] = make_float4(y0,y1,y2,y3);
    g_xbh[(size_t)r*256 + tid*2    ] = packh2(y0,y1);
    g_xbh[(size_t)r*256 + tid*2 + 1] = packh2(y2,y3);
}

// ---------------- launch ----------------
extern "C" void kernel_launch(void* const* d_in, const int* in_sizes, int n_in,
                              void* d_out, int out_size)
{
    const float* x     = (const float*)d_in[0];
    const float* Wq    = (const float*)d_in[1];
    const float* bq    = (const float*)d_in[2];
    const float* Wk    = (const float*)d_in[3];
    const float* bk    = (const float*)d_in[4];
    const float* Wv    = (const float*)d_in[5];
    const float* bv    = (const float*)d_in[6];
    const float* Wo    = (const float*)d_in[7];
    const float* bo    = (const float*)d_in[8];
    const float* alpha = (const float*)d_in[9];
    const float* ln_g  = (const float*)d_in[10];
    const float* ln_b  = (const float*)d_in[11];
    const float* adj_w = (const float*)d_in[12];
    const float* adj_b = (const float*)d_in[13];
    float* out = (float*)d_out;

    cudaFuncSetAttribute(k_flash, cudaFuncAttributeMaxDynamicSharedMemorySize, FLASH_SMEM);
    cudaFuncSetAttribute(k_proj,  cudaFuncAttributeMaxDynamicSharedMemorySize, PROJ_SMEM);

    k_prep_w<<<4096, 256>>>(Wq, Wk, Wv, Wo);
    k_transpose_in<<<ROWS, 256>>>(x);
    k_adj<<<1, Tn>>>(adj_w, adj_b);
    for (int l=0; l<2; l++){
        k_proj<<<dim3(8,64,3), 256, PROJ_SMEM>>>(bq,bk,bv,bo, 0, l);
        k_flash<<<dim3(16,64), 256, FLASH_SMEM>>>(alpha, l);
        k_colnorm<<<512, 256>>>();
        k_scale_tmp<<<ROWS, 256>>>();
        k_proj<<<dim3(8,64,1), 256, PROJ_SMEM>>>(bq,bk,bv,bo, 1, l);
        k_ln<<<ROWS, 128>>>(ln_g, ln_b, l);
    }
    k_transpose_out<<<(ROWS*Dn)/256, 256>>>(out);
}

// round 11
// speedup vs baseline: 2.5730x; 1.0312x over previous
#include <cuda_runtime.h>
#include <cuda_fp16.h>
#include <math.h>
#include <stdint.h>

#define Tn 1024
#define Bn 8
#define Dn 512
#define Hn 8
#define DHn 64
#define NPAIR 64           // Hn*Bn
#define ROWS (Bn*Tn)       // 8192
#define LOG2E 1.4426950408889634f

// ---------------- scratch (device globals: allocation-free) ----------------
__device__ float    g_xb [Bn*Tn*Dn];
__device__ uint32_t g_xbh[Bn*Tn*Dn/2];   // xb fp16 shadow, half2 pairs over d
__device__ uint32_t g_Qh [Bn*Tn*Dn/2];
__device__ uint32_t g_Kh [Bn*Tn*Dn/2];
__device__ uint32_t g_Vh [Bn*Tn*Dn/2];
__device__ float    g_tmp[Bn*Tn*Dn];
__device__ uint32_t g_tmph[Bn*Tn*Dn/2];  // (tmp*invnorm) fp16, pairs over d
__device__ uint32_t g_Wh [8*256*512];    // [layer*4+z][k/2][n] half2 pairs over k
__device__ float    g_invnorm[Bn*Dn];
__device__ float    g_adj[Tn];

__device__ __forceinline__ float powtf(float v){
    return sqrtf(fmaxf(v,0.f)) - sqrtf(fmaxf(-v,0.f));
}

__device__ __forceinline__ uint32_t packh2(float a, float b){
    __half2 h = __floats2half2_rn(a, b);   // .x (low) = a
    return *(uint32_t*)&h;
}

__device__ __forceinline__ float ex2a(float x){
    float y; asm("ex2.approx.ftz.f32 %0, %1;" : "=f"(y) : "f"(x)); return y;
}

// mma.sync m16n8k16 fp16 in, fp32 accum, row.col
__device__ __forceinline__ void mma16(float* c, const uint32_t* a, const uint32_t* b){
    asm volatile(
        "mma.sync.aligned.m16n8k16.row.col.f32.f16.f16.f32 "
        "{%0,%1,%2,%3},{%4,%5,%6,%7},{%8,%9},{%0,%1,%2,%3};"
        : "+f"(c[0]),"+f"(c[1]),"+f"(c[2]),"+f"(c[3])
        : "r"(a[0]),"r"(a[1]),"r"(a[2]),"r"(a[3]),"r"(b[0]),"r"(b[1]));
}

__device__ __forceinline__ void cpa16(uint32_t dst, const void* src){
    asm volatile("cp.async.cg.shared.global [%0], [%1], 16;" :: "r"(dst), "l"(src));
}

__device__ __forceinline__ void ldsm4(uint32_t& r0, uint32_t& r1, uint32_t& r2, uint32_t& r3, uint32_t addr){
    asm volatile("ldmatrix.sync.aligned.m8n8.x4.shared.b16 {%0,%1,%2,%3}, [%4];"
        : "=r"(r0),"=r"(r1),"=r"(r2),"=r"(r3) : "r"(addr));
}

__device__ __forceinline__ void ldsm4t(uint32_t& r0, uint32_t& r1, uint32_t& r2, uint32_t& r3, uint32_t addr){
    asm volatile("ldmatrix.sync.aligned.m8n8.x4.trans.shared.b16 {%0,%1,%2,%3}, [%4];"
        : "=r"(r0),"=r"(r1),"=r"(r2),"=r"(r3) : "r"(addr));
}

// ---------------- weight prep: fp32 -> fp16 k-paired, once ----------------
__global__ void k_prep_w(const float* __restrict__ Wq, const float* __restrict__ Wk,
                         const float* __restrict__ Wv, const float* __restrict__ Wo){
    int idx = blockIdx.x*256 + threadIdx.x;       // < 8*131072
    int m8  = idx >> 17;
    int rem = idx & 131071;
    int kp  = rem >> 9;
    int n   = rem & 511;
    int l = m8 >> 2, z = m8 & 3;
    const float* W = (z==0?Wq:(z==1?Wk:(z==2?Wv:Wo))) + (size_t)l*Dn*Dn;
    g_Wh[idx] = packh2(W[(size_t)(2*kp)*Dn + n], W[(size_t)(2*kp+1)*Dn + n]);
}

// ---------------- transpose in: x[T,B,D] -> g_xb[B,T,D] + fp16 shadow ----------------
__global__ void k_transpose_in(const float* __restrict__ x){
    int i = blockIdx.x*256 + threadIdx.x;         // word idx < ROWS*256
    int d0 = (i & 255)*2;
    int row = i >> 8;
    int b = row >> 10, t = row & 1023;
    const float* src = &x[(size_t)(t*Bn + b)*Dn + d0];
    float v0 = src[0], v1 = src[1];
    float2* dst = (float2*)&g_xb[(size_t)row*Dn + d0];
    *dst = make_float2(v0, v1);
    g_xbh[i] = packh2(v0, v1);
}

__global__ void k_transpose_out(float* __restrict__ out){
    int idx = blockIdx.x*256 + threadIdx.x;          // [T,B,D] linear
    int d = idx & (Dn-1);
    int b = (idx >> 9) & (Bn-1);
    int t = idx >> 12;
    out[idx] = g_xb[((b<<10) + t)*Dn + d];
}

// ---------------- adj table ----------------
__global__ void k_adj(const float* __restrict__ aw, const float* __restrict__ ab){
    int i = threadIdx.x;
    float dist = (float)i;
    g_adj[i] = expf(-fabsf(aw[0]*dist*dist - ab[0]));
}

// ================= unified cp.async double-buffered fp16 GEMM (round-8, unchanged) =================
#define PA_ST 4608
#define PB_ST 2304
#define PROJ_SMEM ((2*PA_ST + 2*PB_ST)*4)

__global__ __launch_bounds__(256,2) void k_proj(
    const float* __restrict__ bq, const float* __restrict__ bk,
    const float* __restrict__ bv, const float* __restrict__ bo,
    int mode, int layer)
{
    extern __shared__ uint32_t shp[];
    const int tid = threadIdx.x;
    const int z   = (mode==0) ? blockIdx.z : 3;
    const uint32_t* Bsrc = g_Wh + (size_t)(layer*4 + z)*131072;
    const uint32_t* Asrc = (mode==0) ? g_xbh : g_tmph;
    const float* bias = ((mode==0) ? (z==0?bq:(z==1?bk:bv)) : bo) + layer*Dn;
    uint32_t* Ch = (z==0? g_Qh : (z==1? g_Kh : g_Vh));

    const int m0 = blockIdx.y*128, n0 = blockIdx.x*64;
    const int wid = tid>>5, lane = tid&31, g = lane>>2, t = lane&3;
    const int m_off = (wid>>1)*32, n_off = (wid&1)*32;
    const uint32_t sbase = (uint32_t)__cvta_generic_to_shared(shp);

    float c[2][4][4] = {};

    auto issue = [&](int kt, int buf){
        const uint32_t* Ag = Asrc + (size_t)m0*256 + kt*32;
#pragma unroll
        for (int i2=0;i2<4;i2++){
            int cc = tid + i2*256;
            int r = cc>>3, ch = cc&7;
            cpa16(sbase + (buf*PA_ST + r*36 + ch*4)*4, Ag + (size_t)r*256 + ch*4);
        }
        const uint32_t* Bg = Bsrc + (size_t)(kt*32)*512 + n0;
#pragma unroll
        for (int i2=0;i2<2;i2++){
            int cc = tid + i2*256;
            int kr = cc>>4, ch = cc&15;
            cpa16(sbase + (2*PA_ST + buf*PB_ST + kr*72 + ch*4)*4, Bg + (size_t)kr*512 + ch*4);
        }
        asm volatile("cp.async.commit_group;");
    };

    issue(0, 0);
    for (int kt=0; kt<8; kt++){
        if (kt < 7) issue(kt+1, (kt+1)&1);
        if (kt < 7) asm volatile("cp.async.wait_group 1;");
        else        asm volatile("cp.async.wait_group 0;");
        __syncthreads();
        uint32_t (*Ah2)[36] = (uint32_t(*)[36])(shp + (kt&1)*PA_ST);
        uint32_t (*Bh2)[72] = (uint32_t(*)[72])(shp + 2*PA_ST + (kt&1)*PB_ST);
#pragma unroll
        for (int j=0; j<4; j++){
            uint32_t a[2][4], b[4][2];
#pragma unroll
            for (int mi=0;mi<2;mi++){
                int r = m_off+mi*16;
                a[mi][0]=Ah2[r+g  ][j*8+t];   a[mi][1]=Ah2[r+g+8][j*8+t];
                a[mi][2]=Ah2[r+g  ][j*8+t+4]; a[mi][3]=Ah2[r+g+8][j*8+t+4];
            }
#pragma unroll
            for (int ni=0;ni<4;ni++){
                b[ni][0]=Bh2[j*8+t  ][n_off+ni*8+g];
                b[ni][1]=Bh2[j*8+t+4][n_off+ni*8+g];
            }
#pragma unroll
            for (int mi=0;mi<2;mi++)
#pragma unroll
                for (int ni=0;ni<4;ni++) mma16(c[mi][ni], a[mi], b[ni]);
        }
        __syncthreads();
    }

#pragma unroll
    for (int mi=0;mi<2;mi++){
#pragma unroll
        for (int ni=0;ni<4;ni++){
            int row = m0 + m_off + mi*16 + g;
            int col = n0 + n_off + ni*8 + 2*t;
            float b0 = bias[col], b1 = bias[col+1];
            if (mode==0){
                int w = col>>1;
                Ch[(size_t)row*256 + w]     = packh2(c[mi][ni][0]+b0, c[mi][ni][1]+b1);
                Ch[(size_t)(row+8)*256 + w] = packh2(c[mi][ni][2]+b0, c[mi][ni][3]+b1);
            } else {
                float2 r0 = *(float2*)&g_xb[(size_t)row*Dn + col];
                float2 r1 = *(float2*)&g_xb[(size_t)(row+8)*Dn + col];
                float2 v0 = {c[mi][ni][0]+b0+r0.x, c[mi][ni][1]+b1+r0.y};
                float2 v1 = {c[mi][ni][2]+b0+r1.x, c[mi][ni][3]+b1+r1.y};
                *(float2*)&g_xb[(size_t)row*Dn + col]     = v0;
                *(float2*)&g_xb[(size_t)(row+8)*Dn + col] = v1;
            }
        }
    }
}

// ================= flash attention: private per-warp softmax stats, single merge =================
#define K_ST 4608                  // 128 rows * 36
#define V_ST 4608                  // 128 rows * 36 (plain [key][d-word])
#define SH_Q   0                   // 64*36 = 2304
#define SH_K   2304
#define SH_V   (SH_K + 2*K_ST)     // 11520
#define SH_ADJ (SH_V + 2*V_ST)     // 20736
#define SH_SB  (SH_ADJ + Tn)       // 21760
#define FLASH_SMEM ((SH_SB + 256)*4)   // 88064 B
#define OG_STRIDE 68

__global__ __launch_bounds__(256,2) void k_flash(const float* __restrict__ alpha, int layer){
    extern __shared__ uint32_t sh[];
    uint32_t (*Qh2)[36] = (uint32_t(*)[36])(sh + SH_Q);
    float* adj_s = (float*)(sh + SH_ADJ);     // log2-scaled adj
    float* sb    = (float*)(sh + SH_SB);
    float (*Og)[OG_STRIDE] = (float(*)[OG_STRIDE])(sh + SH_K);  // overlay K stages post-mainloop

    const int tid = threadIdx.x;
    const int p  = blockIdx.y;
    const int q0 = blockIdx.x*64;
    const uint4* Qp4 = (const uint4*)(g_Qh + ((size_t)p<<15));
    const uint32_t* Kpw = g_Kh + ((size_t)p<<15);
    const uint32_t* Vpw = g_Vh + ((size_t)p<<15);
    const uint32_t sbase = (uint32_t)__cvta_generic_to_shared(sh);

    for (int i=tid;i<Tn;i+=256) adj_s[i] = g_adj[i]*LOG2E;
#pragma unroll
    for (int i=0;i<2;i++){
        int c = tid + i*256;
        *(uint4*)&Qh2[c>>3][(c&7)<<2] = Qp4[(size_t)(q0 + (c>>3))*8 + (c&7)];
    }

    auto issue = [&](int kb, int buf){
#pragma unroll
        for (int i2=0;i2<4;i2++){
            int cc = tid + i2*256;             // K: 128 rows x 8 chunks
            int r = cc>>3, ch = cc&7;
            cpa16(sbase + (SH_K + buf*K_ST + r*36 + ch*4)*4, Kpw + (size_t)(kb+r)*32 + ch*4);
        }
#pragma unroll
        for (int i2=0;i2<4;i2++){
            int cc = tid + i2*256;             // V: 128 rows x 8 chunks (plain layout)
            int r = cc>>3, ch = cc&7;
            cpa16(sbase + (SH_V + buf*V_ST + r*36 + ch*4)*4, Vpw + (size_t)(kb+r)*32 + ch*4);
        }
        asm volatile("cp.async.commit_group;");
    };

    issue(0, 0);
    __syncthreads();   // Q + adj ready

    const int wid = tid>>5, lane = tid&31, g = lane>>2, t = lane&3;
    const int rg = wid>>1, h = wid&1;
    const int r0 = rg*16;
    const int qlo = q0 + r0 + g;
    const int sidx4 = ((rg*2+h)*8 + g)*4;
    const int pidx4 = ((rg*2+(h^1))*8 + g)*4;
    const float scale2 = 0.04419417382415922f * LOG2E;   // 1/sqrt(512) * log2(e)

    // hoist Q fragments (invariant over k-blocks)
    uint32_t qa[4][4];
#pragma unroll
    for (int ks=0;ks<4;ks++){
        qa[ks][0]=Qh2[r0+g  ][ks*8+t];   qa[ks][1]=Qh2[r0+g+8][ks*8+t];
        qa[ks][2]=Qh2[r0+g  ][ks*8+t+4]; qa[ks][3]=Qh2[r0+g+8][ks*8+t+4];
    }

    // ldmatrix per-thread base offsets (words)
    const int rowin = lane&7;
    const uint32_t k_off0 = (uint32_t)((h*64 + ((lane>>4)&1)*8 + rowin)*36 + ((lane>>3)&1)*4);
    const uint32_t v_off0 = (uint32_t)((h*64 + ((lane>>3)&1)*8 + rowin)*36 + (lane>>4)*4);

    // private per-warp online stats (log2 domain)
    float m_lo=-1e30f, m_hi=-1e30f, l_lo=0.f, l_hi=0.f;
    float o[8][4] = {};

    for (int kbi=0; kbi<8; kbi++){
        int kb = kbi*128;
        if (kbi < 7) issue(kb+128, (kbi+1)&1);
        if (kbi < 7) asm volatile("cp.async.wait_group 1;");
        else         asm volatile("cp.async.wait_group 0;");
        __syncthreads();
        const uint32_t kstage = sbase + (SH_K + (kbi&1)*K_ST)*4;
        const uint32_t vstage = sbase + (SH_V + (kbi&1)*V_ST)*4;

        // S = Q K^T: 16 rows x 64 keys via ldmatrix b-frags
        float c[8][4] = {};
#pragma unroll
        for (int ks=0; ks<4; ks++){
#pragma unroll
            for (int m=0; m<4; m++){
                uint32_t b0,b1,b2,b3;
                ldsm4(b0,b1,b2,b3, kstage + (k_off0 + m*576 + ks*8)*4);
                uint32_t bb[2];
                bb[0]=b0; bb[1]=b1; mma16(c[2*m  ], qa[ks], bb);
                bb[0]=b2; bb[1]=b3; mma16(c[2*m+1], qa[ks], bb);
            }
        }
#pragma unroll
        for (int ni=0;ni<8;ni++){
            int kk = kb + h*64 + ni*8 + 2*t;
            c[ni][0] = fmaf(c[ni][0], scale2, adj_s[abs(qlo   - kk    )]);
            c[ni][1] = fmaf(c[ni][1], scale2, adj_s[abs(qlo   - kk - 1)]);
            c[ni][2] = fmaf(c[ni][2], scale2, adj_s[abs(qlo+8 - kk    )]);
            c[ni][3] = fmaf(c[ni][3], scale2, adj_s[abs(qlo+8 - kk - 1)]);
        }
        // own-warp row max (rows live inside one quad)
        float rmx_lo=-1e30f, rmx_hi=-1e30f;
#pragma unroll
        for (int ni=0;ni<8;ni++){
            rmx_lo = fmaxf(rmx_lo, fmaxf(c[ni][0], c[ni][1]));
            rmx_hi = fmaxf(rmx_hi, fmaxf(c[ni][2], c[ni][3]));
        }
        rmx_lo = fmaxf(rmx_lo, __shfl_xor_sync(0xffffffffu, rmx_lo, 1));
        rmx_lo = fmaxf(rmx_lo, __shfl_xor_sync(0xffffffffu, rmx_lo, 2));
        rmx_hi = fmaxf(rmx_hi, __shfl_xor_sync(0xffffffffu, rmx_hi, 1));
        rmx_hi = fmaxf(rmx_hi, __shfl_xor_sync(0xffffffffu, rmx_hi, 2));
        float mn_lo = fmaxf(m_lo, rmx_lo), mn_hi = fmaxf(m_hi, rmx_hi);
        float fold_lo = ex2a(m_lo - mn_lo),  fold_hi = ex2a(m_hi - mn_hi);
        m_lo = mn_lo; m_hi = mn_hi;
        // exp against (merged-with-own) max + rowsum
        float rs_lo=0.f, rs_hi=0.f;
#pragma unroll
        for (int ni=0;ni<8;ni++){
            c[ni][0]=ex2a(c[ni][0]-mn_lo); c[ni][1]=ex2a(c[ni][1]-mn_lo);
            c[ni][2]=ex2a(c[ni][2]-mn_hi); c[ni][3]=ex2a(c[ni][3]-mn_hi);
            rs_lo += c[ni][0]+c[ni][1];
            rs_hi += c[ni][2]+c[ni][3];
        }
        rs_lo += __shfl_xor_sync(0xffffffffu, rs_lo, 1);
        rs_lo += __shfl_xor_sync(0xffffffffu, rs_lo, 2);
        rs_hi += __shfl_xor_sync(0xffffffffu, rs_hi, 1);
        rs_hi += __shfl_xor_sync(0xffffffffu, rs_hi, 2);
        l_lo = l_lo*fold_lo + rs_lo;
        l_hi = l_hi*fold_hi + rs_hi;
#pragma unroll
        for (int ni=0;ni<8;ni++){
            o[ni][0]*=fold_lo; o[ni][1]*=fold_lo; o[ni][2]*=fold_hi; o[ni][3]*=fold_hi;
        }
        // P @ V : ldmatrix.trans b-frags; plain pack (no cross-warp correction)
#pragma unroll
        for (int j=0; j<4; j++){
            uint32_t a[4];
            a[0] = packh2(c[2*j  ][0], c[2*j  ][1]);
            a[1] = packh2(c[2*j  ][2], c[2*j  ][3]);
            a[2] = packh2(c[2*j+1][0], c[2*j+1][1]);
            a[3] = packh2(c[2*j+1][2], c[2*j+1][3]);
#pragma unroll
            for (int m=0; m<4; m++){
                uint32_t b0,b1,b2,b3;
                ldsm4t(b0,b1,b2,b3, vstage + (v_off0 + j*576 + m*8)*4);
                uint32_t bb[2];
                bb[0]=b0; bb[1]=b1; mma16(o[2*m  ], a, bb);
                bb[0]=b2; bb[1]=b3; mma16(o[2*m+1], a, bb);
            }
        }
        __syncthreads();
    }

    // ---- single cross-warp merge of (m, l) triples ----
    if ((lane&3)==0) *(float4*)&sb[sidx4] = make_float4(m_lo, m_hi, l_lo, l_hi);
    asm volatile("bar.sync %0, 64;" :: "r"(rg+1) : "memory");
    float4 pr = *(float4*)&sb[pidx4];
    float M_lo = fmaxf(m_lo, pr.x), M_hi = fmaxf(m_hi, pr.y);
    float eo_lo = ex2a(m_lo - M_lo), ep_lo = ex2a(pr.x - M_lo);
    float eo_hi = ex2a(m_hi - M_hi), ep_hi = ex2a(pr.y - M_hi);
    float w_lo = eo_lo / fmaf(l_lo, eo_lo, pr.z*ep_lo);
    float w_hi = eo_hi / fmaf(l_hi, eo_hi, pr.w*ep_hi);

    if (h==0){
#pragma unroll
        for (int ni=0;ni<8;ni++){
            Og[r0+g  ][ni*8+2*t  ] = o[ni][0]*w_lo;
            Og[r0+g  ][ni*8+2*t+1] = o[ni][1]*w_lo;
            Og[r0+g+8][ni*8+2*t  ] = o[ni][2]*w_hi;
            Og[r0+g+8][ni*8+2*t+1] = o[ni][3]*w_hi;
        }
    }
    __syncthreads();
    if (h==1){
#pragma unroll
        for (int ni=0;ni<8;ni++){
            Og[r0+g  ][ni*8+2*t  ] += o[ni][0]*w_lo;
            Og[r0+g  ][ni*8+2*t+1] += o[ni][1]*w_lo;
            Og[r0+g+8][ni*8+2*t  ] += o[ni][2]*w_hi;
            Og[r0+g+8][ni*8+2*t+1] += o[ni][3]*w_hi;
        }
    }
    __syncthreads();

    // ---- local-window epilogue: 4 lanes per row, 16 dims each (log2 domain) ----
    const float aa = 1.f/(1.f+__expf(-alpha[layer]));
    const int rowl = wid*8 + (lane>>2);
    const int q = q0 + rowl;
    const int d0 = (lane&3)*16;
    const int lo = (q-4>0)? q-4 : 0;
    const int hi = (q+4<Tn-1)? q+4 : Tn-1;
    const int nw = hi-lo+1;

    float s[9];
    for (int j=0;j<nw;j++){
        float dot = 0.f;
#pragma unroll
        for (int i=0;i<8;i++){
            __half2 q2 = *(__half2*)&Qh2[rowl][(d0>>1)+i];
            __half2 k2 = *(__half2*)&Kpw[(size_t)(lo+j)*(DHn/2) + (d0>>1)+i];
            dot = fmaf(__half2float(q2.x), __half2float(k2.x), dot);
            dot = fmaf(__half2float(q2.y), __half2float(k2.y), dot);
        }
        dot += __shfl_xor_sync(0xffffffffu, dot, 1);
        dot += __shfl_xor_sync(0xffffffffu, dot, 2);
        s[j] = fmaf(dot, scale2, adj_s[abs(q-(lo+j))]);
    }
    float lm = -1e30f;
    for (int j=0;j<nw;j++) lm = fmaxf(lm, s[j]);
    float ls = 0.f;
    for (int j=0;j<nw;j++){ s[j] = ex2a(s[j]-lm); ls += s[j]; }
    float linv = (1.f-aa)/ls;

    float acc[16];
#pragma unroll
    for (int i=0;i<16;i++) acc[i] = aa*Og[rowl][d0+i];
    for (int j=0;j<nw;j++){
        float w = s[j]*linv;
#pragma unroll
        for (int i=0;i<8;i++){
            __half2 v2 = *(__half2*)&Vpw[(size_t)(lo+j)*(DHn/2) + (d0>>1)+i];
            acc[2*i  ] = fmaf(w, __half2float(v2.x), acc[2*i  ]);
            acc[2*i+1] = fmaf(w, __half2float(v2.y), acc[2*i+1]);
        }
    }
    float* outp = &g_tmp[(size_t)p*Tn*DHn + (size_t)q*DHn + d0];
#pragma unroll
    for (int i=0;i<16;i+=4){
        float4 v;
        v.x=powtf(acc[i]); v.y=powtf(acc[i+1]); v.z=powtf(acc[i+2]); v.w=powtf(acc[i+3]);
        *(float4*)&outp[i] = v;
    }
}

// ---------------- column L2 norms over seq axis (per b,d) ----------------
__global__ void k_colnorm(){
    int tid = threadIdx.x;
    int col = blockIdx.x*8 + (tid>>5);   // 0..4095
    int lane = tid&31;
    int b = col >> 9, d = col & (Dn-1);
    const float* base = g_tmp + (size_t)b*Tn*Dn + d;
    float sum = 0.f;
    for (int t=lane; t<Tn; t+=32){ float v = base[(size_t)t*Dn]; sum = fmaf(v,v,sum); }
#pragma unroll
    for (int o=16;o;o>>=1) sum += __shfl_xor_sync(0xffffffffu,sum,o);
    if (lane==0) g_invnorm[col] = 1.f/fmaxf(sqrtf(sum), 1e-12f);
}

// ---------------- scale tmp by invnorm -> fp16 ----------------
__global__ void k_scale_tmp(){
    int i = blockIdx.x*256 + threadIdx.x;   // word idx < ROWS*256
    int d0 = (i & 255)*2;
    int row = i >> 8;
    float2 v = *(float2*)&g_tmp[(size_t)row*Dn + d0];
    const float* inv = &g_invnorm[(row>>10)*Dn + d0];
    g_tmph[i] = packh2(v.x*inv[0], v.y*inv[1]);
}

// ---------------- LayerNorm over D, writes fp32 + fp16 shadow ----------------
__global__ __launch_bounds__(128) void k_ln(
    const float* __restrict__ lng, const float* __restrict__ lnb, int layer)
{
    __shared__ float shm[10];
    int r = blockIdx.x;
    int tid = threadIdx.x, lane = tid&31, wid = tid>>5;
    int d0 = tid*4;
    float4 v = *(const float4*)&g_xb[(size_t)r*Dn + d0];
    float sum = v.x+v.y+v.z+v.w;
    float sq  = v.x*v.x+v.y*v.y+v.z*v.z+v.w*v.w;
#pragma unroll
    for (int o=16;o;o>>=1){ sum += __shfl_xor_sync(0xffffffffu,sum,o); sq += __shfl_xor_sync(0xffffffffu,sq,o); }
    if (lane==0){ shm[wid]=sum; shm[4+wid]=sq; }
    __syncthreads();
    if (tid==0){ shm[8]=shm[0]+shm[1]+shm[2]+shm[3]; shm[9]=shm[4]+shm[5]+shm[6]+shm[7]; }
    __syncthreads();
    float mu  = shm[8]*(1.f/Dn);
    float var = shm[9]*(1.f/Dn) - mu*mu;
    float rstd = rsqrtf(fmaxf(var,0.f) + 1e-5f);
    float4 gg = *(const float4*)&lng[layer*Dn + d0];
    float4 bb = *(const float4*)&lnb[layer*Dn + d0];
    float y0 = (v.x-mu)*rstd*gg.x + bb.x;
    float y1 = (v.y-mu)*rstd*gg.y + bb.y;
    float y2 = (v.z-mu)*rstd*gg.z + bb.z;
    float y3 = (v.w-mu)*rstd*gg.w + bb.w;
    *(float4*)&g_xb[(size_t)r*Dn + d0] = make_float4(y0,y1,y2,y3);
    g_xbh[(size_t)r*256 + tid*2    ] = packh2(y0,y1);
    g_xbh[(size_t)r*256 + tid*2 + 1] = packh2(y2,y3);
}

// ---------------- launch ----------------
extern "C" void kernel_launch(void* const* d_in, const int* in_sizes, int n_in,
                              void* d_out, int out_size)
{
    const float* x     = (const float*)d_in[0];
    const float* Wq    = (const float*)d_in[1];
    const float* bq    = (const float*)d_in[2];
    const float* Wk    = (const float*)d_in[3];
    const float* bk    = (const float*)d_in[4];
    const float* Wv    = (const float*)d_in[5];
    const float* bv    = (const float*)d_in[6];
    const float* Wo    = (const float*)d_in[7];
    const float* bo    = (const float*)d_in[8];
    const float* alpha = (const float*)d_in[9];
    const float* ln_g  = (const float*)d_in[10];
    const float* ln_b  = (const float*)d_in[11];
    const float* adj_w = (const float*)d_in[12];
    const float* adj_b = (const float*)d_in[13];
    float* out = (float*)d_out;

    cudaFuncSetAttribute(k_flash, cudaFuncAttributeMaxDynamicSharedMemorySize, FLASH_SMEM);
    cudaFuncSetAttribute(k_proj,  cudaFuncAttributeMaxDynamicSharedMemorySize, PROJ_SMEM);

    k_prep_w<<<4096, 256>>>(Wq, Wk, Wv, Wo);
    k_transpose_in<<<ROWS, 256>>>(x);
    k_adj<<<1, Tn>>>(adj_w, adj_b);
    for (int l=0; l<2; l++){
        k_proj<<<dim3(8,64,3), 256, PROJ_SMEM>>>(bq,bk,bv,bo, 0, l);
        k_flash<<<dim3(16,64), 256, FLASH_SMEM>>>(alpha, l);
        k_colnorm<<<512, 256>>>();
        k_scale_tmp<<<ROWS, 256>>>();
        k_proj<<<dim3(8,64,1), 256, PROJ_SMEM>>>(bq,bk,bv,bo, 1, l);
        k_ln<<<ROWS, 128>>>(ln_g, ln_b, l);
    }
    k_transpose_out<<<(ROWS*Dn)/256, 256>>>(out);
}

// round 13
// speedup vs baseline: 2.6560x; 1.0323x over previous
#include <cuda_runtime.h>
#include <cuda_fp16.h>
#include <math.h>
#include <stdint.h>

#define Tn 1024
#define Bn 8
#define Dn 512
#define Hn 8
#define DHn 64
#define NPAIR 64           // Hn*Bn
#define ROWS (Bn*Tn)       // 8192
#define LOG2E 1.4426950408889634f

// ---------------- scratch (device globals: allocation-free) ----------------
__device__ float    g_xb [Bn*Tn*Dn];
__device__ uint32_t g_xbh[Bn*Tn*Dn/2];   // xb fp16 shadow, half2 pairs over d
__device__ uint32_t g_Qh [Bn*Tn*Dn/2];
__device__ uint32_t g_Kh [Bn*Tn*Dn/2];
__device__ uint32_t g_Vh [Bn*Tn*Dn/2];
__device__ uint32_t g_tmph[Bn*Tn*Dn/2];  // attention out fp16 (then scaled in place)
__device__ uint32_t g_Wp [8*512*256];    // [layer*4+z][k][n-pair] plain fp16
__device__ float    g_adj[Tn];

__device__ __forceinline__ float powtf(float v){
    return sqrtf(fmaxf(v,0.f)) - sqrtf(fmaxf(-v,0.f));
}

__device__ __forceinline__ uint32_t packh2(float a, float b){
    __half2 h = __floats2half2_rn(a, b);   // .x (low) = a
    return *(uint32_t*)&h;
}

__device__ __forceinline__ float ex2a(float x){
    float y; asm("ex2.approx.ftz.f32 %0, %1;" : "=f"(y) : "f"(x)); return y;
}

// mma.sync m16n8k16 fp16 in, fp32 accum, row.col
__device__ __forceinline__ void mma16(float* c, const uint32_t* a, const uint32_t* b){
    asm volatile(
        "mma.sync.aligned.m16n8k16.row.col.f32.f16.f16.f32 "
        "{%0,%1,%2,%3},{%4,%5,%6,%7},{%8,%9},{%0,%1,%2,%3};"
        : "+f"(c[0]),"+f"(c[1]),"+f"(c[2]),"+f"(c[3])
        : "r"(a[0]),"r"(a[1]),"r"(a[2]),"r"(a[3]),"r"(b[0]),"r"(b[1]));
}

__device__ __forceinline__ void cpa16(uint32_t dst, const void* src){
    asm volatile("cp.async.cg.shared.global [%0], [%1], 16;" :: "r"(dst), "l"(src));
}

__device__ __forceinline__ void ldsm4(uint32_t& r0, uint32_t& r1, uint32_t& r2, uint32_t& r3, uint32_t addr){
    asm volatile("ldmatrix.sync.aligned.m8n8.x4.shared.b16 {%0,%1,%2,%3}, [%4];"
        : "=r"(r0),"=r"(r1),"=r"(r2),"=r"(r3) : "r"(addr));
}

__device__ __forceinline__ void ldsm4t(uint32_t& r0, uint32_t& r1, uint32_t& r2, uint32_t& r3, uint32_t addr){
    asm volatile("ldmatrix.sync.aligned.m8n8.x4.trans.shared.b16 {%0,%1,%2,%3}, [%4];"
        : "=r"(r0),"=r"(r1),"=r"(r2),"=r"(r3) : "r"(addr));
}

// ---------------- weight prep: fp32 -> fp16 plain [k][n-pair], once ----------------
__global__ void k_prep_w(const float* __restrict__ Wq, const float* __restrict__ Wk,
                         const float* __restrict__ Wv, const float* __restrict__ Wo){
    int idx = blockIdx.x*256 + threadIdx.x;       // < 8*131072
    int m8  = idx >> 17;
    int rem = idx & 131071;
    int k   = rem >> 8;
    int np  = rem & 255;
    int l = m8 >> 2, z = m8 & 3;
    const float* W = (z==0?Wq:(z==1?Wk:(z==2?Wv:Wo))) + (size_t)l*Dn*Dn;
    g_Wp[idx] = packh2(W[(size_t)k*Dn + 2*np], W[(size_t)k*Dn + 2*np + 1]);
}

// ---------------- transpose in: x[T,B,D] -> g_xb[B,T,D] + fp16 shadow ----------------
__global__ void k_transpose_in(const float* __restrict__ x){
    int i = blockIdx.x*256 + threadIdx.x;         // word idx < ROWS*256
    int d0 = (i & 255)*2;
    int row = i >> 8;
    int b = row >> 10, t = row & 1023;
    const float* src = &x[(size_t)(t*Bn + b)*Dn + d0];
    float v0 = src[0], v1 = src[1];
    float2* dst = (float2*)&g_xb[(size_t)row*Dn + d0];
    *dst = make_float2(v0, v1);
    g_xbh[i] = packh2(v0, v1);
}

__global__ void k_transpose_out(float* __restrict__ out){
    int idx = blockIdx.x*256 + threadIdx.x;          // [T,B,D] linear
    int d = idx & (Dn-1);
    int b = (idx >> 9) & (Bn-1);
    int t = idx >> 12;
    out[idx] = g_xb[((b<<10) + t)*Dn + d];
}

// ---------------- adj table ----------------
__global__ void k_adj(const float* __restrict__ aw, const float* __restrict__ ab){
    int i = threadIdx.x;
    float dist = (float)i;
    g_adj[i] = expf(-fabsf(aw[0]*dist*dist - ab[0]));
}

// ================= cp.async fp16 GEMM, ldmatrix fragments =================
// mode 0: C = xbh @ W[z] + b[z] -> g_{Q,K,V}h (fp16), grid z = 3
// mode 1: g_xb += tmph @ Wo + bo (fp32 residual), grid z = 1
// M=8192, N=512, K=512; block 128x64, BK=32, 2-stage cp.async pipeline.
#define PA_ST 4608                 // A stage: 128*36 words
#define PB_ST 1152                 // B stage: 32 k-rows * 36 words (64 n halves + pad)
#define PROJ_SMEM ((2*PA_ST + 2*PB_ST)*4)   // 46080 B

__global__ __launch_bounds__(256,2) void k_proj(
    const float* __restrict__ bq, const float* __restrict__ bk,
    const float* __restrict__ bv, const float* __restrict__ bo,
    int mode, int layer)
{
    extern __shared__ uint32_t shp[];
    const int tid = threadIdx.x;
    const int z   = (mode==0) ? blockIdx.z : 3;
    const uint32_t* Bsrc = g_Wp + (size_t)(layer*4 + z)*131072;   // [k][n-pair]
    const uint32_t* Asrc = (mode==0) ? g_xbh : g_tmph;
    const float* bias = ((mode==0) ? (z==0?bq:(z==1?bk:bv)) : bo) + layer*Dn;
    uint32_t* Ch = (z==0? g_Qh : (z==1? g_Kh : g_Vh));

    const int m0 = blockIdx.y*128, n0 = blockIdx.x*64;
    const int wid = tid>>5, lane = tid&31, g = lane>>2, t = lane&3;
    const int m_off = (wid>>1)*32, n_off = (wid&1)*32;
    const uint32_t sbase = (uint32_t)__cvta_generic_to_shared(shp);

    float c[2][4][4] = {};

    auto issue = [&](int kt, int buf){
        const uint32_t* Ag = Asrc + (size_t)m0*256 + kt*16;   // 16 words = 32 k halves
#pragma unroll
        for (int i2=0;i2<2;i2++){
            int cc = tid + i2*256;                 // 512 chunks: 128 rows x 4
            int r = cc>>2, ch = cc&3;
            cpa16(sbase + (buf*PA_ST + r*36 + ch*4)*4, Ag + (size_t)r*256 + ch*4);
        }
        {   // B: 32 k-rows x 32 n-pair words = 8 chunks/row, 256 chunks
            int r = tid>>3, ch = tid&7;
            cpa16(sbase + (2*PA_ST + buf*PB_ST + r*36 + ch*4)*4,
                  Bsrc + (size_t)(kt*32 + r)*256 + (n0>>1) + ch*4);
        }
        asm volatile("cp.async.commit_group;");
    };

    // ldmatrix per-thread offsets (words)
    const int rowin = lane&7;
    const uint32_t a_off = (uint32_t)((m_off + ((lane>>3)&1)*8 + rowin)*36 + (lane>>4)*4);
    const uint32_t b_off = (uint32_t)((((lane>>3)&1)*8 + rowin)*36 + (n_off>>1) + (lane>>4)*4);

    issue(0, 0);
    for (int kt=0; kt<16; kt++){
        if (kt < 15) issue(kt+1, (kt+1)&1);
        if (kt < 15) asm volatile("cp.async.wait_group 1;");
        else         asm volatile("cp.async.wait_group 0;");
        __syncthreads();
        const uint32_t abase = sbase + ((kt&1)*PA_ST)*4;
        const uint32_t bbase = sbase + (2*PA_ST + (kt&1)*PB_ST)*4;
#pragma unroll
        for (int j=0; j<2; j++){
            uint32_t a[2][4], b[4][2];
#pragma unroll
            for (int mi=0;mi<2;mi++)
                ldsm4(a[mi][0],a[mi][1],a[mi][2],a[mi][3], abase + (a_off + mi*16*36 + j*8)*4);
            {
                uint32_t b0,b1,b2,b3;
                ldsm4t(b0,b1,b2,b3, bbase + (b_off + j*16*36)*4);
                b[0][0]=b0; b[0][1]=b1; b[1][0]=b2; b[1][1]=b3;
                ldsm4t(b0,b1,b2,b3, bbase + (b_off + j*16*36 + 8)*4);
                b[2][0]=b0; b[2][1]=b1; b[3][0]=b2; b[3][1]=b3;
            }
#pragma unroll
            for (int mi=0;mi<2;mi++)
#pragma unroll
                for (int ni=0;ni<4;ni++) mma16(c[mi][ni], a[mi], b[ni]);
        }
        __syncthreads();
    }

#pragma unroll
    for (int mi=0;mi<2;mi++){
#pragma unroll
        for (int ni=0;ni<4;ni++){
            int row = m0 + m_off + mi*16 + g;
            int col = n0 + n_off + ni*8 + 2*t;
            float b0 = bias[col], b1 = bias[col+1];
            if (mode==0){
                int w = col>>1;
                Ch[(size_t)row*256 + w]     = packh2(c[mi][ni][0]+b0, c[mi][ni][1]+b1);
                Ch[(size_t)(row+8)*256 + w] = packh2(c[mi][ni][2]+b0, c[mi][ni][3]+b1);
            } else {
                float2 r0 = *(float2*)&g_xb[(size_t)row*Dn + col];
                float2 r1 = *(float2*)&g_xb[(size_t)(row+8)*Dn + col];
                float2 v0 = {c[mi][ni][0]+b0+r0.x, c[mi][ni][1]+b1+r0.y};
                float2 v1 = {c[mi][ni][2]+b0+r1.x, c[mi][ni][3]+b1+r1.y};
                *(float2*)&g_xb[(size_t)row*Dn + col]     = v0;
                *(float2*)&g_xb[(size_t)(row+8)*Dn + col] = v1;
            }
        }
    }
}

// ================= flash attention (round-11 core, fp16 output) =================
#define K_ST 4608                  // 128 rows * 36
#define V_ST 4608
#define SH_Q   0                   // 64*36 = 2304
#define SH_K   2304
#define SH_V   (SH_K + 2*K_ST)     // 11520
#define SH_ADJ (SH_V + 2*V_ST)     // 20736
#define SH_SB  (SH_ADJ + Tn)       // 21760
#define FLASH_SMEM ((SH_SB + 256)*4)   // 88064 B
#define OG_STRIDE 68

__global__ __launch_bounds__(256,2) void k_flash(const float* __restrict__ alpha, int layer){
    extern __shared__ uint32_t sh[];
    uint32_t (*Qh2)[36] = (uint32_t(*)[36])(sh + SH_Q);
    float* adj_s = (float*)(sh + SH_ADJ);     // log2-scaled adj
    float* sb    = (float*)(sh + SH_SB);
    float (*Og)[OG_STRIDE] = (float(*)[OG_STRIDE])(sh + SH_K);

    const int tid = threadIdx.x;
    const int p  = blockIdx.y;
    const int q0 = blockIdx.x*64;
    const uint4* Qp4 = (const uint4*)(g_Qh + ((size_t)p<<15));
    const uint32_t* Kpw = g_Kh + ((size_t)p<<15);
    const uint32_t* Vpw = g_Vh + ((size_t)p<<15);
    const uint32_t sbase = (uint32_t)__cvta_generic_to_shared(sh);

    for (int i=tid;i<Tn;i+=256) adj_s[i] = g_adj[i]*LOG2E;
#pragma unroll
    for (int i=0;i<2;i++){
        int c = tid + i*256;
        *(uint4*)&Qh2[c>>3][(c&7)<<2] = Qp4[(size_t)(q0 + (c>>3))*8 + (c&7)];
    }

    auto issue = [&](int kb, int buf){
#pragma unroll
        for (int i2=0;i2<4;i2++){
            int cc = tid + i2*256;
            int r = cc>>3, ch = cc&7;
            cpa16(sbase + (SH_K + buf*K_ST + r*36 + ch*4)*4, Kpw + (size_t)(kb+r)*32 + ch*4);
        }
#pragma unroll
        for (int i2=0;i2<4;i2++){
            int cc = tid + i2*256;
            int r = cc>>3, ch = cc&7;
            cpa16(sbase + (SH_V + buf*V_ST + r*36 + ch*4)*4, Vpw + (size_t)(kb+r)*32 + ch*4);
        }
        asm volatile("cp.async.commit_group;");
    };

    issue(0, 0);
    __syncthreads();

    const int wid = tid>>5, lane = tid&31, g = lane>>2, t = lane&3;
    const int rg = wid>>1, h = wid&1;
    const int r0 = rg*16;
    const int qlo = q0 + r0 + g;
    const int sidx4 = ((rg*2+h)*8 + g)*4;
    const int pidx4 = ((rg*2+(h^1))*8 + g)*4;
    const float scale2 = 0.04419417382415922f * LOG2E;

    uint32_t qa[4][4];
#pragma unroll
    for (int ks=0;ks<4;ks++){
        qa[ks][0]=Qh2[r0+g  ][ks*8+t];   qa[ks][1]=Qh2[r0+g+8][ks*8+t];
        qa[ks][2]=Qh2[r0+g  ][ks*8+t+4]; qa[ks][3]=Qh2[r0+g+8][ks*8+t+4];
    }

    const int rowin = lane&7;
    const uint32_t k_off0 = (uint32_t)((h*64 + ((lane>>4)&1)*8 + rowin)*36 + ((lane>>3)&1)*4);
    const uint32_t v_off0 = (uint32_t)((h*64 + ((lane>>3)&1)*8 + rowin)*36 + (lane>>4)*4);

    float m_lo=-1e30f, m_hi=-1e30f, l_lo=0.f, l_hi=0.f;
    float o[8][4] = {};

    for (int kbi=0; kbi<8; kbi++){
        int kb = kbi*128;
        if (kbi < 7) issue(kb+128, (kbi+1)&1);
        if (kbi < 7) asm volatile("cp.async.wait_group 1;");
        else         asm volatile("cp.async.wait_group 0;");
        __syncthreads();
        const uint32_t kstage = sbase + (SH_K + (kbi&1)*K_ST)*4;
        const uint32_t vstage = sbase + (SH_V + (kbi&1)*V_ST)*4;

        float c[8][4] = {};
#pragma unroll
        for (int ks=0; ks<4; ks++){
#pragma unroll
            for (int m=0; m<4; m++){
                uint32_t b0,b1,b2,b3;
                ldsm4(b0,b1,b2,b3, kstage + (k_off0 + m*576 + ks*8)*4);
                uint32_t bb[2];
                bb[0]=b0; bb[1]=b1; mma16(c[2*m  ], qa[ks], bb);
                bb[0]=b2; bb[1]=b3; mma16(c[2*m+1], qa[ks], bb);
            }
        }
#pragma unroll
        for (int ni=0;ni<8;ni++){
            int kk = kb + h*64 + ni*8 + 2*t;
            c[ni][0] = fmaf(c[ni][0], scale2, adj_s[abs(qlo   - kk    )]);
            c[ni][1] = fmaf(c[ni][1], scale2, adj_s[abs(qlo   - kk - 1)]);
            c[ni][2] = fmaf(c[ni][2], scale2, adj_s[abs(qlo+8 - kk    )]);
            c[ni][3] = fmaf(c[ni][3], scale2, adj_s[abs(qlo+8 - kk - 1)]);
        }
        float rmx_lo=-1e30f, rmx_hi=-1e30f;
#pragma unroll
        for (int ni=0;ni<8;ni++){
            rmx_lo = fmaxf(rmx_lo, fmaxf(c[ni][0], c[ni][1]));
            rmx_hi = fmaxf(rmx_hi, fmaxf(c[ni][2], c[ni][3]));
        }
        rmx_lo = fmaxf(rmx_lo, __shfl_xor_sync(0xffffffffu, rmx_lo, 1));
        rmx_lo = fmaxf(rmx_lo, __shfl_xor_sync(0xffffffffu, rmx_lo, 2));
        rmx_hi = fmaxf(rmx_hi, __shfl_xor_sync(0xffffffffu, rmx_hi, 1));
        rmx_hi = fmaxf(rmx_hi, __shfl_xor_sync(0xffffffffu, rmx_hi, 2));
        float mn_lo = fmaxf(m_lo, rmx_lo), mn_hi = fmaxf(m_hi, rmx_hi);
        float fold_lo = ex2a(m_lo - mn_lo),  fold_hi = ex2a(m_hi - mn_hi);
        m_lo = mn_lo; m_hi = mn_hi;
        float rs_lo=0.f, rs_hi=0.f;
#pragma unroll
        for (int ni=0;ni<8;ni++){
            c[ni][0]=ex2a(c[ni][0]-mn_lo); c[ni][1]=ex2a(c[ni][1]-mn_lo);
            c[ni][2]=ex2a(c[ni][2]-mn_hi); c[ni][3]=ex2a(c[ni][3]-mn_hi);
            rs_lo += c[ni][0]+c[ni][1];
            rs_hi += c[ni][2]+c[ni][3];
        }
        rs_lo += __shfl_xor_sync(0xffffffffu, rs_lo, 1);
        rs_lo += __shfl_xor_sync(0xffffffffu, rs_lo, 2);
        rs_hi += __shfl_xor_sync(0xffffffffu, rs_hi, 1);
        rs_hi += __shfl_xor_sync(0xffffffffu, rs_hi, 2);
        l_lo = l_lo*fold_lo + rs_lo;
        l_hi = l_hi*fold_hi + rs_hi;
#pragma unroll
        for (int ni=0;ni<8;ni++){
            o[ni][0]*=fold_lo; o[ni][1]*=fold_lo; o[ni][2]*=fold_hi; o[ni][3]*=fold_hi;
        }
#pragma unroll
        for (int j=0; j<4; j++){
            uint32_t a[4];
            a[0] = packh2(c[2*j  ][0], c[2*j  ][1]);
            a[1] = packh2(c[2*j  ][2], c[2*j  ][3]);
            a[2] = packh2(c[2*j+1][0], c[2*j+1][1]);
            a[3] = packh2(c[2*j+1][2], c[2*j+1][3]);
#pragma unroll
            for (int m=0; m<4; m++){
                uint32_t b0,b1,b2,b3;
                ldsm4t(b0,b1,b2,b3, vstage + (v_off0 + j*576 + m*8)*4);
                uint32_t bb[2];
                bb[0]=b0; bb[1]=b1; mma16(o[2*m  ], a, bb);
                bb[0]=b2; bb[1]=b3; mma16(o[2*m+1], a, bb);
            }
        }
        __syncthreads();
    }

    // ---- single cross-warp merge of (m, l) ----
    if ((lane&3)==0) *(float4*)&sb[sidx4] = make_float4(m_lo, m_hi, l_lo, l_hi);
    asm volatile("bar.sync %0, 64;" :: "r"(rg+1) : "memory");
    float4 pr = *(float4*)&sb[pidx4];
    float M_lo = fmaxf(m_lo, pr.x), M_hi = fmaxf(m_hi, pr.y);
    float eo_lo = ex2a(m_lo - M_lo), ep_lo = ex2a(pr.x - M_lo);
    float eo_hi = ex2a(m_hi - M_hi), ep_hi = ex2a(pr.y - M_hi);
    float w_lo = eo_lo / fmaf(l_lo, eo_lo, pr.z*ep_lo);
    float w_hi = eo_hi / fmaf(l_hi, eo_hi, pr.w*ep_hi);

    if (h==0){
#pragma unroll
        for (int ni=0;ni<8;ni++){
            Og[r0+g  ][ni*8+2*t  ] = o[ni][0]*w_lo;
            Og[r0+g  ][ni*8+2*t+1] = o[ni][1]*w_lo;
            Og[r0+g+8][ni*8+2*t  ] = o[ni][2]*w_hi;
            Og[r0+g+8][ni*8+2*t+1] = o[ni][3]*w_hi;
        }
    }
    __syncthreads();
    if (h==1){
#pragma unroll
        for (int ni=0;ni<8;ni++){
            Og[r0+g  ][ni*8+2*t  ] += o[ni][0]*w_lo;
            Og[r0+g  ][ni*8+2*t+1] += o[ni][1]*w_lo;
            Og[r0+g+8][ni*8+2*t  ] += o[ni][2]*w_hi;
            Og[r0+g+8][ni*8+2*t+1] += o[ni][3]*w_hi;
        }
    }
    __syncthreads();

    // ---- local-window epilogue (log2 domain), fp16 output ----
    const float aa = 1.f/(1.f+__expf(-alpha[layer]));
    const int rowl = wid*8 + (lane>>2);
    const int q = q0 + rowl;
    const int d0 = (lane&3)*16;
    const int lo = (q-4>0)? q-4 : 0;
    const int hi = (q+4<Tn-1)? q+4 : Tn-1;
    const int nw = hi-lo+1;

    float s[9];
    for (int j=0;j<nw;j++){
        float dot = 0.f;
#pragma unroll
        for (int i=0;i<8;i++){
            __half2 q2 = *(__half2*)&Qh2[rowl][(d0>>1)+i];
            __half2 k2 = *(__half2*)&Kpw[(size_t)(lo+j)*(DHn/2) + (d0>>1)+i];
            dot = fmaf(__half2float(q2.x), __half2float(k2.x), dot);
            dot = fmaf(__half2float(q2.y), __half2float(k2.y), dot);
        }
        dot += __shfl_xor_sync(0xffffffffu, dot, 1);
        dot += __shfl_xor_sync(0xffffffffu, dot, 2);
        s[j] = fmaf(dot, scale2, adj_s[abs(q-(lo+j))]);
    }
    float lm = -1e30f;
    for (int j=0;j<nw;j++) lm = fmaxf(lm, s[j]);
    float ls = 0.f;
    for (int j=0;j<nw;j++){ s[j] = ex2a(s[j]-lm); ls += s[j]; }
    float linv = (1.f-aa)/ls;

    float acc[16];
#pragma unroll
    for (int i=0;i<16;i++) acc[i] = aa*Og[rowl][d0+i];
    for (int j=0;j<nw;j++){
        float w = s[j]*linv;
#pragma unroll
        for (int i=0;i<8;i++){
            __half2 v2 = *(__half2*)&Vpw[(size_t)(lo+j)*(DHn/2) + (d0>>1)+i];
            acc[2*i  ] = fmaf(w, __half2float(v2.x), acc[2*i  ]);
            acc[2*i+1] = fmaf(w, __half2float(v2.y), acc[2*i+1]);
        }
    }
    uint32_t* outw = g_tmph + ((size_t)p<<15) + (size_t)q*32 + (d0>>1);
    uint32_t w8[8];
#pragma unroll
    for (int i=0;i<8;i++) w8[i] = packh2(powtf(acc[2*i]), powtf(acc[2*i+1]));
    *(uint4*)&outw[0] = *(uint4*)&w8[0];
    *(uint4*)&outw[4] = *(uint4*)&w8[4];
}

// ---------------- fused column L2 norm + in-place scale (fp16) ----------------
// warp per word-column (b, wc): 1024 values over seq, kept in regs.
__global__ __launch_bounds__(256) void k_colnorm_scale(){
    int wid = threadIdx.x>>5, lane = threadIdx.x&31;
    int w = blockIdx.x*8 + wid;          // 0..2047
    int b = w >> 8, wc = w & 255;
    uint32_t* base = g_tmph + ((size_t)b<<18) + wc;   // b*1024*256 + wc
    uint32_t vals[32];
    float sq0=0.f, sq1=0.f;
#pragma unroll
    for (int j=0;j<32;j++){
        uint32_t v = base[(size_t)(j*32+lane)<<8];
        vals[j]=v;
        __half2 hh = *(__half2*)&v;
        float a=__half2float(hh.x), bb=__half2float(hh.y);
        sq0 = fmaf(a,a,sq0); sq1 = fmaf(bb,bb,sq1);
    }
#pragma unroll
    for (int o=16;o;o>>=1){ sq0 += __shfl_xor_sync(0xffffffffu,sq0,o); sq1 += __shfl_xor_sync(0xffffffffu,sq1,o); }
    float inv0 = 1.f/fmaxf(sqrtf(sq0), 1e-12f);
    float inv1 = 1.f/fmaxf(sqrtf(sq1), 1e-12f);
#pragma unroll
    for (int j=0;j<32;j++){
        __half2 hh = *(__half2*)&vals[j];
        base[(size_t)(j*32+lane)<<8] = packh2(__half2float(hh.x)*inv0, __half2float(hh.y)*inv1);
    }
}

// ---------------- LayerNorm over D, writes fp32 + fp16 shadow ----------------
__global__ __launch_bounds__(128) void k_ln(
    const float* __restrict__ lng, const float* __restrict__ lnb, int layer)
{
    __shared__ float shm[10];
    int r = blockIdx.x;
    int tid = threadIdx.x, lane = tid&31, wid = tid>>5;
    int d0 = tid*4;
    float4 v = *(const float4*)&g_xb[(size_t)r*Dn + d0];
    float sum = v.x+v.y+v.z+v.w;
    float sq  = v.x*v.x+v.y*v.y+v.z*v.z+v.w*v.w;
#pragma unroll
    for (int o=16;o;o>>=1){ sum += __shfl_xor_sync(0xffffffffu,sum,o); sq += __shfl_xor_sync(0xffffffffu,sq,o); }
    if (lane==0){ shm[wid]=sum; shm[4+wid]=sq; }
    __syncthreads();
    if (tid==0){ shm[8]=shm[0]+shm[1]+shm[2]+shm[3]; shm[9]=shm[4]+shm[5]+shm[6]+shm[7]; }
    __syncthreads();
    float mu  = shm[8]*(1.f/Dn);
    float var = shm[9]*(1.f/Dn) - mu*mu;
    float rstd = rsqrtf(fmaxf(var,0.f) + 1e-5f);
    float4 gg = *(const float4*)&lng[layer*Dn + d0];
    float4 bb = *(const float4*)&lnb[layer*Dn + d0];
    float y0 = (v.x-mu)*rstd*gg.x + bb.x;
    float y1 = (v.y-mu)*rstd*gg.y + bb.y;
    float y2 = (v.z-mu)*rstd*gg.z + bb.z;
    float y3 = (v.w-mu)*rstd*gg.w + bb.w;
    *(float4*)&g_xb[(size_t)r*Dn + d0] = make_float4(y0,y1,y2,y3);
    g_xbh[(size_t)r*256 + tid*2    ] = packh2(y0,y1);
    g_xbh[(size_t)r*256 + tid*2 + 1] = packh2(y2,y3);
}

// ---------------- launch ----------------
extern "C" void kernel_launch(void* const* d_in, const int* in_sizes, int n_in,
                              void* d_out, int out_size)
{
    const float* x     = (const float*)d_in[0];
    const float* Wq    = (const float*)d_in[1];
    const float* bq    = (const float*)d_in[2];
    const float* Wk    = (const float*)d_in[3];
    const float* bk    = (const float*)d_in[4];
    const float* Wv    = (const float*)d_in[5];
    const float* bv    = (const float*)d_in[6];
    const float* Wo    = (const float*)d_in[7];
    const float* bo    = (const float*)d_in[8];
    const float* alpha = (const float*)d_in[9];
    const float* ln_g  = (const float*)d_in[10];
    const float* ln_b  = (const float*)d_in[11];
    const float* adj_w = (const float*)d_in[12];
    const float* adj_b = (const float*)d_in[13];
    float* out = (float*)d_out;

    cudaFuncSetAttribute(k_flash, cudaFuncAttributeMaxDynamicSharedMemorySize, FLASH_SMEM);
    cudaFuncSetAttribute(k_proj,  cudaFuncAttributeMaxDynamicSharedMemorySize, PROJ_SMEM);

    k_prep_w<<<4096, 256>>>(Wq, Wk, Wv, Wo);
    k_transpose_in<<<ROWS, 256>>>(x);
    k_adj<<<1, Tn>>>(adj_w, adj_b);
    for (int l=0; l<2; l++){
        k_proj<<<dim3(8,64,3), 256, PROJ_SMEM>>>(bq,bk,bv,bo, 0, l);
        k_flash<<<dim3(16,64), 256, FLASH_SMEM>>>(alpha, l);
        k_colnorm_scale<<<256, 256>>>();
        k_proj<<<dim3(8,64,1), 256, PROJ_SMEM>>>(bq,bk,bv,bo, 1, l);
        k_ln<<<ROWS, 128>>>(ln_g, ln_b, l);
    }
    k_transpose_out<<<(ROWS*Dn)/256, 256>>>(out);
}

// round 14
// speedup vs baseline: 2.7366x; 1.0304x over previous
#include <cuda_runtime.h>
#include <cuda_fp16.h>
#include <math.h>
#include <stdint.h>

#define Tn 1024
#define Bn 8
#define Dn 512
#define Hn 8
#define DHn 64
#define NPAIR 64           // Hn*Bn
#define ROWS (Bn*Tn)       // 8192
#define LOG2E 1.4426950408889634f

// ---------------- scratch (device globals: allocation-free) ----------------
__device__ float    g_xb [Bn*Tn*Dn];
__device__ uint32_t g_xbh[Bn*Tn*Dn/2];   // xb fp16 shadow, half2 pairs over d
__device__ uint32_t g_Qh [Bn*Tn*Dn/2];
__device__ uint32_t g_Kh [Bn*Tn*Dn/2];
__device__ uint32_t g_Vh [Bn*Tn*Dn/2];
__device__ uint32_t g_tmph[Bn*Tn*Dn/2];  // attention out fp16 (then scaled in place)
__device__ uint32_t g_Wp [8*512*256];    // [layer*4+z][k][n-pair] plain fp16
__device__ float    g_adj[Tn];

__device__ __forceinline__ float powtf(float v){
    return sqrtf(fmaxf(v,0.f)) - sqrtf(fmaxf(-v,0.f));
}

__device__ __forceinline__ uint32_t packh2(float a, float b){
    __half2 h = __floats2half2_rn(a, b);   // .x (low) = a
    return *(uint32_t*)&h;
}

__device__ __forceinline__ float ex2a(float x){
    float y; asm("ex2.approx.ftz.f32 %0, %1;" : "=f"(y) : "f"(x)); return y;
}

// mma.sync m16n8k16 fp16 in, fp32 accum, row.col
__device__ __forceinline__ void mma16(float* c, const uint32_t* a, const uint32_t* b){
    asm volatile(
        "mma.sync.aligned.m16n8k16.row.col.f32.f16.f16.f32 "
        "{%0,%1,%2,%3},{%4,%5,%6,%7},{%8,%9},{%0,%1,%2,%3};"
        : "+f"(c[0]),"+f"(c[1]),"+f"(c[2]),"+f"(c[3])
        : "r"(a[0]),"r"(a[1]),"r"(a[2]),"r"(a[3]),"r"(b[0]),"r"(b[1]));
}

__device__ __forceinline__ void cpa16(uint32_t dst, const void* src){
    asm volatile("cp.async.cg.shared.global [%0], [%1], 16;" :: "r"(dst), "l"(src));
}

__device__ __forceinline__ void ldsm4(uint32_t& r0, uint32_t& r1, uint32_t& r2, uint32_t& r3, uint32_t addr){
    asm volatile("ldmatrix.sync.aligned.m8n8.x4.shared.b16 {%0,%1,%2,%3}, [%4];"
        : "=r"(r0),"=r"(r1),"=r"(r2),"=r"(r3) : "r"(addr));
}

__device__ __forceinline__ void ldsm4t(uint32_t& r0, uint32_t& r1, uint32_t& r2, uint32_t& r3, uint32_t addr){
    asm volatile("ldmatrix.sync.aligned.m8n8.x4.trans.shared.b16 {%0,%1,%2,%3}, [%4];"
        : "=r"(r0),"=r"(r1),"=r"(r2),"=r"(r3) : "r"(addr));
}

// ---------------- weight prep: fp32 -> fp16 plain [k][n-pair], once ----------------
__global__ void k_prep_w(const float* __restrict__ Wq, const float* __restrict__ Wk,
                         const float* __restrict__ Wv, const float* __restrict__ Wo){
    int idx = blockIdx.x*256 + threadIdx.x;       // < 8*131072
    int m8  = idx >> 17;
    int rem = idx & 131071;
    int k   = rem >> 8;
    int np  = rem & 255;
    int l = m8 >> 2, z = m8 & 3;
    const float* W = (z==0?Wq:(z==1?Wk:(z==2?Wv:Wo))) + (size_t)l*Dn*Dn;
    g_Wp[idx] = packh2(W[(size_t)k*Dn + 2*np], W[(size_t)k*Dn + 2*np + 1]);
}

// ---------------- transpose in: x[T,B,D] -> g_xb[B,T,D] + fp16 shadow ----------------
__global__ void k_transpose_in(const float* __restrict__ x){
    int i = blockIdx.x*256 + threadIdx.x;         // word idx < ROWS*256
    int d0 = (i & 255)*2;
    int row = i >> 8;
    int b = row >> 10, t = row & 1023;
    const float* src = &x[(size_t)(t*Bn + b)*Dn + d0];
    float v0 = src[0], v1 = src[1];
    float2* dst = (float2*)&g_xb[(size_t)row*Dn + d0];
    *dst = make_float2(v0, v1);
    g_xbh[i] = packh2(v0, v1);
}

__global__ void k_transpose_out(float* __restrict__ out){
    int idx = blockIdx.x*256 + threadIdx.x;          // [T,B,D] linear
    int d = idx & (Dn-1);
    int b = (idx >> 9) & (Bn-1);
    int t = idx >> 12;
    out[idx] = g_xb[((b<<10) + t)*Dn + d];
}

// ---------------- adj table ----------------
__global__ void k_adj(const float* __restrict__ aw, const float* __restrict__ ab){
    int i = threadIdx.x;
    float dist = (float)i;
    g_adj[i] = expf(-fabsf(aw[0]*dist*dist - ab[0]));
}

// ================= 512-thread 128x128 fp16 GEMM, 3-stage cp.async =================
// mode 0: C = xbh @ W[z] + b[z] -> g_{Q,K,V}h (fp16), grid z = 3
// mode 1: g_xb += tmph @ Wo + bo (fp32 residual), grid z = 1
// M=8192, N=512, K=512; block 128x128, BK=32, 16 warps 4(m)x4(n), warp 32x32.
#define PA_ST 4608                 // A stage: 128 rows * 36 words
#define PB_ST 2176                 // B stage: 32 k-rows * 68 words (64 n-pairs + pad)
#define PROJ_SMEM ((3*PA_ST + 3*PB_ST)*4)   // 81408 B

__global__ __launch_bounds__(512,1) void k_proj(
    const float* __restrict__ bq, const float* __restrict__ bk,
    const float* __restrict__ bv, const float* __restrict__ bo,
    int mode, int layer)
{
    extern __shared__ uint32_t shp[];
    const int tid = threadIdx.x;
    const int z   = (mode==0) ? blockIdx.z : 3;
    const uint32_t* Bsrc = g_Wp + (size_t)(layer*4 + z)*131072;   // [k][n-pair]
    const uint32_t* Asrc = (mode==0) ? g_xbh : g_tmph;
    const float* bias = ((mode==0) ? (z==0?bq:(z==1?bk:bv)) : bo) + layer*Dn;
    uint32_t* Ch = (z==0? g_Qh : (z==1? g_Kh : g_Vh));

    const int m0 = blockIdx.y*128, n0 = blockIdx.x*128;
    const int wid = tid>>5, lane = tid&31, g = lane>>2, t = lane&3;
    const int m_off = (wid&3)*32, n_off = (wid>>2)*32;
    const uint32_t sbase = (uint32_t)__cvta_generic_to_shared(shp);

    float c[2][4][4] = {};

    auto issue = [&](int kt, int buf){
        {   // A: 128 rows x 4 chunks of 4 words (16 words/row for BK=32)
            int r = tid>>2, ch = tid&3;
            cpa16(sbase + (buf*PA_ST + r*36 + ch*4)*4,
                  Asrc + (size_t)(m0+r)*256 + kt*16 + ch*4);
        }
        {   // B: 32 k-rows x 16 chunks of 4 words (64 n-pair words/row)
            int r = tid>>4, ch = tid&15;
            cpa16(sbase + (3*PA_ST + buf*PB_ST + r*68 + ch*4)*4,
                  Bsrc + (size_t)(kt*32 + r)*256 + (n0>>1) + ch*4);
        }
        asm volatile("cp.async.commit_group;");
    };

    // ldmatrix per-thread offsets (words)
    const int rowin = lane&7;
    const uint32_t a_off = (uint32_t)((m_off + ((lane>>3)&1)*8 + rowin)*36 + (lane>>4)*4);
    const uint32_t b_off = (uint32_t)((((lane>>3)&1)*8 + rowin)*68 + (n_off>>1) + (lane>>4)*4);

    issue(0, 0);
    issue(1, 1);
    for (int kt=0; kt<16; kt++){
        if (kt < 15) asm volatile("cp.async.wait_group 1;");
        else         asm volatile("cp.async.wait_group 0;");
        __syncthreads();
        if (kt+2 <= 15) issue(kt+2, (kt+2)%3);
        const uint32_t abase = sbase + ((kt%3)*PA_ST)*4;
        const uint32_t bbase = sbase + (3*PA_ST + (kt%3)*PB_ST)*4;
#pragma unroll
        for (int j=0; j<2; j++){
            uint32_t a[2][4], b[4][2];
#pragma unroll
            for (int mi=0;mi<2;mi++)
                ldsm4(a[mi][0],a[mi][1],a[mi][2],a[mi][3], abase + (a_off + mi*16*36 + j*8)*4);
#pragma unroll
            for (int u=0;u<2;u++){
                uint32_t b0,b1,b2,b3;
                ldsm4t(b0,b1,b2,b3, bbase + (b_off + j*16*68 + u*8)*4);
                b[2*u][0]=b0; b[2*u][1]=b1; b[2*u+1][0]=b2; b[2*u+1][1]=b3;
            }
#pragma unroll
            for (int mi=0;mi<2;mi++)
#pragma unroll
                for (int ni=0;ni<4;ni++) mma16(c[mi][ni], a[mi], b[ni]);
        }
    }

#pragma unroll
    for (int mi=0;mi<2;mi++){
#pragma unroll
        for (int ni=0;ni<4;ni++){
            int row = m0 + m_off + mi*16 + g;
            int col = n0 + n_off + ni*8 + 2*t;
            float b0 = bias[col], b1 = bias[col+1];
            if (mode==0){
                int w = col>>1;
                Ch[(size_t)row*256 + w]     = packh2(c[mi][ni][0]+b0, c[mi][ni][1]+b1);
                Ch[(size_t)(row+8)*256 + w] = packh2(c[mi][ni][2]+b0, c[mi][ni][3]+b1);
            } else {
                float2 r0 = *(float2*)&g_xb[(size_t)row*Dn + col];
                float2 r1 = *(float2*)&g_xb[(size_t)(row+8)*Dn + col];
                float2 v0 = {c[mi][ni][0]+b0+r0.x, c[mi][ni][1]+b1+r0.y};
                float2 v1 = {c[mi][ni][2]+b0+r1.x, c[mi][ni][3]+b1+r1.y};
                *(float2*)&g_xb[(size_t)row*Dn + col]     = v0;
                *(float2*)&g_xb[(size_t)(row+8)*Dn + col] = v1;
            }
        }
    }
}

// ================= flash attention (round-13, unchanged) =================
#define K_ST 4608                  // 128 rows * 36
#define V_ST 4608
#define SH_Q   0                   // 64*36 = 2304
#define SH_K   2304
#define SH_V   (SH_K + 2*K_ST)     // 11520
#define SH_ADJ (SH_V + 2*V_ST)     // 20736
#define SH_SB  (SH_ADJ + Tn)       // 21760
#define FLASH_SMEM ((SH_SB + 256)*4)   // 88064 B
#define OG_STRIDE 68

__global__ __launch_bounds__(256,2) void k_flash(const float* __restrict__ alpha, int layer){
    extern __shared__ uint32_t sh[];
    uint32_t (*Qh2)[36] = (uint32_t(*)[36])(sh + SH_Q);
    float* adj_s = (float*)(sh + SH_ADJ);     // log2-scaled adj
    float* sb    = (float*)(sh + SH_SB);
    float (*Og)[OG_STRIDE] = (float(*)[OG_STRIDE])(sh + SH_K);

    const int tid = threadIdx.x;
    const int p  = blockIdx.y;
    const int q0 = blockIdx.x*64;
    const uint4* Qp4 = (const uint4*)(g_Qh + ((size_t)p<<15));
    const uint32_t* Kpw = g_Kh + ((size_t)p<<15);
    const uint32_t* Vpw = g_Vh + ((size_t)p<<15);
    const uint32_t sbase = (uint32_t)__cvta_generic_to_shared(sh);

    for (int i=tid;i<Tn;i+=256) adj_s[i] = g_adj[i]*LOG2E;
#pragma unroll
    for (int i=0;i<2;i++){
        int c = tid + i*256;
        *(uint4*)&Qh2[c>>3][(c&7)<<2] = Qp4[(size_t)(q0 + (c>>3))*8 + (c&7)];
    }

    auto issue = [&](int kb, int buf){
#pragma unroll
        for (int i2=0;i2<4;i2++){
            int cc = tid + i2*256;
            int r = cc>>3, ch = cc&7;
            cpa16(sbase + (SH_K + buf*K_ST + r*36 + ch*4)*4, Kpw + (size_t)(kb+r)*32 + ch*4);
        }
#pragma unroll
        for (int i2=0;i2<4;i2++){
            int cc = tid + i2*256;
            int r = cc>>3, ch = cc&7;
            cpa16(sbase + (SH_V + buf*V_ST + r*36 + ch*4)*4, Vpw + (size_t)(kb+r)*32 + ch*4);
        }
        asm volatile("cp.async.commit_group;");
    };

    issue(0, 0);
    __syncthreads();

    const int wid = tid>>5, lane = tid&31, g = lane>>2, t = lane&3;
    const int rg = wid>>1, h = wid&1;
    const int r0 = rg*16;
    const int qlo = q0 + r0 + g;
    const int sidx4 = ((rg*2+h)*8 + g)*4;
    const int pidx4 = ((rg*2+(h^1))*8 + g)*4;
    const float scale2 = 0.04419417382415922f * LOG2E;

    uint32_t qa[4][4];
#pragma unroll
    for (int ks=0;ks<4;ks++){
        qa[ks][0]=Qh2[r0+g  ][ks*8+t];   qa[ks][1]=Qh2[r0+g+8][ks*8+t];
        qa[ks][2]=Qh2[r0+g  ][ks*8+t+4]; qa[ks][3]=Qh2[r0+g+8][ks*8+t+4];
    }

    const int rowin = lane&7;
    const uint32_t k_off0 = (uint32_t)((h*64 + ((lane>>4)&1)*8 + rowin)*36 + ((lane>>3)&1)*4);
    const uint32_t v_off0 = (uint32_t)((h*64 + ((lane>>3)&1)*8 + rowin)*36 + (lane>>4)*4);

    float m_lo=-1e30f, m_hi=-1e30f, l_lo=0.f, l_hi=0.f;
    float o[8][4] = {};

    for (int kbi=0; kbi<8; kbi++){
        int kb = kbi*128;
        if (kbi < 7) issue(kb+128, (kbi+1)&1);
        if (kbi < 7) asm volatile("cp.async.wait_group 1;");
        else         asm volatile("cp.async.wait_group 0;");
        __syncthreads();
        const uint32_t kstage = sbase + (SH_K + (kbi&1)*K_ST)*4;
        const uint32_t vstage = sbase + (SH_V + (kbi&1)*V_ST)*4;

        float c[8][4] = {};
#pragma unroll
        for (int ks=0; ks<4; ks++){
#pragma unroll
            for (int m=0; m<4; m++){
                uint32_t b0,b1,b2,b3;
                ldsm4(b0,b1,b2,b3, kstage + (k_off0 + m*576 + ks*8)*4);
                uint32_t bb[2];
                bb[0]=b0; bb[1]=b1; mma16(c[2*m  ], qa[ks], bb);
                bb[0]=b2; bb[1]=b3; mma16(c[2*m+1], qa[ks], bb);
            }
        }
#pragma unroll
        for (int ni=0;ni<8;ni++){
            int kk = kb + h*64 + ni*8 + 2*t;
            c[ni][0] = fmaf(c[ni][0], scale2, adj_s[abs(qlo   - kk    )]);
            c[ni][1] = fmaf(c[ni][1], scale2, adj_s[abs(qlo   - kk - 1)]);
            c[ni][2] = fmaf(c[ni][2], scale2, adj_s[abs(qlo+8 - kk    )]);
            c[ni][3] = fmaf(c[ni][3], scale2, adj_s[abs(qlo+8 - kk - 1)]);
        }
        float rmx_lo=-1e30f, rmx_hi=-1e30f;
#pragma unroll
        for (int ni=0;ni<8;ni++){
            rmx_lo = fmaxf(rmx_lo, fmaxf(c[ni][0], c[ni][1]));
            rmx_hi = fmaxf(rmx_hi, fmaxf(c[ni][2], c[ni][3]));
        }
        rmx_lo = fmaxf(rmx_lo, __shfl_xor_sync(0xffffffffu, rmx_lo, 1));
        rmx_lo = fmaxf(rmx_lo, __shfl_xor_sync(0xffffffffu, rmx_lo, 2));
        rmx_hi = fmaxf(rmx_hi, __shfl_xor_sync(0xffffffffu, rmx_hi, 1));
        rmx_hi = fmaxf(rmx_hi, __shfl_xor_sync(0xffffffffu, rmx_hi, 2));
        float mn_lo = fmaxf(m_lo, rmx_lo), mn_hi = fmaxf(m_hi, rmx_hi);
        float fold_lo = ex2a(m_lo - mn_lo),  fold_hi = ex2a(m_hi - mn_hi);
        m_lo = mn_lo; m_hi = mn_hi;
        float rs_lo=0.f, rs_hi=0.f;
#pragma unroll
        for (int ni=0;ni<8;ni++){
            c[ni][0]=ex2a(c[ni][0]-mn_lo); c[ni][1]=ex2a(c[ni][1]-mn_lo);
            c[ni][2]=ex2a(c[ni][2]-mn_hi); c[ni][3]=ex2a(c[ni][3]-mn_hi);
            rs_lo += c[ni][0]+c[ni][1];
            rs_hi += c[ni][2]+c[ni][3];
        }
        rs_lo += __shfl_xor_sync(0xffffffffu, rs_lo, 1);
        rs_lo += __shfl_xor_sync(0xffffffffu, rs_lo, 2);
        rs_hi += __shfl_xor_sync(0xffffffffu, rs_hi, 1);
        rs_hi += __shfl_xor_sync(0xffffffffu, rs_hi, 2);
        l_lo = l_lo*fold_lo + rs_lo;
        l_hi = l_hi*fold_hi + rs_hi;
#pragma unroll
        for (int ni=0;ni<8;ni++){
            o[ni][0]*=fold_lo; o[ni][1]*=fold_lo; o[ni][2]*=fold_hi; o[ni][3]*=fold_hi;
        }
#pragma unroll
        for (int j=0; j<4; j++){
            uint32_t a[4];
            a[0] = packh2(c[2*j  ][0], c[2*j  ][1]);
            a[1] = packh2(c[2*j  ][2], c[2*j  ][3]);
            a[2] = packh2(c[2*j+1][0], c[2*j+1][1]);
            a[3] = packh2(c[2*j+1][2], c[2*j+1][3]);
#pragma unroll
            for (int m=0; m<4; m++){
                uint32_t b0,b1,b2,b3;
                ldsm4t(b0,b1,b2,b3, vstage + (v_off0 + j*576 + m*8)*4);
                uint32_t bb[2];
                bb[0]=b0; bb[1]=b1; mma16(o[2*m  ], a, bb);
                bb[0]=b2; bb[1]=b3; mma16(o[2*m+1], a, bb);
            }
        }
        __syncthreads();
    }

    // ---- single cross-warp merge of (m, l) ----
    if ((lane&3)==0) *(float4*)&sb[sidx4] = make_float4(m_lo, m_hi, l_lo, l_hi);
    asm volatile("bar.sync %0, 64;" :: "r"(rg+1) : "memory");
    float4 pr = *(float4*)&sb[pidx4];
    float M_lo = fmaxf(m_lo, pr.x), M_hi = fmaxf(m_hi, pr.y);
    float eo_lo = ex2a(m_lo - M_lo), ep_lo = ex2a(pr.x - M_lo);
    float eo_hi = ex2a(m_hi - M_hi), ep_hi = ex2a(pr.y - M_hi);
    float w_lo = eo_lo / fmaf(l_lo, eo_lo, pr.z*ep_lo);
    float w_hi = eo_hi / fmaf(l_hi, eo_hi, pr.w*ep_hi);

    if (h==0){
#pragma unroll
        for (int ni=0;ni<8;ni++){
            Og[r0+g  ][ni*8+2*t  ] = o[ni][0]*w_lo;
            Og[r0+g  ][ni*8+2*t+1] = o[ni][1]*w_lo;
            Og[r0+g+8][ni*8+2*t  ] = o[ni][2]*w_hi;
            Og[r0+g+8][ni*8+2*t+1] = o[ni][3]*w_hi;
        }
    }
    __syncthreads();
    if (h==1){
#pragma unroll
        for (int ni=0;ni<8;ni++){
            Og[r0+g  ][ni*8+2*t  ] += o[ni][0]*w_lo;
            Og[r0+g  ][ni*8+2*t+1] += o[ni][1]*w_lo;
            Og[r0+g+8][ni*8+2*t  ] += o[ni][2]*w_hi;
            Og[r0+g+8][ni*8+2*t+1] += o[ni][3]*w_hi;
        }
    }
    __syncthreads();

    // ---- local-window epilogue (log2 domain), fp16 output ----
    const float aa = 1.f/(1.f+__expf(-alpha[layer]));
    const int rowl = wid*8 + (lane>>2);
    const int q = q0 + rowl;
    const int d0 = (lane&3)*16;
    const int lo = (q-4>0)? q-4 : 0;
    const int hi = (q+4<Tn-1)? q+4 : Tn-1;
    const int nw = hi-lo+1;

    float s[9];
    for (int j=0;j<nw;j++){
        float dot = 0.f;
#pragma unroll
        for (int i=0;i<8;i++){
            __half2 q2 = *(__half2*)&Qh2[rowl][(d0>>1)+i];
            __half2 k2 = *(__half2*)&Kpw[(size_t)(lo+j)*(DHn/2) + (d0>>1)+i];
            dot = fmaf(__half2float(q2.x), __half2float(k2.x), dot);
            dot = fmaf(__half2float(q2.y), __half2float(k2.y), dot);
        }
        dot += __shfl_xor_sync(0xffffffffu, dot, 1);
        dot += __shfl_xor_sync(0xffffffffu, dot, 2);
        s[j] = fmaf(dot, scale2, adj_s[abs(q-(lo+j))]);
    }
    float lm = -1e30f;
    for (int j=0;j<nw;j++) lm = fmaxf(lm, s[j]);
    float ls = 0.f;
    for (int j=0;j<nw;j++){ s[j] = ex2a(s[j]-lm); ls += s[j]; }
    float linv = (1.f-aa)/ls;

    float acc[16];
#pragma unroll
    for (int i=0;i<16;i++) acc[i] = aa*Og[rowl][d0+i];
    for (int j=0;j<nw;j++){
        float w = s[j]*linv;
#pragma unroll
        for (int i=0;i<8;i++){
            __half2 v2 = *(__half2*)&Vpw[(size_t)(lo+j)*(DHn/2) + (d0>>1)+i];
            acc[2*i  ] = fmaf(w, __half2float(v2.x), acc[2*i  ]);
            acc[2*i+1] = fmaf(w, __half2float(v2.y), acc[2*i+1]);
        }
    }
    uint32_t* outw = g_tmph + ((size_t)p<<15) + (size_t)q*32 + (d0>>1);
    uint32_t w8[8];
#pragma unroll
    for (int i=0;i<8;i++) w8[i] = packh2(powtf(acc[2*i]), powtf(acc[2*i+1]));
    *(uint4*)&outw[0] = *(uint4*)&w8[0];
    *(uint4*)&outw[4] = *(uint4*)&w8[4];
}

// ---------------- fused column L2 norm + in-place scale (fp16) ----------------
__global__ __launch_bounds__(256) void k_colnorm_scale(){
    int wid = threadIdx.x>>5, lane = threadIdx.x&31;
    int w = blockIdx.x*8 + wid;          // 0..2047
    int b = w >> 8, wc = w & 255;
    uint32_t* base = g_tmph + ((size_t)b<<18) + wc;   // b*1024*256 + wc
    uint32_t vals[32];
    float sq0=0.f, sq1=0.f;
#pragma unroll
    for (int j=0;j<32;j++){
        uint32_t v = base[(size_t)(j*32+lane)<<8];
        vals[j]=v;
        __half2 hh = *(__half2*)&v;
        float a=__half2float(hh.x), bb=__half2float(hh.y);
        sq0 = fmaf(a,a,sq0); sq1 = fmaf(bb,bb,sq1);
    }
#pragma unroll
    for (int o=16;o;o>>=1){ sq0 += __shfl_xor_sync(0xffffffffu,sq0,o); sq1 += __shfl_xor_sync(0xffffffffu,sq1,o); }
    float inv0 = 1.f/fmaxf(sqrtf(sq0), 1e-12f);
    float inv1 = 1.f/fmaxf(sqrtf(sq1), 1e-12f);
#pragma unroll
    for (int j=0;j<32;j++){
        __half2 hh = *(__half2*)&vals[j];
        base[(size_t)(j*32+lane)<<8] = packh2(__half2float(hh.x)*inv0, __half2float(hh.y)*inv1);
    }
}

// ---------------- LayerNorm over D, writes fp32 + fp16 shadow ----------------
__global__ __launch_bounds__(128) void k_ln(
    const float* __restrict__ lng, const float* __restrict__ lnb, int layer)
{
    __shared__ float shm[10];
    int r = blockIdx.x;
    int tid = threadIdx.x, lane = tid&31, wid = tid>>5;
    int d0 = tid*4;
    float4 v = *(const float4*)&g_xb[(size_t)r*Dn + d0];
    float sum = v.x+v.y+v.z+v.w;
    float sq  = v.x*v.x+v.y*v.y+v.z*v.z+v.w*v.w;
#pragma unroll
    for (int o=16;o;o>>=1){ sum += __shfl_xor_sync(0xffffffffu,sum,o); sq += __shfl_xor_sync(0xffffffffu,sq,o); }
    if (lane==0){ shm[wid]=sum; shm[4+wid]=sq; }
    __syncthreads();
    if (tid==0){ shm[8]=shm[0]+shm[1]+shm[2]+shm[3]; shm[9]=shm[4]+shm[5]+shm[6]+shm[7]; }
    __syncthreads();
    float mu  = shm[8]*(1.f/Dn);
    float var = shm[9]*(1.f/Dn) - mu*mu;
    float rstd = rsqrtf(fmaxf(var,0.f) + 1e-5f);
    float4 gg = *(const float4*)&lng[layer*Dn + d0];
    float4 bb = *(const float4*)&lnb[layer*Dn + d0];
    float y0 = (v.x-mu)*rstd*gg.x + bb.x;
    float y1 = (v.y-mu)*rstd*gg.y + bb.y;
    float y2 = (v.z-mu)*rstd*gg.z + bb.z;
    float y3 = (v.w-mu)*rstd*gg.w + bb.w;
    *(float4*)&g_xb[(size_t)r*Dn + d0] = make_float4(y0,y1,y2,y3);
    g_xbh[(size_t)r*256 + tid*2    ] = packh2(y0,y1);
    g_xbh[(size_t)r*256 + tid*2 + 1] = packh2(y2,y3);
}

// ---------------- launch ----------------
extern "C" void kernel_launch(void* const* d_in, const int* in_sizes, int n_in,
                              void* d_out, int out_size)
{
    const float* x     = (const float*)d_in[0];
    const float* Wq    = (const float*)d_in[1];
    const float* bq    = (const float*)d_in[2];
    const float* Wk    = (const float*)d_in[3];
    const float* bk    = (const float*)d_in[4];
    const float* Wv    = (const float*)d_in[5];
    const float* bv    = (const float*)d_in[6];
    const float* Wo    = (const float*)d_in[7];
    const float* bo    = (const float*)d_in[8];
    const float* alpha = (const float*)d_in[9];
    const float* ln_g  = (const float*)d_in[10];
    const float* ln_b  = (const float*)d_in[11];
    const float* adj_w = (const float*)d_in[12];
    const float* adj_b = (const float*)d_in[13];
    float* out = (float*)d_out;

    cudaFuncSetAttribute(k_flash, cudaFuncAttributeMaxDynamicSharedMemorySize, FLASH_SMEM);
    cudaFuncSetAttribute(k_proj,  cudaFuncAttributeMaxDynamicSharedMemorySize, PROJ_SMEM);

    k_prep_w<<<4096, 256>>>(Wq, Wk, Wv, Wo);
    k_transpose_in<<<ROWS, 256>>>(x);
    k_adj<<<1, Tn>>>(adj_w, adj_b);
    for (int l=0; l<2; l++){
        k_proj<<<dim3(4,64,3), 512, PROJ_SMEM>>>(bq,bk,bv,bo, 0, l);
        k_flash<<<dim3(16,64), 256, FLASH_SMEM>>>(alpha, l);
        k_colnorm_scale<<<256, 256>>>();
        k_proj<<<dim3(4,64,1), 512, PROJ_SMEM>>>(bq,bk,bv,bo, 1, l);
        k_ln<<<ROWS, 128>>>(ln_g, ln_b, l);
    }
    k_transpose_out<<<(ROWS*Dn)/256, 256>>>(out);
}

// round 16
// speedup vs baseline: 2.7472x; 1.0039x over previous
#include <cuda_runtime.h>
#include <cuda_fp16.h>
#include <math.h>
#include <stdint.h>

#define Tn 1024
#define Bn 8
#define Dn 512
#define Hn 8
#define DHn 64
#define NPAIR 64           // Hn*Bn
#define ROWS (Bn*Tn)       // 8192
#define LOG2E 1.4426950408889634f

// ---------------- scratch (device globals: allocation-free) ----------------
__device__ float    g_xb [Bn*Tn*Dn];
__device__ uint32_t g_xbh[Bn*Tn*Dn/2];   // xb fp16 shadow, half2 pairs over d
__device__ uint32_t g_Qh [Bn*Tn*Dn/2];
__device__ uint32_t g_Kh [Bn*Tn*Dn/2];
__device__ uint32_t g_Vh [Bn*Tn*Dn/2];
__device__ uint32_t g_tmph[Bn*Tn*Dn/2];  // attention out fp16 (then scaled in place)
__device__ uint32_t g_Wp [8*512*256];    // [layer*4+z][k][n-pair] plain fp16
__device__ float    g_adj[Tn];

__device__ __forceinline__ float powtf(float v){
    return sqrtf(fmaxf(v,0.f)) - sqrtf(fmaxf(-v,0.f));
}

__device__ __forceinline__ uint32_t packh2(float a, float b){
    __half2 h = __floats2half2_rn(a, b);   // .x (low) = a
    return *(uint32_t*)&h;
}

__device__ __forceinline__ float ex2a(float x){
    float y; asm("ex2.approx.ftz.f32 %0, %1;" : "=f"(y) : "f"(x)); return y;
}

// mma.sync m16n8k16 fp16 in, fp32 accum, row.col
__device__ __forceinline__ void mma16(float* c, const uint32_t* a, const uint32_t* b){
    asm volatile(
        "mma.sync.aligned.m16n8k16.row.col.f32.f16.f16.f32 "
        "{%0,%1,%2,%3},{%4,%5,%6,%7},{%8,%9},{%0,%1,%2,%3};"
        : "+f"(c[0]),"+f"(c[1]),"+f"(c[2]),"+f"(c[3])
        : "r"(a[0]),"r"(a[1]),"r"(a[2]),"r"(a[3]),"r"(b[0]),"r"(b[1]));
}

__device__ __forceinline__ void cpa16(uint32_t dst, const void* src){
    asm volatile("cp.async.cg.shared.global [%0], [%1], 16;" :: "r"(dst), "l"(src));
}

__device__ __forceinline__ void ldsm4(uint32_t& r0, uint32_t& r1, uint32_t& r2, uint32_t& r3, uint32_t addr){
    asm volatile("ldmatrix.sync.aligned.m8n8.x4.shared.b16 {%0,%1,%2,%3}, [%4];"
        : "=r"(r0),"=r"(r1),"=r"(r2),"=r"(r3) : "r"(addr));
}

__device__ __forceinline__ void ldsm4t(uint32_t& r0, uint32_t& r1, uint32_t& r2, uint32_t& r3, uint32_t addr){
    asm volatile("ldmatrix.sync.aligned.m8n8.x4.trans.shared.b16 {%0,%1,%2,%3}, [%4];"
        : "=r"(r0),"=r"(r1),"=r"(r2),"=r"(r3) : "r"(addr));
}

// ---------------- weight prep: fp32 -> fp16 plain [k][n-pair], once ----------------
__global__ void k_prep_w(const float* __restrict__ Wq, const float* __restrict__ Wk,
                         const float* __restrict__ Wv, const float* __restrict__ Wo){
    int idx = blockIdx.x*256 + threadIdx.x;       // < 8*131072
    int m8  = idx >> 17;
    int rem = idx & 131071;
    int k   = rem >> 8;
    int np  = rem & 255;
    int l = m8 >> 2, z = m8 & 3;
    const float* W = (z==0?Wq:(z==1?Wk:(z==2?Wv:Wo))) + (size_t)l*Dn*Dn;
    g_Wp[idx] = packh2(W[(size_t)k*Dn + 2*np], W[(size_t)k*Dn + 2*np + 1]);
}

// ---------------- transpose in: x[T,B,D] -> g_xb[B,T,D] + fp16 shadow ----------------
__global__ void k_transpose_in(const float* __restrict__ x){
    int i = blockIdx.x*256 + threadIdx.x;         // word idx < ROWS*256
    int d0 = (i & 255)*2;
    int row = i >> 8;
    int b = row >> 10, t = row & 1023;
    const float* src = &x[(size_t)(t*Bn + b)*Dn + d0];
    float v0 = src[0], v1 = src[1];
    float2* dst = (float2*)&g_xb[(size_t)row*Dn + d0];
    *dst = make_float2(v0, v1);
    g_xbh[i] = packh2(v0, v1);
}

__global__ void k_transpose_out(float* __restrict__ out){
    int idx = blockIdx.x*256 + threadIdx.x;          // [T,B,D] linear
    int d = idx & (Dn-1);
    int b = (idx >> 9) & (Bn-1);
    int t = idx >> 12;
    out[idx] = g_xb[((b<<10) + t)*Dn + d];
}

// ---------------- adj table ----------------
__global__ void k_adj(const float* __restrict__ aw, const float* __restrict__ ab){
    int i = threadIdx.x;
    float dist = (float)i;
    g_adj[i] = expf(-fabsf(aw[0]*dist*dist - ab[0]));
}

// ================= 256-thread 128x128 fp16 GEMM, 3-stage cp.async, 2 CTAs/SM =================
// mode 0: C = xbh @ W[z] + b[z] -> g_{Q,K,V}h (fp16), grid z = 3
// mode 1: g_xb += tmph @ Wo + bo (fp32 residual), grid z = 1
// M=8192, N=512, K=512; block 128x128, BK=32, 8 warps 2(m)x4(n), warp 64x32.
#define PA_ST 4608                 // A stage: 128 rows * 36 words
#define PB_ST 2176                 // B stage: 32 k-rows * 68 words (64 n-pairs + pad)
#define PROJ_SMEM ((3*PA_ST + 3*PB_ST)*4)   // 81408 B

__global__ __launch_bounds__(256,2) void k_proj(
    const float* __restrict__ bq, const float* __restrict__ bk,
    const float* __restrict__ bv, const float* __restrict__ bo,
    int mode, int layer)
{
    extern __shared__ uint32_t shp[];
    const int tid = threadIdx.x;
    const int z   = (mode==0) ? blockIdx.z : 3;
    const uint32_t* Bsrc = g_Wp + (size_t)(layer*4 + z)*131072;   // [k][n-pair]
    const uint32_t* Asrc = (mode==0) ? g_xbh : g_tmph;
    const float* bias = ((mode==0) ? (z==0?bq:(z==1?bk:bv)) : bo) + layer*Dn;
    uint32_t* Ch = (z==0? g_Qh : (z==1? g_Kh : g_Vh));

    const int m0 = blockIdx.y*128, n0 = blockIdx.x*128;
    const int wid = tid>>5, lane = tid&31, g = lane>>2, t = lane&3;
    const int m_off = (wid&1)*64, n_off = (wid>>1)*32;
    const uint32_t sbase = (uint32_t)__cvta_generic_to_shared(shp);

    float c[4][4][4] = {};

    auto issue = [&](int kt, int buf){
#pragma unroll
        for (int i2=0;i2<2;i2++){   // A: 128 rows x 4 chunks (16 words/row)
            int cc = tid + i2*256;
            int r = cc>>2, ch = cc&3;
            cpa16(sbase + (buf*PA_ST + r*36 + ch*4)*4,
                  Asrc + (size_t)(m0+r)*256 + kt*16 + ch*4);
        }
#pragma unroll
        for (int i2=0;i2<2;i2++){   // B: 32 k-rows x 16 chunks (64 n-pair words/row)
            int cc = tid + i2*256;
            int r = cc>>4, ch = cc&15;
            cpa16(sbase + (3*PA_ST + buf*PB_ST + r*68 + ch*4)*4,
                  Bsrc + (size_t)(kt*32 + r)*256 + (n0>>1) + ch*4);
        }
        asm volatile("cp.async.commit_group;");
    };

    // ldmatrix per-thread offsets (words)
    const int rowin = lane&7;
    const uint32_t a_off = (uint32_t)((m_off + ((lane>>3)&1)*8 + rowin)*36 + (lane>>4)*4);
    const uint32_t b_off = (uint32_t)((((lane>>3)&1)*8 + rowin)*68 + (n_off>>1) + (lane>>4)*4);

    issue(0, 0);
    issue(1, 1);
    for (int kt=0; kt<16; kt++){
        if (kt < 15) asm volatile("cp.async.wait_group 1;");
        else         asm volatile("cp.async.wait_group 0;");
        __syncthreads();
        if (kt+2 <= 15) issue(kt+2, (kt+2)%3);
        const uint32_t abase = sbase + ((kt%3)*PA_ST)*4;
        const uint32_t bbase = sbase + (3*PA_ST + (kt%3)*PB_ST)*4;
#pragma unroll
        for (int j=0; j<2; j++){
            uint32_t a[4][4], b[4][2];
#pragma unroll
            for (int mi=0;mi<4;mi++)
                ldsm4(a[mi][0],a[mi][1],a[mi][2],a[mi][3], abase + (a_off + mi*16*36 + j*8)*4);
#pragma unroll
            for (int u=0;u<2;u++){
                uint32_t b0,b1,b2,b3;
                ldsm4t(b0,b1,b2,b3, bbase + (b_off + j*16*68 + u*8)*4);
                b[2*u][0]=b0; b[2*u][1]=b1; b[2*u+1][0]=b2; b[2*u+1][1]=b3;
            }
#pragma unroll
            for (int mi=0;mi<4;mi++)
#pragma unroll
                for (int ni=0;ni<4;ni++) mma16(c[mi][ni], a[mi], b[ni]);
        }
    }

#pragma unroll
    for (int mi=0;mi<4;mi++){
#pragma unroll
        for (int ni=0;ni<4;ni++){
            int row = m0 + m_off + mi*16 + g;
            int col = n0 + n_off + ni*8 + 2*t;
            float b0 = bias[col], b1 = bias[col+1];
            if (mode==0){
                int w = col>>1;
                Ch[(size_t)row*256 + w]     = packh2(c[mi][ni][0]+b0, c[mi][ni][1]+b1);
                Ch[(size_t)(row+8)*256 + w] = packh2(c[mi][ni][2]+b0, c[mi][ni][3]+b1);
            } else {
                float2 r0 = *(float2*)&g_xb[(size_t)row*Dn + col];
                float2 r1 = *(float2*)&g_xb[(size_t)(row+8)*Dn + col];
                float2 v0 = {c[mi][ni][0]+b0+r0.x, c[mi][ni][1]+b1+r0.y};
                float2 v1 = {c[mi][ni][2]+b0+r1.x, c[mi][ni][3]+b1+r1.y};
                *(float2*)&g_xb[(size_t)row*Dn + col]     = v0;
                *(float2*)&g_xb[(size_t)(row+8)*Dn + col] = v1;
            }
        }
    }
}

// ================= flash attention (round-13, unchanged) =================
#define K_ST 4608                  // 128 rows * 36
#define V_ST 4608
#define SH_Q   0                   // 64*36 = 2304
#define SH_K   2304
#define SH_V   (SH_K + 2*K_ST)     // 11520
#define SH_ADJ (SH_V + 2*V_ST)     // 20736
#define SH_SB  (SH_ADJ + Tn)       // 21760
#define FLASH_SMEM ((SH_SB + 256)*4)   // 88064 B
#define OG_STRIDE 68

__global__ __launch_bounds__(256,2) void k_flash(const float* __restrict__ alpha, int layer){
    extern __shared__ uint32_t sh[];
    uint32_t (*Qh2)[36] = (uint32_t(*)[36])(sh + SH_Q);
    float* adj_s = (float*)(sh + SH_ADJ);     // log2-scaled adj
    float* sb    = (float*)(sh + SH_SB);
    float (*Og)[OG_STRIDE] = (float(*)[OG_STRIDE])(sh + SH_K);

    const int tid = threadIdx.x;
    const int p  = blockIdx.y;
    const int q0 = blockIdx.x*64;
    const uint4* Qp4 = (const uint4*)(g_Qh + ((size_t)p<<15));
    const uint32_t* Kpw = g_Kh + ((size_t)p<<15);
    const uint32_t* Vpw = g_Vh + ((size_t)p<<15);
    const uint32_t sbase = (uint32_t)__cvta_generic_to_shared(sh);

    for (int i=tid;i<Tn;i+=256) adj_s[i] = g_adj[i]*LOG2E;
#pragma unroll
    for (int i=0;i<2;i++){
        int c = tid + i*256;
        *(uint4*)&Qh2[c>>3][(c&7)<<2] = Qp4[(size_t)(q0 + (c>>3))*8 + (c&7)];
    }

    auto issue = [&](int kb, int buf){
#pragma unroll
        for (int i2=0;i2<4;i2++){
            int cc = tid + i2*256;
            int r = cc>>3, ch = cc&7;
            cpa16(sbase + (SH_K + buf*K_ST + r*36 + ch*4)*4, Kpw + (size_t)(kb+r)*32 + ch*4);
        }
#pragma unroll
        for (int i2=0;i2<4;i2++){
            int cc = tid + i2*256;
            int r = cc>>3, ch = cc&7;
            cpa16(sbase + (SH_V + buf*V_ST + r*36 + ch*4)*4, Vpw + (size_t)(kb+r)*32 + ch*4);
        }
        asm volatile("cp.async.commit_group;");
    };

    issue(0, 0);
    __syncthreads();

    const int wid = tid>>5, lane = tid&31, g = lane>>2, t = lane&3;
    const int rg = wid>>1, h = wid&1;
    const int r0 = rg*16;
    const int qlo = q0 + r0 + g;
    const int sidx4 = ((rg*2+h)*8 + g)*4;
    const int pidx4 = ((rg*2+(h^1))*8 + g)*4;
    const float scale2 = 0.04419417382415922f * LOG2E;

    uint32_t qa[4][4];
#pragma unroll
    for (int ks=0;ks<4;ks++){
        qa[ks][0]=Qh2[r0+g  ][ks*8+t];   qa[ks][1]=Qh2[r0+g+8][ks*8+t];
        qa[ks][2]=Qh2[r0+g  ][ks*8+t+4]; qa[ks][3]=Qh2[r0+g+8][ks*8+t+4];
    }

    const int rowin = lane&7;
    const uint32_t k_off0 = (uint32_t)((h*64 + ((lane>>4)&1)*8 + rowin)*36 + ((lane>>3)&1)*4);
    const uint32_t v_off0 = (uint32_t)((h*64 + ((lane>>3)&1)*8 + rowin)*36 + (lane>>4)*4);

    float m_lo=-1e30f, m_hi=-1e30f, l_lo=0.f, l_hi=0.f;
    float o[8][4] = {};

    for (int kbi=0; kbi<8; kbi++){
        int kb = kbi*128;
        if (kbi < 7) issue(kb+128, (kbi+1)&1);
        if (kbi < 7) asm volatile("cp.async.wait_group 1;");
        else         asm volatile("cp.async.wait_group 0;");
        __syncthreads();
        const uint32_t kstage = sbase + (SH_K + (kbi&1)*K_ST)*4;
        const uint32_t vstage = sbase + (SH_V + (kbi&1)*V_ST)*4;

        float c[8][4] = {};
#pragma unroll
        for (int ks=0; ks<4; ks++){
#pragma unroll
            for (int m=0; m<4; m++){
                uint32_t b0,b1,b2,b3;
                ldsm4(b0,b1,b2,b3, kstage + (k_off0 + m*576 + ks*8)*4);
                uint32_t bb[2];
                bb[0]=b0; bb[1]=b1; mma16(c[2*m  ], qa[ks], bb);
                bb[0]=b2; bb[1]=b3; mma16(c[2*m+1], qa[ks], bb);
            }
        }
#pragma unroll
        for (int ni=0;ni<8;ni++){
            int kk = kb + h*64 + ni*8 + 2*t;
            c[ni][0] = fmaf(c[ni][0], scale2, adj_s[abs(qlo   - kk    )]);
            c[ni][1] = fmaf(c[ni][1], scale2, adj_s[abs(qlo   - kk - 1)]);
            c[ni][2] = fmaf(c[ni][2], scale2, adj_s[abs(qlo+8 - kk    )]);
            c[ni][3] = fmaf(c[ni][3], scale2, adj_s[abs(qlo+8 - kk - 1)]);
        }
        float rmx_lo=-1e30f, rmx_hi=-1e30f;
#pragma unroll
        for (int ni=0;ni<8;ni++){
            rmx_lo = fmaxf(rmx_lo, fmaxf(c[ni][0], c[ni][1]));
            rmx_hi = fmaxf(rmx_hi, fmaxf(c[ni][2], c[ni][3]));
        }
        rmx_lo = fmaxf(rmx_lo, __shfl_xor_sync(0xffffffffu, rmx_lo, 1));
        rmx_lo = fmaxf(rmx_lo, __shfl_xor_sync(0xffffffffu, rmx_lo, 2));
        rmx_hi = fmaxf(rmx_hi, __shfl_xor_sync(0xffffffffu, rmx_hi, 1));
        rmx_hi = fmaxf(rmx_hi, __shfl_xor_sync(0xffffffffu, rmx_hi, 2));
        float mn_lo = fmaxf(m_lo, rmx_lo), mn_hi = fmaxf(m_hi, rmx_hi);
        float fold_lo = ex2a(m_lo - mn_lo),  fold_hi = ex2a(m_hi - mn_hi);
        m_lo = mn_lo; m_hi = mn_hi;
        float rs_lo=0.f, rs_hi=0.f;
#pragma unroll
        for (int ni=0;ni<8;ni++){
            c[ni][0]=ex2a(c[ni][0]-mn_lo); c[ni][1]=ex2a(c[ni][1]-mn_lo);
            c[ni][2]=ex2a(c[ni][2]-mn_hi); c[ni][3]=ex2a(c[ni][3]-mn_hi);
            rs_lo += c[ni][0]+c[ni][1];
            rs_hi += c[ni][2]+c[ni][3];
        }
        rs_lo += __shfl_xor_sync(0xffffffffu, rs_lo, 1);
        rs_lo += __shfl_xor_sync(0xffffffffu, rs_lo, 2);
        rs_hi += __shfl_xor_sync(0xffffffffu, rs_hi, 1);
        rs_hi += __shfl_xor_sync(0xffffffffu, rs_hi, 2);
        l_lo = l_lo*fold_lo + rs_lo;
        l_hi = l_hi*fold_hi + rs_hi;
#pragma unroll
        for (int ni=0;ni<8;ni++){
            o[ni][0]*=fold_lo; o[ni][1]*=fold_lo; o[ni][2]*=fold_hi; o[ni][3]*=fold_hi;
        }
#pragma unroll
        for (int j=0; j<4; j++){
            uint32_t a[4];
            a[0] = packh2(c[2*j  ][0], c[2*j  ][1]);
            a[1] = packh2(c[2*j  ][2], c[2*j  ][3]);
            a[2] = packh2(c[2*j+1][0], c[2*j+1][1]);
            a[3] = packh2(c[2*j+1][2], c[2*j+1][3]);
#pragma unroll
            for (int m=0; m<4; m++){
                uint32_t b0,b1,b2,b3;
                ldsm4t(b0,b1,b2,b3, vstage + (v_off0 + j*576 + m*8)*4);
                uint32_t bb[2];
                bb[0]=b0; bb[1]=b1; mma16(o[2*m  ], a, bb);
                bb[0]=b2; bb[1]=b3; mma16(o[2*m+1], a, bb);
            }
        }
        __syncthreads();
    }

    // ---- single cross-warp merge of (m, l) ----
    if ((lane&3)==0) *(float4*)&sb[sidx4] = make_float4(m_lo, m_hi, l_lo, l_hi);
    asm volatile("bar.sync %0, 64;" :: "r"(rg+1) : "memory");
    float4 pr = *(float4*)&sb[pidx4];
    float M_lo = fmaxf(m_lo, pr.x), M_hi = fmaxf(m_hi, pr.y);
    float eo_lo = ex2a(m_lo - M_lo), ep_lo = ex2a(pr.x - M_lo);
    float eo_hi = ex2a(m_hi - M_hi), ep_hi = ex2a(pr.y - M_hi);
    float w_lo = eo_lo / fmaf(l_lo, eo_lo, pr.z*ep_lo);
    float w_hi = eo_hi / fmaf(l_hi, eo_hi, pr.w*ep_hi);

    if (h==0){
#pragma unroll
        for (int ni=0;ni<8;ni++){
            Og[r0+g  ][ni*8+2*t  ] = o[ni][0]*w_lo;
            Og[r0+g  ][ni*8+2*t+1] = o[ni][1]*w_lo;
            Og[r0+g+8][ni*8+2*t  ] = o[ni][2]*w_hi;
            Og[r0+g+8][ni*8+2*t+1] = o[ni][3]*w_hi;
        }
    }
    __syncthreads();
    if (h==1){
#pragma unroll
        for (int ni=0;ni<8;ni++){
            Og[r0+g  ][ni*8+2*t  ] += o[ni][0]*w_lo;
            Og[r0+g  ][ni*8+2*t+1] += o[ni][1]*w_lo;
            Og[r0+g+8][ni*8+2*t  ] += o[ni][2]*w_hi;
            Og[r0+g+8][ni*8+2*t+1] += o[ni][3]*w_hi;
        }
    }
    __syncthreads();

    // ---- local-window epilogue (log2 domain), fp16 output ----
    const float aa = 1.f/(1.f+__expf(-alpha[layer]));
    const int rowl = wid*8 + (lane>>2);
    const int q = q0 + rowl;
    const int d0 = (lane&3)*16;
    const int lo = (q-4>0)? q-4 : 0;
    const int hi = (q+4<Tn-1)? q+4 : Tn-1;
    const int nw = hi-lo+1;

    float s[9];
    for (int j=0;j<nw;j++){
        float dot = 0.f;
#pragma unroll
        for (int i=0;i<8;i++){
            __half2 q2 = *(__half2*)&Qh2[rowl][(d0>>1)+i];
            __half2 k2 = *(__half2*)&Kpw[(size_t)(lo+j)*(DHn/2) + (d0>>1)+i];
            dot = fmaf(__half2float(q2.x), __half2float(k2.x), dot);
            dot = fmaf(__half2float(q2.y), __half2float(k2.y), dot);
        }
        dot += __shfl_xor_sync(0xffffffffu, dot, 1);
        dot += __shfl_xor_sync(0xffffffffu, dot, 2);
        s[j] = fmaf(dot, scale2, adj_s[abs(q-(lo+j))]);
    }
    float lm = -1e30f;
    for (int j=0;j<nw;j++) lm = fmaxf(lm, s[j]);
    float ls = 0.f;
    for (int j=0;j<nw;j++){ s[j] = ex2a(s[j]-lm); ls += s[j]; }
    float linv = (1.f-aa)/ls;

    float acc[16];
#pragma unroll
    for (int i=0;i<16;i++) acc[i] = aa*Og[rowl][d0+i];
    for (int j=0;j<nw;j++){
        float w = s[j]*linv;
#pragma unroll
        for (int i=0;i<8;i++){
            __half2 v2 = *(__half2*)&Vpw[(size_t)(lo+j)*(DHn/2) + (d0>>1)+i];
            acc[2*i  ] = fmaf(w, __half2float(v2.x), acc[2*i  ]);
            acc[2*i+1] = fmaf(w, __half2float(v2.y), acc[2*i+1]);
        }
    }
    uint32_t* outw = g_tmph + ((size_t)p<<15) + (size_t)q*32 + (d0>>1);
    uint32_t w8[8];
#pragma unroll
    for (int i=0;i<8;i++) w8[i] = packh2(powtf(acc[2*i]), powtf(acc[2*i+1]));
    *(uint4*)&outw[0] = *(uint4*)&w8[0];
    *(uint4*)&outw[4] = *(uint4*)&w8[4];
}

// ---------------- fused column L2 norm + in-place scale (fp16) ----------------
__global__ __launch_bounds__(256) void k_colnorm_scale(){
    int wid = threadIdx.x>>5, lane = threadIdx.x&31;
    int w = blockIdx.x*8 + wid;          // 0..2047
    int b = w >> 8, wc = w & 255;
    uint32_t* base = g_tmph + ((size_t)b<<18) + wc;   // b*1024*256 + wc
    uint32_t vals[32];
    float sq0=0.f, sq1=0.f;
#pragma unroll
    for (int j=0;j<32;j++){
        uint32_t v = base[(size_t)(j*32+lane)<<8];
        vals[j]=v;
        __half2 hh = *(__half2*)&v;
        float a=__half2float(hh.x), bb=__half2float(hh.y);
        sq0 = fmaf(a,a,sq0); sq1 = fmaf(bb,bb,sq1);
    }
#pragma unroll
    for (int o=16;o;o>>=1){ sq0 += __shfl_xor_sync(0xffffffffu,sq0,o); sq1 += __shfl_xor_sync(0xffffffffu,sq1,o); }
    float inv0 = 1.f/fmaxf(sqrtf(sq0), 1e-12f);
    float inv1 = 1.f/fmaxf(sqrtf(sq1), 1e-12f);
#pragma unroll
    for (int j=0;j<32;j++){
        __half2 hh = *(__half2*)&vals[j];
        base[(size_t)(j*32+lane)<<8] = packh2(__half2float(hh.x)*inv0, __half2float(hh.y)*inv1);
    }
}

// ---------------- LayerNorm over D, writes fp32 + fp16 shadow ----------------
__global__ __launch_bounds__(128) void k_ln(
    const float* __restrict__ lng, const float* __restrict__ lnb, int layer)
{
    __shared__ float shm[10];
    int r = blockIdx.x;
    int tid = threadIdx.x, lane = tid&31, wid = tid>>5;
    int d0 = tid*4;
    float4 v = *(const float4*)&g_xb[(size_t)r*Dn + d0];
    float sum = v.x+v.y+v.z+v.w;
    float sq  = v.x*v.x+v.y*v.y+v.z*v.z+v.w*v.w;
#pragma unroll
    for (int o=16;o;o>>=1){ sum += __shfl_xor_sync(0xffffffffu,sum,o); sq += __shfl_xor_sync(0xffffffffu,sq,o); }
    if (lane==0){ shm[wid]=sum; shm[4+wid]=sq; }
    __syncthreads();
    if (tid==0){ shm[8]=shm[0]+shm[1]+shm[2]+shm[3]; shm[9]=shm[4]+shm[5]+shm[6]+shm[7]; }
    __syncthreads();
    float mu  = shm[8]*(1.f/Dn);
    float var = shm[9]*(1.f/Dn) - mu*mu;
    float rstd = rsqrtf(fmaxf(var,0.f) + 1e-5f);
    float4 gg = *(const float4*)&lng[layer*Dn + d0];
    float4 bb = *(const float4*)&lnb[layer*Dn + d0];
    float y0 = (v.x-mu)*rstd*gg.x + bb.x;
    float y1 = (v.y-mu)*rstd*gg.y + bb.y;
    float y2 = (v.z-mu)*rstd*gg.z + bb.z;
    float y3 = (v.w-mu)*rstd*gg.w + bb.w;
    *(float4*)&g_xb[(size_t)r*Dn + d0] = make_float4(y0,y1,y2,y3);
    g_xbh[(size_t)r*256 + tid*2    ] = packh2(y0,y1);
    g_xbh[(size_t)r*256 + tid*2 + 1] = packh2(y2,y3);
}

// ---------------- launch ----------------
extern "C" void kernel_launch(void* const* d_in, const int* in_sizes, int n_in,
                              void* d_out, int out_size)
{
    const float* x     = (const float*)d_in[0];
    const float* Wq    = (const float*)d_in[1];
    const float* bq    = (const float*)d_in[2];
    const float* Wk    = (const float*)d_in[3];
    const float* bk    = (const float*)d_in[4];
    const float* Wv    = (const float*)d_in[5];
    const float* bv    = (const float*)d_in[6];
    const float* Wo    = (const float*)d_in[7];
    const float* bo    = (const float*)d_in[8];
    const float* alpha = (const float*)d_in[9];
    const float* ln_g  = (const float*)d_in[10];
    const float* ln_b  = (const float*)d_in[11];
    const float* adj_w = (const float*)d_in[12];
    const float* adj_b = (const float*)d_in[13];
    float* out = (float*)d_out;

    cudaFuncSetAttribute(k_flash, cudaFuncAttributeMaxDynamicSharedMemorySize, FLASH_SMEM);
    cudaFuncSetAttribute(k_proj,  cudaFuncAttributeMaxDynamicSharedMemorySize, PROJ_SMEM);

    k_prep_w<<<4096, 256>>>(Wq, Wk, Wv, Wo);
    k_transpose_in<<<ROWS, 256>>>(x);
    k_adj<<<1, Tn>>>(adj_w, adj_b);
    for (int l=0; l<2; l++){
        k_proj<<<dim3(4,64,3), 256, PROJ_SMEM>>>(bq,bk,bv,bo, 0, l);
        k_flash<<<dim3(16,64), 256, FLASH_SMEM>>>(alpha, l);
        k_colnorm_scale<<<256, 256>>>();
        k_proj<<<dim3(4,64,1), 256, PROJ_SMEM>>>(bq,bk,bv,bo, 1, l);
        k_ln<<<ROWS, 128>>>(ln_g, ln_b, l);
    }
    k_transpose_out<<<(ROWS*Dn)/256, 256>>>(out);
}